// round 1
// baseline (speedup 1.0000x reference)
#include <cuda_runtime.h>
#include <math.h>

// ---------------- problem constants ----------------
#define RTOT   32768          // B*N = 32*1024
#define CIN    384
#define HID    1024
#define NRES   20
#define NTAB   21

// output layout (floats)
#define OFF_LOGITS 0
#define OFF_SEQ0   655360
#define OFF_PRED   688128
#define OFF_FINAL  2064384
#define OFF_M14    5701632
#define OFF_M37    6160384

// ---------------- scratch (no cudaMalloc allowed) ----------------
__device__ float g_xn[(size_t)RTOT * CIN];
__device__ float g_h1[(size_t)RTOT * HID];
__device__ float g_h2[(size_t)RTOT * HID];
__device__ int   g_seq0i[RTOT];

// ---------------- LayerNorm: one warp per row of 384 ----------------
__global__ __launch_bounds__(256) void ln_kernel(
    const float* __restrict__ act,
    const float* __restrict__ gamma,
    const float* __restrict__ beta,
    float* __restrict__ out)
{
    int row  = blockIdx.x * 8 + (threadIdx.x >> 5);
    int lane = threadIdx.x & 31;
    const float* x = act + (size_t)row * CIN;

    float v[12];
    float sum = 0.f;
#pragma unroll
    for (int i = 0; i < 12; i++) { v[i] = x[lane + i * 32]; sum += v[i]; }
#pragma unroll
    for (int o = 16; o; o >>= 1) sum += __shfl_xor_sync(0xffffffffu, sum, o);
    float mu = sum * (1.f / CIN);

    float vs = 0.f;
#pragma unroll
    for (int i = 0; i < 12; i++) { float d = v[i] - mu; vs += d * d; }
#pragma unroll
    for (int o = 16; o; o >>= 1) vs += __shfl_xor_sync(0xffffffffu, vs, o);
    float rstd = rsqrtf(vs * (1.f / CIN) + 1e-5f);

    float* o_ = out + (size_t)row * CIN;
#pragma unroll
    for (int i = 0; i < 12; i++) {
        int c = lane + i * 32;
        o_[c] = (v[i] - mu) * rstd * gamma[c] + beta[c];
    }
}

// ---------------- SGEMM 128x128x8, 8x8 microtile, fused bias+relu ----------------
#define BM 128
#define BN 128
#define BK 8
#define TM 8
#define TN 8

template <bool RELU>
__global__ __launch_bounds__(256) void sgemm_kernel(
    const float* __restrict__ A,   // [M,K] row-major
    const float* __restrict__ B,   // [K,N] row-major
    const float* __restrict__ bias,// [N]
    float* __restrict__ C,         // [M,N]
    int M, int N, int K)
{
    __shared__ float As[BK][BM];
    __shared__ float Bs[BK][BN];

    const int tid = threadIdx.x;
    const int bx = blockIdx.x;   // N tiles
    const int by = blockIdx.y;   // M tiles

    const int tx = tid & 15;
    const int ty = tid >> 4;

    const int a_row = tid >> 1;          // 0..127
    const int a_col = (tid & 1) * 4;     // 0 or 4
    const int b_row = tid >> 5;          // 0..7
    const int b_col = (tid & 31) * 4;    // 0..124

    const float* Aptr = A + (size_t)(by * BM + a_row) * K + a_col;
    const float* Bptr = B + (size_t)b_row * N + (size_t)bx * BN + b_col;

    float acc[TM][TN];
#pragma unroll
    for (int i = 0; i < TM; i++)
#pragma unroll
        for (int j = 0; j < TN; j++) acc[i][j] = 0.f;

    for (int k0 = 0; k0 < K; k0 += BK) {
        float4 av = *(const float4*)Aptr;
        As[a_col + 0][a_row] = av.x;
        As[a_col + 1][a_row] = av.y;
        As[a_col + 2][a_row] = av.z;
        As[a_col + 3][a_row] = av.w;
        *(float4*)&Bs[b_row][b_col] = *(const float4*)Bptr;
        __syncthreads();
        Aptr += BK;
        Bptr += (size_t)BK * N;

#pragma unroll
        for (int kk = 0; kk < BK; kk++) {
            float ra[TM], rb[TN];
#pragma unroll
            for (int i = 0; i < TM; i++) ra[i] = As[kk][ty * TM + i];
#pragma unroll
            for (int j = 0; j < TN; j++) rb[j] = Bs[kk][tx * TN + j];
#pragma unroll
            for (int i = 0; i < TM; i++)
#pragma unroll
                for (int j = 0; j < TN; j++)
                    acc[i][j] = fmaf(ra[i], rb[j], acc[i][j]);
        }
        __syncthreads();
    }

    const int col0 = bx * BN + tx * TN;
#pragma unroll
    for (int i = 0; i < TM; i++) {
        int row = by * BM + ty * TM + i;
        float* crow = C + (size_t)row * N + col0;
#pragma unroll
        for (int j = 0; j < TN; j += 4) {
            float4 v;
            v.x = acc[i][j + 0] + bias[col0 + j + 0];
            v.y = acc[i][j + 1] + bias[col0 + j + 1];
            v.z = acc[i][j + 2] + bias[col0 + j + 2];
            v.w = acc[i][j + 3] + bias[col0 + j + 3];
            if (RELU) {
                v.x = fmaxf(v.x, 0.f); v.y = fmaxf(v.y, 0.f);
                v.z = fmaxf(v.z, 0.f); v.w = fmaxf(v.w, 0.f);
            }
            *(float4*)(crow + j) = v;
        }
    }
}

// ---------------- head: h2 @ w3 + b3, argmax, fixed-mask select ----------------
__global__ __launch_bounds__(256) void head_kernel(
    const float* __restrict__ h2,     // [R,1024]
    const float* __restrict__ w3,     // [1024,20]
    const float* __restrict__ b3,     // [20]
    const int* __restrict__ fixed_mask,
    const int* __restrict__ seq_t,
    float* __restrict__ out_logits,   // [R,20]
    float* __restrict__ out_seq0f,    // [R]
    int* __restrict__ seq0i)          // [R]
{
    int row  = blockIdx.x * 8 + (threadIdx.x >> 5);
    int lane = threadIdx.x & 31;
    const float* hrow = h2 + (size_t)row * HID;

    float acc[NRES];
#pragma unroll
    for (int c = 0; c < NRES; c++) acc[c] = 0.f;

    for (int k = lane; k < HID; k += 32) {
        float a = hrow[k];
        const float* w = w3 + k * NRES;
#pragma unroll
        for (int c = 0; c < NRES; c++) acc[c] = fmaf(a, w[c], acc[c]);
    }
#pragma unroll
    for (int c = 0; c < NRES; c++)
#pragma unroll
        for (int o = 16; o; o >>= 1)
            acc[c] += __shfl_xor_sync(0xffffffffu, acc[c], o);

    if (lane == 0) {
        int best = 0; float bv = -INFINITY;
        float* lrow = out_logits + (size_t)row * NRES;
#pragma unroll
        for (int c = 0; c < NRES; c++) {
            float v = acc[c] + b3[c];
            lrow[c] = v;
            if (v > bv) { bv = v; best = c; }   // first max wins (strict >)
        }
        int s = fixed_mask[row] ? seq_t[row] : best;
        seq0i[row] = s;
        out_seq0f[row] = (float)s;
    }
}

// ---------------- geometry: one thread per residue ----------------
__global__ __launch_bounds__(128) void geom_kernel(
    const float* __restrict__ angles,          // [R,7,2]
    const float* __restrict__ rigids,          // [R,7]
    const int* __restrict__ residx,            // [R,37]
    const float* __restrict__ default_frames,  // [21,8,4,4]
    const int* __restrict__ group_idx,         // [21,14]
    const float* __restrict__ atom14_mask,     // [21,14]
    const float* __restrict__ atom37_mask,     // [21,37]
    const float* __restrict__ lit_positions,   // [21,14,3]
    const int* __restrict__ seq0i,
    float* __restrict__ out_pred,   // [R,14,3]
    float* __restrict__ out_final,  // [R,37,3]
    float* __restrict__ out_m14,    // [R,14]
    float* __restrict__ out_m37)    // [R,37]
{
    int r = blockIdx.x * blockDim.x + threadIdx.x;
    if (r >= RTOT) return;

    // backbone rigid: quat -> rot
    float q0 = rigids[r * 7 + 0], q1 = rigids[r * 7 + 1];
    float q2 = rigids[r * 7 + 2], q3 = rigids[r * 7 + 3];
    float tb0 = rigids[r * 7 + 4], tb1 = rigids[r * 7 + 5], tb2 = rigids[r * 7 + 6];
    float inv = rsqrtf(q0 * q0 + q1 * q1 + q2 * q2 + q3 * q3 + 1e-8f);
    float w = q0 * inv, x = q1 * inv, y = q2 * inv, z = q3 * inv;
    float rb[9];
    rb[0] = 1.f - 2.f * (y * y + z * z); rb[1] = 2.f * (x * y - w * z); rb[2] = 2.f * (x * z + w * y);
    rb[3] = 2.f * (x * y + w * z); rb[4] = 1.f - 2.f * (x * x + z * z); rb[5] = 2.f * (y * z - w * x);
    rb[6] = 2.f * (x * z - w * y); rb[7] = 2.f * (y * z + w * x); rb[8] = 1.f - 2.f * (x * x + y * y);

    int s = seq0i[r];

    float G[8][12];       // per group: global rot (9) + global trans (3)
    float chain_r[9], chain_t[3];   // running composed local frame (groups 4->7)

    for (int g = 0; g < 8; g++) {
        const float* df = default_frames + ((size_t)s * 8 + g) * 16;
        float dr[9], dt[3];
#pragma unroll
        for (int i = 0; i < 3; i++) {
            dr[i * 3 + 0] = df[i * 4 + 0];
            dr[i * 3 + 1] = df[i * 4 + 1];
            dr[i * 3 + 2] = df[i * 4 + 2];
            dt[i] = df[i * 4 + 3];
        }
        float sn, cs;
        if (g == 0) { sn = 0.f; cs = 1.f; }
        else { sn = angles[r * 14 + (g - 1) * 2 + 0]; cs = angles[r * 14 + (g - 1) * 2 + 1]; }

        // fr = dr @ [[1,0,0],[0,c,-s],[0,s,c]]
        float fr[9], ft[3];
#pragma unroll
        for (int i = 0; i < 3; i++) {
            fr[i * 3 + 0] = dr[i * 3 + 0];
            fr[i * 3 + 1] = dr[i * 3 + 1] * cs + dr[i * 3 + 2] * sn;
            fr[i * 3 + 2] = -dr[i * 3 + 1] * sn + dr[i * 3 + 2] * cs;
            ft[i] = dt[i];
        }

        float fo[9], to[3];   // frot_g / ftr_g in local (backbone) frame
        if (g <= 4) {
#pragma unroll
            for (int i = 0; i < 9; i++) fo[i] = fr[i];
#pragma unroll
            for (int i = 0; i < 3; i++) to[i] = ft[i];
            if (g == 4) {
#pragma unroll
                for (int i = 0; i < 9; i++) chain_r[i] = fr[i];
#pragma unroll
                for (int i = 0; i < 3; i++) chain_t[i] = ft[i];
            }
        } else {
            // chain = compose(chain, (fr, ft))
            float nr[9], nt[3];
#pragma unroll
            for (int i = 0; i < 3; i++) {
#pragma unroll
                for (int j = 0; j < 3; j++) {
                    nr[i * 3 + j] = chain_r[i * 3 + 0] * fr[0 * 3 + j]
                                  + chain_r[i * 3 + 1] * fr[1 * 3 + j]
                                  + chain_r[i * 3 + 2] * fr[2 * 3 + j];
                }
                nt[i] = chain_r[i * 3 + 0] * ft[0] + chain_r[i * 3 + 1] * ft[1]
                      + chain_r[i * 3 + 2] * ft[2] + chain_t[i];
            }
#pragma unroll
            for (int i = 0; i < 9; i++) { chain_r[i] = nr[i]; fo[i] = nr[i]; }
#pragma unroll
            for (int i = 0; i < 3; i++) { chain_t[i] = nt[i]; to[i] = nt[i]; }
        }

        // global = compose(rb, tb, fo, to)
#pragma unroll
        for (int i = 0; i < 3; i++) {
#pragma unroll
            for (int j = 0; j < 3; j++) {
                G[g][i * 3 + j] = rb[i * 3 + 0] * fo[0 * 3 + j]
                                + rb[i * 3 + 1] * fo[1 * 3 + j]
                                + rb[i * 3 + 2] * fo[2 * 3 + j];
            }
        }
        G[g][9]  = rb[0] * to[0] + rb[1] * to[1] + rb[2] * to[2] + tb0;
        G[g][10] = rb[3] * to[0] + rb[4] * to[1] + rb[5] * to[2] + tb1;
        G[g][11] = rb[6] * to[0] + rb[7] * to[1] + rb[8] * to[2] + tb2;
    }

    // atom14 positions
    float pv[14][3];
#pragma unroll
    for (int a = 0; a < 14; a++) {
        int gi = group_idx[s * 14 + a];
        const float* Gp = G[gi];
        float lx = lit_positions[((size_t)s * 14 + a) * 3 + 0];
        float ly = lit_positions[((size_t)s * 14 + a) * 3 + 1];
        float lz = lit_positions[((size_t)s * 14 + a) * 3 + 2];
        float m = atom14_mask[s * 14 + a];
        float px = (Gp[0] * lx + Gp[1] * ly + Gp[2] * lz + Gp[9])  * m;
        float py = (Gp[3] * lx + Gp[4] * ly + Gp[5] * lz + Gp[10]) * m;
        float pz = (Gp[6] * lx + Gp[7] * ly + Gp[8] * lz + Gp[11]) * m;
        pv[a][0] = px; pv[a][1] = py; pv[a][2] = pz;
        size_t po = ((size_t)r * 14 + a) * 3;
        out_pred[po + 0] = px; out_pred[po + 1] = py; out_pred[po + 2] = pz;
        out_m14[(size_t)r * 14 + a] = m;
    }

    // atom37 gather
#pragma unroll
    for (int j = 0; j < 37; j++) {
        int a = residx[(size_t)r * 37 + j];
        size_t fo_ = ((size_t)r * 37 + j) * 3;
        out_final[fo_ + 0] = pv[a][0];
        out_final[fo_ + 1] = pv[a][1];
        out_final[fo_ + 2] = pv[a][2];
        out_m37[(size_t)r * 37 + j] = atom37_mask[s * 37 + j];
    }
}

// ---------------- launcher ----------------
extern "C" void kernel_launch(void* const* d_in, const int* in_sizes, int n_in,
                              void* d_out, int out_size)
{
    const float* act        = (const float*)d_in[0];
    const float* angles     = (const float*)d_in[1];
    const float* rigids     = (const float*)d_in[2];
    const int*   fixed_mask = (const int*)d_in[3];
    const int*   seq_t      = (const int*)d_in[4];
    const int*   residx     = (const int*)d_in[5];
    const float* ln_g       = (const float*)d_in[6];
    const float* ln_b       = (const float*)d_in[7];
    const float* w1         = (const float*)d_in[8];
    const float* b1         = (const float*)d_in[9];
    const float* w2         = (const float*)d_in[10];
    const float* b2         = (const float*)d_in[11];
    const float* w3         = (const float*)d_in[12];
    const float* b3         = (const float*)d_in[13];
    const float* dframes    = (const float*)d_in[14];
    const int*   group_idx  = (const int*)d_in[15];
    const float* a14_mask   = (const float*)d_in[16];
    const float* a37_mask   = (const float*)d_in[17];
    const float* lit        = (const float*)d_in[18];

    float* out = (float*)d_out;
    float* out_logits = out + OFF_LOGITS;
    float* out_seq0   = out + OFF_SEQ0;
    float* out_pred   = out + OFF_PRED;
    float* out_final  = out + OFF_FINAL;
    float* out_m14    = out + OFF_M14;
    float* out_m37    = out + OFF_M37;

    float *xn, *h1, *h2;
    int* seq0i;
    cudaGetSymbolAddress((void**)&xn, g_xn);
    cudaGetSymbolAddress((void**)&h1, g_h1);
    cudaGetSymbolAddress((void**)&h2, g_h2);
    cudaGetSymbolAddress((void**)&seq0i, g_seq0i);

    // 1. LayerNorm
    ln_kernel<<<RTOT / 8, 256>>>(act, ln_g, ln_b, xn);

    // 2. GEMM1: xn[R,384] @ w1[384,1024] + b1, relu
    {
        dim3 grid(HID / BN, RTOT / BM);
        sgemm_kernel<true><<<grid, 256>>>(xn, w1, b1, h1, RTOT, HID, CIN);
    }
    // 3. GEMM2: h1 @ w2[1024,1024] + b2, relu
    {
        dim3 grid(HID / BN, RTOT / BM);
        sgemm_kernel<true><<<grid, 256>>>(h1, w2, b2, h2, RTOT, HID, HID);
    }
    // 4. logits + argmax + fixed-mask select
    head_kernel<<<RTOT / 8, 256>>>(h2, w3, b3, fixed_mask, seq_t,
                                   out_logits, out_seq0, seq0i);

    // 5. geometry
    geom_kernel<<<RTOT / 128, 128>>>(angles, rigids, residx, dframes, group_idx,
                                     a14_mask, a37_mask, lit, seq0i,
                                     out_pred, out_final, out_m14, out_m37);
}

// round 3
// speedup vs baseline: 1.0381x; 1.0381x over previous
#include <cuda_runtime.h>
#include <math.h>
#include <stdint.h>

// ---------------- problem constants ----------------
#define RTOT   32768          // B*N = 32*1024
#define CIN    384
#define HID    1024
#define NRES   20

// output layout (floats)
#define OFF_LOGITS 0
#define OFF_SEQ0   655360
#define OFF_PRED   688128
#define OFF_FINAL  2064384
#define OFF_M14    5701632
#define OFF_M37    6160384

// ---------------- scratch (no cudaMalloc allowed) ----------------
__device__ float g_xn_hi[(size_t)RTOT * CIN];
__device__ float g_xn_lo[(size_t)RTOT * CIN];
__device__ float g_h1_hi[(size_t)RTOT * HID];
__device__ float g_h1_lo[(size_t)RTOT * HID];
__device__ float g_h2[(size_t)RTOT * HID];
__device__ float g_wt1_hi[(size_t)HID * CIN];
__device__ float g_wt1_lo[(size_t)HID * CIN];
__device__ float g_wt2_hi[(size_t)HID * HID];
__device__ float g_wt2_lo[(size_t)HID * HID];
__device__ int   g_seq0i[RTOT];

__device__ __forceinline__ float tf32r(float v) {
    uint32_t u;
    asm("cvt.rna.tf32.f32 %0, %1;" : "=r"(u) : "f"(v));
    return __uint_as_float(u);
}

__device__ __forceinline__ void mma8(float c[4], const uint32_t a[4], const uint32_t b[2]) {
    asm volatile("mma.sync.aligned.m16n8k8.row.col.f32.tf32.tf32.f32 "
        "{%0,%1,%2,%3}, {%4,%5,%6,%7}, {%8,%9}, {%0,%1,%2,%3};"
        : "+f"(c[0]), "+f"(c[1]), "+f"(c[2]), "+f"(c[3])
        : "r"(a[0]), "r"(a[1]), "r"(a[2]), "r"(a[3]), "r"(b[0]), "r"(b[1]));
}

// ---------------- LayerNorm -> split tf32 hi/lo ----------------
__global__ __launch_bounds__(256) void ln_kernel(
    const float* __restrict__ act,
    const float* __restrict__ gamma,
    const float* __restrict__ beta,
    float* __restrict__ out_hi,
    float* __restrict__ out_lo)
{
    int row  = blockIdx.x * 8 + (threadIdx.x >> 5);
    int lane = threadIdx.x & 31;
    const float* x = act + (size_t)row * CIN;

    float v[12];
    float sum = 0.f;
#pragma unroll
    for (int i = 0; i < 12; i++) { v[i] = x[lane + i * 32]; sum += v[i]; }
#pragma unroll
    for (int o = 16; o; o >>= 1) sum += __shfl_xor_sync(0xffffffffu, sum, o);
    float mu = sum * (1.f / CIN);

    float vs = 0.f;
#pragma unroll
    for (int i = 0; i < 12; i++) { float d = v[i] - mu; vs += d * d; }
#pragma unroll
    for (int o = 16; o; o >>= 1) vs += __shfl_xor_sync(0xffffffffu, vs, o);
    float rstd = rsqrtf(vs * (1.f / CIN) + 1e-5f);

    float* oh = out_hi + (size_t)row * CIN;
    float* ol = out_lo + (size_t)row * CIN;
#pragma unroll
    for (int i = 0; i < 12; i++) {
        int c = lane + i * 32;
        float y = (v[i] - mu) * rstd * gamma[c] + beta[c];
        float hi = tf32r(y);
        oh[c] = hi;
        ol[c] = tf32r(y - hi);
    }
}

// ---------------- weight transpose + split: W[K,N] -> T[N,K] hi/lo ----------------
__global__ __launch_bounds__(256) void tsplit_kernel(
    const float* __restrict__ W, float* __restrict__ Th, float* __restrict__ Tl,
    int Krows, int Ncols)
{
    int t = blockIdx.x * 256 + threadIdx.x;
    if (t >= Krows * Ncols) return;
    int n = t / Krows;
    int k = t - n * Krows;
    float v = W[(size_t)k * Ncols + n];
    float hi = tf32r(v);
    Th[t] = hi;
    Tl[t] = tf32r(v - hi);
}

// ---------------- tf32x3 mma.sync GEMM ----------------
// C[M,1024] = relu(A[M,K] @ Bt[1024,K]^T + bias)
// block 128x128x32, 8 warps (4M x 2N), warp tile 32x64
#define SROW 36   // padded smem row stride (floats)

template<int K, bool SPLIT_OUT>
__global__ __launch_bounds__(256, 1) void mma_gemm_kernel(
    const float* __restrict__ Ah, const float* __restrict__ Al,
    const float* __restrict__ Bh, const float* __restrict__ Bl,
    const float* __restrict__ bias,
    float* __restrict__ Ch, float* __restrict__ Cl)
{
    constexpr int KT = K / 32;
    extern __shared__ float smem[];
    float* Ash = smem;                  // [128][SROW]
    float* Asl = Ash + 128 * SROW;
    float* Bsh = Asl + 128 * SROW;
    float* Bsl = Bsh + 128 * SROW;

    const int tid   = threadIdx.x;
    const int wid   = tid >> 5;
    const int lane  = tid & 31;
    const int warpM = wid & 3;          // 0..3
    const int warpN = wid >> 2;         // 0..1
    const int gr    = lane >> 2;        // 0..7
    const int tc    = lane & 3;         // 0..3

    const int m0 = blockIdx.y * 128;
    const int n0 = blockIdx.x * 128;

    // global load mapping: row = tid>>1 (0..127), kq = (tid&1)*16
    const int lrow = tid >> 1;
    const int kq   = (tid & 1) * 16;
    const float* gAh = Ah + (size_t)(m0 + lrow) * K + kq;
    const float* gAl = Al + (size_t)(m0 + lrow) * K + kq;
    const float* gBh = Bh + (size_t)(n0 + lrow) * K + kq;
    const float* gBl = Bl + (size_t)(n0 + lrow) * K + kq;
    float* sA_h = Ash + lrow * SROW + kq;
    float* sA_l = Asl + lrow * SROW + kq;
    float* sB_h = Bsh + lrow * SROW + kq;
    float* sB_l = Bsl + lrow * SROW + kq;

    // fragment base offsets
    const int aoff0 = (warpM * 32 + gr) * SROW + tc;          // msub 0
    const int boff0 = (warpN * 64 + gr) * SROW + tc;          // nsub 0

    float acc[2][8][4];
#pragma unroll
    for (int i = 0; i < 2; i++)
#pragma unroll
        for (int j = 0; j < 8; j++)
#pragma unroll
            for (int q = 0; q < 4; q++) acc[i][j][q] = 0.f;

    for (int kt = 0; kt < KT; ++kt) {
        __syncthreads();
        const int kg = kt * 32;
#pragma unroll
        for (int i = 0; i < 4; i++) {
            *(float4*)(sA_h + i * 4) = *(const float4*)(gAh + kg + i * 4);
            *(float4*)(sA_l + i * 4) = *(const float4*)(gAl + kg + i * 4);
            *(float4*)(sB_h + i * 4) = *(const float4*)(gBh + kg + i * 4);
            *(float4*)(sB_l + i * 4) = *(const float4*)(gBl + kg + i * 4);
        }
        __syncthreads();

#pragma unroll
        for (int ks = 0; ks < 4; ks++) {
            const int ko = ks * 8;
            uint32_t ah[2][4], al[2][4], bh[8][2], bl[8][2];
#pragma unroll
            for (int ms = 0; ms < 2; ms++) {
                int base = aoff0 + ms * 16 * SROW + ko;
                ah[ms][0] = __float_as_uint(Ash[base]);
                ah[ms][1] = __float_as_uint(Ash[base + 8 * SROW]);
                ah[ms][2] = __float_as_uint(Ash[base + 4]);
                ah[ms][3] = __float_as_uint(Ash[base + 8 * SROW + 4]);
                al[ms][0] = __float_as_uint(Asl[base]);
                al[ms][1] = __float_as_uint(Asl[base + 8 * SROW]);
                al[ms][2] = __float_as_uint(Asl[base + 4]);
                al[ms][3] = __float_as_uint(Asl[base + 8 * SROW + 4]);
            }
#pragma unroll
            for (int ns = 0; ns < 8; ns++) {
                int base = boff0 + ns * 8 * SROW + ko;
                bh[ns][0] = __float_as_uint(Bsh[base]);
                bh[ns][1] = __float_as_uint(Bsh[base + 4]);
                bl[ns][0] = __float_as_uint(Bsl[base]);
                bl[ns][1] = __float_as_uint(Bsl[base + 4]);
            }
            // pass 1: hi*hi
#pragma unroll
            for (int ms = 0; ms < 2; ms++)
#pragma unroll
                for (int ns = 0; ns < 8; ns++) mma8(acc[ms][ns], ah[ms], bh[ns]);
            // pass 2: hi*lo
#pragma unroll
            for (int ms = 0; ms < 2; ms++)
#pragma unroll
                for (int ns = 0; ns < 8; ns++) mma8(acc[ms][ns], ah[ms], bl[ns]);
            // pass 3: lo*hi
#pragma unroll
            for (int ms = 0; ms < 2; ms++)
#pragma unroll
                for (int ns = 0; ns < 8; ns++) mma8(acc[ms][ns], al[ms], bh[ns]);
        }
    }

    // epilogue: bias + relu (+ optional tf32 split), direct stores
    const int mwb = m0 + warpM * 32;
    const int nwb = n0 + warpN * 64;
#pragma unroll
    for (int ms = 0; ms < 2; ms++) {
        int r0 = mwb + ms * 16 + gr;
        int r1 = r0 + 8;
#pragma unroll
        for (int ns = 0; ns < 8; ns++) {
            int c = nwb + ns * 8 + 2 * tc;
            float bz0 = bias[c], bz1 = bias[c + 1];
            float v0 = fmaxf(acc[ms][ns][0] + bz0, 0.f);
            float v1 = fmaxf(acc[ms][ns][1] + bz1, 0.f);
            float v2 = fmaxf(acc[ms][ns][2] + bz0, 0.f);
            float v3 = fmaxf(acc[ms][ns][3] + bz1, 0.f);
            if (SPLIT_OUT) {
                float h0 = tf32r(v0), h1 = tf32r(v1), h2 = tf32r(v2), h3 = tf32r(v3);
                *(float2*)(Ch + (size_t)r0 * HID + c) = make_float2(h0, h1);
                *(float2*)(Ch + (size_t)r1 * HID + c) = make_float2(h2, h3);
                *(float2*)(Cl + (size_t)r0 * HID + c) =
                    make_float2(tf32r(v0 - h0), tf32r(v1 - h1));
                *(float2*)(Cl + (size_t)r1 * HID + c) =
                    make_float2(tf32r(v2 - h2), tf32r(v3 - h3));
            } else {
                *(float2*)(Ch + (size_t)r0 * HID + c) = make_float2(v0, v1);
                *(float2*)(Ch + (size_t)r1 * HID + c) = make_float2(v2, v3);
            }
        }
    }
}

// ---------------- head: logits = h2 @ w3 + b3, argmax, select ----------------
__global__ __launch_bounds__(256) void head_kernel(
    const float* __restrict__ h2,
    const float* __restrict__ w3,
    const float* __restrict__ b3,
    const int* __restrict__ fixed_mask,
    const int* __restrict__ seq_t,
    float* __restrict__ out_logits,
    float* __restrict__ out_seq0f,
    int* __restrict__ seq0i)
{
    extern __shared__ float w3s[];   // [20][1024]
    const int tid = threadIdx.x;
    const int wid = tid >> 5;
    const int lane = tid & 31;

    for (int i = tid; i < NRES * HID; i += 256) {
        int c = i >> 10;
        int k = i & 1023;
        w3s[i] = w3[k * NRES + c];
    }
    __syncthreads();

    const int rbase = blockIdx.x * 64 + wid * 8;
#pragma unroll
    for (int j = 0; j < 8; j += 2) {
        int ra = rbase + j, rb = ra + 1;
        const float* ha = h2 + (size_t)ra * HID;
        const float* hb = h2 + (size_t)rb * HID;
        float acc0[NRES], acc1[NRES];
#pragma unroll
        for (int c = 0; c < NRES; c++) { acc0[c] = 0.f; acc1[c] = 0.f; }
        for (int it = 0; it < 32; it++) {
            int k = it * 32 + lane;
            float va = ha[k];
            float vb = hb[k];
#pragma unroll
            for (int c = 0; c < NRES; c++) {
                float w = w3s[c * HID + k];
                acc0[c] = fmaf(va, w, acc0[c]);
                acc1[c] = fmaf(vb, w, acc1[c]);
            }
        }
#pragma unroll
        for (int c = 0; c < NRES; c++) {
#pragma unroll
            for (int o = 16; o; o >>= 1) {
                acc0[c] += __shfl_xor_sync(0xffffffffu, acc0[c], o);
                acc1[c] += __shfl_xor_sync(0xffffffffu, acc1[c], o);
            }
        }
        if (lane == 0) {
            int best0 = 0, best1 = 0;
            float bv0 = -INFINITY, bv1 = -INFINITY;
            float* l0 = out_logits + (size_t)ra * NRES;
            float* l1 = out_logits + (size_t)rb * NRES;
#pragma unroll
            for (int c = 0; c < NRES; c++) {
                float v0 = acc0[c] + b3[c];
                float v1 = acc1[c] + b3[c];
                l0[c] = v0; l1[c] = v1;
                if (v0 > bv0) { bv0 = v0; best0 = c; }
                if (v1 > bv1) { bv1 = v1; best1 = c; }
            }
            int s0 = fixed_mask[ra] ? seq_t[ra] : best0;
            int s1 = fixed_mask[rb] ? seq_t[rb] : best1;
            seq0i[ra] = s0; seq0i[rb] = s1;
            out_seq0f[ra] = (float)s0; out_seq0f[rb] = (float)s1;
        }
    }
}

// ---------------- geometry: one thread per residue ----------------
__global__ __launch_bounds__(128) void geom_kernel(
    const float* __restrict__ angles,
    const float* __restrict__ rigids,
    const int* __restrict__ residx,
    const float* __restrict__ default_frames,
    const int* __restrict__ group_idx,
    const float* __restrict__ atom14_mask,
    const float* __restrict__ atom37_mask,
    const float* __restrict__ lit_positions,
    const int* __restrict__ seq0i,
    float* __restrict__ out_pred,
    float* __restrict__ out_final,
    float* __restrict__ out_m14,
    float* __restrict__ out_m37)
{
    int r = blockIdx.x * blockDim.x + threadIdx.x;
    if (r >= RTOT) return;

    float q0 = rigids[r * 7 + 0], q1 = rigids[r * 7 + 1];
    float q2 = rigids[r * 7 + 2], q3 = rigids[r * 7 + 3];
    float tb0 = rigids[r * 7 + 4], tb1 = rigids[r * 7 + 5], tb2 = rigids[r * 7 + 6];
    float inv = rsqrtf(q0 * q0 + q1 * q1 + q2 * q2 + q3 * q3 + 1e-8f);
    float w = q0 * inv, x = q1 * inv, y = q2 * inv, z = q3 * inv;
    float rb[9];
    rb[0] = 1.f - 2.f * (y * y + z * z); rb[1] = 2.f * (x * y - w * z); rb[2] = 2.f * (x * z + w * y);
    rb[3] = 2.f * (x * y + w * z); rb[4] = 1.f - 2.f * (x * x + z * z); rb[5] = 2.f * (y * z - w * x);
    rb[6] = 2.f * (x * z - w * y); rb[7] = 2.f * (y * z + w * x); rb[8] = 1.f - 2.f * (x * x + y * y);

    int s = seq0i[r];

    float G[8][12];
    float chain_r[9], chain_t[3];

    for (int g = 0; g < 8; g++) {
        const float* df = default_frames + ((size_t)s * 8 + g) * 16;
        float dr[9], dt[3];
#pragma unroll
        for (int i = 0; i < 3; i++) {
            dr[i * 3 + 0] = df[i * 4 + 0];
            dr[i * 3 + 1] = df[i * 4 + 1];
            dr[i * 3 + 2] = df[i * 4 + 2];
            dt[i] = df[i * 4 + 3];
        }
        float sn, cs;
        if (g == 0) { sn = 0.f; cs = 1.f; }
        else { sn = angles[r * 14 + (g - 1) * 2 + 0]; cs = angles[r * 14 + (g - 1) * 2 + 1]; }

        float fr[9], ft[3];
#pragma unroll
        for (int i = 0; i < 3; i++) {
            fr[i * 3 + 0] = dr[i * 3 + 0];
            fr[i * 3 + 1] = dr[i * 3 + 1] * cs + dr[i * 3 + 2] * sn;
            fr[i * 3 + 2] = -dr[i * 3 + 1] * sn + dr[i * 3 + 2] * cs;
            ft[i] = dt[i];
        }

        float fo[9], to[3];
        if (g <= 4) {
#pragma unroll
            for (int i = 0; i < 9; i++) fo[i] = fr[i];
#pragma unroll
            for (int i = 0; i < 3; i++) to[i] = ft[i];
            if (g == 4) {
#pragma unroll
                for (int i = 0; i < 9; i++) chain_r[i] = fr[i];
#pragma unroll
                for (int i = 0; i < 3; i++) chain_t[i] = ft[i];
            }
        } else {
            float nr[9], nt[3];
#pragma unroll
            for (int i = 0; i < 3; i++) {
#pragma unroll
                for (int j = 0; j < 3; j++) {
                    nr[i * 3 + j] = chain_r[i * 3 + 0] * fr[0 * 3 + j]
                                  + chain_r[i * 3 + 1] * fr[1 * 3 + j]
                                  + chain_r[i * 3 + 2] * fr[2 * 3 + j];
                }
                nt[i] = chain_r[i * 3 + 0] * ft[0] + chain_r[i * 3 + 1] * ft[1]
                      + chain_r[i * 3 + 2] * ft[2] + chain_t[i];
            }
#pragma unroll
            for (int i = 0; i < 9; i++) { chain_r[i] = nr[i]; fo[i] = nr[i]; }
#pragma unroll
            for (int i = 0; i < 3; i++) { chain_t[i] = nt[i]; to[i] = nt[i]; }
        }

#pragma unroll
        for (int i = 0; i < 3; i++) {
#pragma unroll
            for (int j = 0; j < 3; j++) {
                G[g][i * 3 + j] = rb[i * 3 + 0] * fo[0 * 3 + j]
                                + rb[i * 3 + 1] * fo[1 * 3 + j]
                                + rb[i * 3 + 2] * fo[2 * 3 + j];
            }
        }
        G[g][9]  = rb[0] * to[0] + rb[1] * to[1] + rb[2] * to[2] + tb0;
        G[g][10] = rb[3] * to[0] + rb[4] * to[1] + rb[5] * to[2] + tb1;
        G[g][11] = rb[6] * to[0] + rb[7] * to[1] + rb[8] * to[2] + tb2;
    }

    float pv[14][3];
#pragma unroll
    for (int a = 0; a < 14; a++) {
        int gi = group_idx[s * 14 + a];
        const float* Gp = G[gi];
        float lx = lit_positions[((size_t)s * 14 + a) * 3 + 0];
        float ly = lit_positions[((size_t)s * 14 + a) * 3 + 1];
        float lz = lit_positions[((size_t)s * 14 + a) * 3 + 2];
        float m = atom14_mask[s * 14 + a];
        float px = (Gp[0] * lx + Gp[1] * ly + Gp[2] * lz + Gp[9])  * m;
        float py = (Gp[3] * lx + Gp[4] * ly + Gp[5] * lz + Gp[10]) * m;
        float pz = (Gp[6] * lx + Gp[7] * ly + Gp[8] * lz + Gp[11]) * m;
        pv[a][0] = px; pv[a][1] = py; pv[a][2] = pz;
        size_t po = ((size_t)r * 14 + a) * 3;
        out_pred[po + 0] = px; out_pred[po + 1] = py; out_pred[po + 2] = pz;
        out_m14[(size_t)r * 14 + a] = m;
    }

#pragma unroll
    for (int j = 0; j < 37; j++) {
        int a = residx[(size_t)r * 37 + j];
        size_t fo_ = ((size_t)r * 37 + j) * 3;
        out_final[fo_ + 0] = pv[a][0];
        out_final[fo_ + 1] = pv[a][1];
        out_final[fo_ + 2] = pv[a][2];
        out_m37[(size_t)r * 37 + j] = atom37_mask[s * 37 + j];
    }
}

// ---------------- launcher ----------------
extern "C" void kernel_launch(void* const* d_in, const int* in_sizes, int n_in,
                              void* d_out, int out_size)
{
    const float* act        = (const float*)d_in[0];
    const float* angles     = (const float*)d_in[1];
    const float* rigids     = (const float*)d_in[2];
    const int*   fixed_mask = (const int*)d_in[3];
    const int*   seq_t      = (const int*)d_in[4];
    const int*   residx     = (const int*)d_in[5];
    const float* ln_g       = (const float*)d_in[6];
    const float* ln_b       = (const float*)d_in[7];
    const float* w1         = (const float*)d_in[8];
    const float* b1         = (const float*)d_in[9];
    const float* w2         = (const float*)d_in[10];
    const float* b2         = (const float*)d_in[11];
    const float* w3         = (const float*)d_in[12];
    const float* b3         = (const float*)d_in[13];
    const float* dframes    = (const float*)d_in[14];
    const int*   group_idx  = (const int*)d_in[15];
    const float* a14_mask   = (const float*)d_in[16];
    const float* a37_mask   = (const float*)d_in[17];
    const float* lit        = (const float*)d_in[18];

    float* out = (float*)d_out;
    float* out_logits = out + OFF_LOGITS;
    float* out_seq0   = out + OFF_SEQ0;
    float* out_pred   = out + OFF_PRED;
    float* out_final  = out + OFF_FINAL;
    float* out_m14    = out + OFF_M14;
    float* out_m37    = out + OFF_M37;

    float *xnh, *xnl, *h1h, *h1l, *h2, *wt1h, *wt1l, *wt2h, *wt2l;
    int* seq0i;
    cudaGetSymbolAddress((void**)&xnh, g_xn_hi);
    cudaGetSymbolAddress((void**)&xnl, g_xn_lo);
    cudaGetSymbolAddress((void**)&h1h, g_h1_hi);
    cudaGetSymbolAddress((void**)&h1l, g_h1_lo);
    cudaGetSymbolAddress((void**)&h2,  g_h2);
    cudaGetSymbolAddress((void**)&wt1h, g_wt1_hi);
    cudaGetSymbolAddress((void**)&wt1l, g_wt1_lo);
    cudaGetSymbolAddress((void**)&wt2h, g_wt2_hi);
    cudaGetSymbolAddress((void**)&wt2l, g_wt2_lo);
    cudaGetSymbolAddress((void**)&seq0i, g_seq0i);

    const int GEMM_SMEM = 4 * 128 * SROW * 4;   // 73728 B
    cudaFuncSetAttribute(mma_gemm_kernel<CIN, true>,
                         cudaFuncAttributeMaxDynamicSharedMemorySize, GEMM_SMEM);
    cudaFuncSetAttribute(mma_gemm_kernel<HID, false>,
                         cudaFuncAttributeMaxDynamicSharedMemorySize, GEMM_SMEM);
    cudaFuncSetAttribute(head_kernel,
                         cudaFuncAttributeMaxDynamicSharedMemorySize, NRES * HID * 4);

    // 1. LayerNorm with tf32 split output
    ln_kernel<<<RTOT / 8, 256>>>(act, ln_g, ln_b, xnh, xnl);

    // 2. weight prep: transpose + tf32 split
    tsplit_kernel<<<(CIN * HID + 255) / 256, 256>>>(w1, wt1h, wt1l, CIN, HID);
    tsplit_kernel<<<(HID * HID + 255) / 256, 256>>>(w2, wt2h, wt2l, HID, HID);

    // 3. GEMM1: relu(xn @ w1 + b1) -> h1 (split)
    {
        dim3 grid(HID / 128, RTOT / 128);
        mma_gemm_kernel<CIN, true><<<grid, 256, GEMM_SMEM>>>(
            xnh, xnl, wt1h, wt1l, b1, h1h, h1l);
    }
    // 4. GEMM2: relu(h1 @ w2 + b2) -> h2
    {
        dim3 grid(HID / 128, RTOT / 128);
        mma_gemm_kernel<HID, false><<<grid, 256, GEMM_SMEM>>>(
            h1h, h1l, wt2h, wt2l, b2, h2, nullptr);
    }
    // 5. logits + argmax + select
    head_kernel<<<RTOT / 64, 256, NRES * HID * 4>>>(h2, w3, b3, fixed_mask, seq_t,
                                                    out_logits, out_seq0, seq0i);
    // 6. geometry
    geom_kernel<<<RTOT / 128, 128>>>(angles, rigids, residx, dframes, group_idx,
                                     a14_mask, a37_mask, lit, seq0i,
                                     out_pred, out_final, out_m14, out_m37);
}

// round 4
// speedup vs baseline: 1.0773x; 1.0378x over previous
#include <cuda_runtime.h>
#include <math.h>
#include <stdint.h>

// ---------------- problem constants ----------------
#define RTOT   32768          // B*N = 32*1024
#define CIN    384
#define HID    1024
#define NRES   20

// output layout (floats)
#define OFF_LOGITS 0
#define OFF_SEQ0   655360
#define OFF_PRED   688128
#define OFF_FINAL  2064384
#define OFF_M14    5701632
#define OFF_M37    6160384

// ---------------- scratch (no cudaMalloc allowed) ----------------
__device__ float g_xn_hi[(size_t)RTOT * CIN];
__device__ float g_xn_lo[(size_t)RTOT * CIN];
__device__ float g_h1_hi[(size_t)RTOT * HID];
__device__ float g_h1_lo[(size_t)RTOT * HID];
__device__ float g_h2[(size_t)RTOT * HID];
__device__ float g_wt1_hi[(size_t)HID * CIN];
__device__ float g_wt1_lo[(size_t)HID * CIN];
__device__ float g_wt2_hi[(size_t)HID * HID];
__device__ float g_wt2_lo[(size_t)HID * HID];
__device__ int   g_seq0i[RTOT];

__device__ __forceinline__ float tf32r(float v) {
    uint32_t u;
    asm("cvt.rna.tf32.f32 %0, %1;" : "=r"(u) : "f"(v));
    return __uint_as_float(u);
}

__device__ __forceinline__ void mma8(float c[4], const uint32_t a[4], const uint32_t b[2]) {
    asm volatile("mma.sync.aligned.m16n8k8.row.col.f32.tf32.tf32.f32 "
        "{%0,%1,%2,%3}, {%4,%5,%6,%7}, {%8,%9}, {%0,%1,%2,%3};"
        : "+f"(c[0]), "+f"(c[1]), "+f"(c[2]), "+f"(c[3])
        : "r"(a[0]), "r"(a[1]), "r"(a[2]), "r"(a[3]), "r"(b[0]), "r"(b[1]));
}

__device__ __forceinline__ uint32_t smem_u32(const void* p) {
    uint32_t a;
    asm("{ .reg .u64 t; cvta.to.shared.u64 t, %1; cvt.u32.u64 %0, t; }" : "=r"(a) : "l"(p));
    return a;
}

#define CP16(dst, src) \
    asm volatile("cp.async.cg.shared.global [%0], [%1], 16;" :: "r"(dst), "l"(src))
#define CP_COMMIT() asm volatile("cp.async.commit_group;" ::: "memory")
#define CP_WAIT(n)  asm volatile("cp.async.wait_group %0;" :: "n"(n) : "memory")

// ---------------- LayerNorm -> split tf32 hi/lo ----------------
__global__ __launch_bounds__(256) void ln_kernel(
    const float* __restrict__ act,
    const float* __restrict__ gamma,
    const float* __restrict__ beta,
    float* __restrict__ out_hi,
    float* __restrict__ out_lo)
{
    int row  = blockIdx.x * 8 + (threadIdx.x >> 5);
    int lane = threadIdx.x & 31;
    const float* x = act + (size_t)row * CIN;

    float v[12];
    float sum = 0.f;
#pragma unroll
    for (int i = 0; i < 12; i++) { v[i] = x[lane + i * 32]; sum += v[i]; }
#pragma unroll
    for (int o = 16; o; o >>= 1) sum += __shfl_xor_sync(0xffffffffu, sum, o);
    float mu = sum * (1.f / CIN);

    float vs = 0.f;
#pragma unroll
    for (int i = 0; i < 12; i++) { float d = v[i] - mu; vs += d * d; }
#pragma unroll
    for (int o = 16; o; o >>= 1) vs += __shfl_xor_sync(0xffffffffu, vs, o);
    float rstd = rsqrtf(vs * (1.f / CIN) + 1e-5f);

    float* oh = out_hi + (size_t)row * CIN;
    float* ol = out_lo + (size_t)row * CIN;
#pragma unroll
    for (int i = 0; i < 12; i++) {
        int c = lane + i * 32;
        float y = (v[i] - mu) * rstd * gamma[c] + beta[c];
        float hi = tf32r(y);
        oh[c] = hi;
        ol[c] = tf32r(y - hi);
    }
}

// ---------------- coalesced transpose + tf32 split: W[K,N] -> T[N,K] hi/lo ----------------
__global__ __launch_bounds__(256) void tsplit_kernel(
    const float* __restrict__ W, float* __restrict__ Th, float* __restrict__ Tl,
    int Krows, int Ncols)
{
    __shared__ float t[32][33];
    const int tx = threadIdx.x;    // 0..31
    const int ty = threadIdx.y;    // 0..7
    const int n0 = blockIdx.x * 32;
    const int k0 = blockIdx.y * 32;

#pragma unroll
    for (int j = ty; j < 32; j += 8)
        t[j][tx] = W[(size_t)(k0 + j) * Ncols + n0 + tx];
    __syncthreads();

#pragma unroll
    for (int j = ty; j < 32; j += 8) {
        float v = t[tx][j];
        float hi = tf32r(v);
        size_t o = (size_t)(n0 + j) * Krows + k0 + tx;
        Th[o] = hi;
        Tl[o] = tf32r(v - hi);
    }
}

// ---------------- tf32x3 mma.sync GEMM, cp.async double-buffered ----------------
// C[M,1024] = relu(A[M,K] @ Bt[1024,K]^T + bias)
// block 128x128x32, 8 warps (4M x 2N), warp tile 32x64
#define SROW 36                       // padded smem row stride (floats)
#define BUFF (4 * 128 * SROW)         // floats per stage (Ah, Al, Bh, Bl)

template<int K, bool SPLIT_OUT>
__global__ __launch_bounds__(256, 1) void mma_gemm_kernel(
    const float* __restrict__ Ah, const float* __restrict__ Al,
    const float* __restrict__ Bh, const float* __restrict__ Bl,
    const float* __restrict__ bias,
    float* __restrict__ Ch, float* __restrict__ Cl)
{
    constexpr int KT = K / 32;
    extern __shared__ float smem[];

    const int tid   = threadIdx.x;
    const int wid   = tid >> 5;
    const int lane  = tid & 31;
    const int warpM = wid & 3;
    const int warpN = wid >> 2;
    const int gr    = lane >> 2;
    const int tc    = lane & 3;

    const int m0 = blockIdx.y * 128;
    const int n0 = blockIdx.x * 128;

    // global load mapping: row = tid>>1 (0..127), kq = (tid&1)*16
    const int lrow = tid >> 1;
    const int kq   = (tid & 1) * 16;
    const float* gAh = Ah + (size_t)(m0 + lrow) * K + kq;
    const float* gAl = Al + (size_t)(m0 + lrow) * K + kq;
    const float* gBh = Bh + (size_t)(n0 + lrow) * K + kq;
    const float* gBl = Bl + (size_t)(n0 + lrow) * K + kq;

    const uint32_t sbase = smem_u32(smem);
    // smem byte dst for this thread within a stage, array a (0=Ah,1=Al,2=Bh,3=Bl)
    const uint32_t trd = (uint32_t)(lrow * SROW + kq) * 4;

    // fragment base offsets (floats)
    const int aoff0 = (warpM * 32 + gr) * SROW + tc;
    const int boff0 = (warpN * 64 + gr) * SROW + tc;

    float acc[2][8][4];
#pragma unroll
    for (int i = 0; i < 2; i++)
#pragma unroll
        for (int j = 0; j < 8; j++)
#pragma unroll
            for (int q = 0; q < 4; q++) acc[i][j][q] = 0.f;

    // issue stage-0 loads
    {
        const uint32_t db = sbase + trd;
#pragma unroll
        for (int i = 0; i < 4; i++) {
            CP16(db + 0 * (BUFF / 4) * 16 * 4 / 16 * 16 + i * 16, gAh + i * 4);
        }
        // (rewritten explicitly below for clarity; the loop above handles Ah only)
#pragma unroll
        for (int i = 0; i < 4; i++) CP16(db + (1 * 128 * SROW) * 4 + i * 16, gAl + i * 4);
#pragma unroll
        for (int i = 0; i < 4; i++) CP16(db + (2 * 128 * SROW) * 4 + i * 16, gBh + i * 4);
#pragma unroll
        for (int i = 0; i < 4; i++) CP16(db + (3 * 128 * SROW) * 4 + i * 16, gBl + i * 4);
        CP_COMMIT();
    }

    for (int kt = 0; kt < KT; ++kt) {
        const int buf = kt & 1;
        // prefetch next tile into the other stage
        if (kt + 1 < KT) {
            const int kg = (kt + 1) * 32;
            const uint32_t db = sbase + (uint32_t)((kt + 1) & 1) * BUFF * 4 + trd;
#pragma unroll
            for (int i = 0; i < 4; i++) CP16(db + i * 16, gAh + kg + i * 4);
#pragma unroll
            for (int i = 0; i < 4; i++) CP16(db + (1 * 128 * SROW) * 4 + i * 16, gAl + kg + i * 4);
#pragma unroll
            for (int i = 0; i < 4; i++) CP16(db + (2 * 128 * SROW) * 4 + i * 16, gBh + kg + i * 4);
#pragma unroll
            for (int i = 0; i < 4; i++) CP16(db + (3 * 128 * SROW) * 4 + i * 16, gBl + kg + i * 4);
            CP_COMMIT();
            CP_WAIT(1);
        } else {
            CP_WAIT(0);
        }
        __syncthreads();

        const float* Ash = smem + buf * BUFF;
        const float* Asl = Ash + 128 * SROW;
        const float* Bsh = Asl + 128 * SROW;
        const float* Bsl = Bsh + 128 * SROW;

#pragma unroll
        for (int ks = 0; ks < 4; ks++) {
            const int ko = ks * 8;
            uint32_t ah[2][4], al[2][4], bh[8][2], bl[8][2];
#pragma unroll
            for (int ms = 0; ms < 2; ms++) {
                int base = aoff0 + ms * 16 * SROW + ko;
                ah[ms][0] = __float_as_uint(Ash[base]);
                ah[ms][1] = __float_as_uint(Ash[base + 8 * SROW]);
                ah[ms][2] = __float_as_uint(Ash[base + 4]);
                ah[ms][3] = __float_as_uint(Ash[base + 8 * SROW + 4]);
                al[ms][0] = __float_as_uint(Asl[base]);
                al[ms][1] = __float_as_uint(Asl[base + 8 * SROW]);
                al[ms][2] = __float_as_uint(Asl[base + 4]);
                al[ms][3] = __float_as_uint(Asl[base + 8 * SROW + 4]);
            }
#pragma unroll
            for (int ns = 0; ns < 8; ns++) {
                int base = boff0 + ns * 8 * SROW + ko;
                bh[ns][0] = __float_as_uint(Bsh[base]);
                bh[ns][1] = __float_as_uint(Bsh[base + 4]);
                bl[ns][0] = __float_as_uint(Bsl[base]);
                bl[ns][1] = __float_as_uint(Bsl[base + 4]);
            }
#pragma unroll
            for (int ms = 0; ms < 2; ms++)
#pragma unroll
                for (int ns = 0; ns < 8; ns++) mma8(acc[ms][ns], ah[ms], bh[ns]);
#pragma unroll
            for (int ms = 0; ms < 2; ms++)
#pragma unroll
                for (int ns = 0; ns < 8; ns++) mma8(acc[ms][ns], ah[ms], bl[ns]);
#pragma unroll
            for (int ms = 0; ms < 2; ms++)
#pragma unroll
                for (int ns = 0; ns < 8; ns++) mma8(acc[ms][ns], al[ms], bh[ns]);
        }
        __syncthreads();
    }

    // epilogue: bias + relu (+ optional tf32 split), direct stores
    const int mwb = m0 + warpM * 32;
    const int nwb = n0 + warpN * 64;
#pragma unroll
    for (int ms = 0; ms < 2; ms++) {
        int r0 = mwb + ms * 16 + gr;
        int r1 = r0 + 8;
#pragma unroll
        for (int ns = 0; ns < 8; ns++) {
            int c = nwb + ns * 8 + 2 * tc;
            float bz0 = bias[c], bz1 = bias[c + 1];
            float v0 = fmaxf(acc[ms][ns][0] + bz0, 0.f);
            float v1 = fmaxf(acc[ms][ns][1] + bz1, 0.f);
            float v2 = fmaxf(acc[ms][ns][2] + bz0, 0.f);
            float v3 = fmaxf(acc[ms][ns][3] + bz1, 0.f);
            if (SPLIT_OUT) {
                float h0 = tf32r(v0), h1 = tf32r(v1), h2 = tf32r(v2), h3 = tf32r(v3);
                *(float2*)(Ch + (size_t)r0 * HID + c) = make_float2(h0, h1);
                *(float2*)(Ch + (size_t)r1 * HID + c) = make_float2(h2, h3);
                *(float2*)(Cl + (size_t)r0 * HID + c) =
                    make_float2(tf32r(v0 - h0), tf32r(v1 - h1));
                *(float2*)(Cl + (size_t)r1 * HID + c) =
                    make_float2(tf32r(v2 - h2), tf32r(v3 - h3));
            } else {
                *(float2*)(Ch + (size_t)r0 * HID + c) = make_float2(v0, v1);
                *(float2*)(Ch + (size_t)r1 * HID + c) = make_float2(v2, v3);
            }
        }
    }
}

// ---------------- head: logits = h2 @ w3 + b3, argmax, select ----------------
__global__ __launch_bounds__(256) void head_kernel(
    const float* __restrict__ h2,
    const float* __restrict__ w3,
    const float* __restrict__ b3,
    const int* __restrict__ fixed_mask,
    const int* __restrict__ seq_t,
    float* __restrict__ out_logits,
    float* __restrict__ out_seq0f,
    int* __restrict__ seq0i)
{
    extern __shared__ float w3s[];   // [20][1024]
    const int tid = threadIdx.x;
    const int wid = tid >> 5;
    const int lane = tid & 31;

    for (int i = tid; i < NRES * HID; i += 256) {
        int c = i >> 10;
        int k = i & 1023;
        w3s[i] = w3[k * NRES + c];
    }
    __syncthreads();

    const int rbase = blockIdx.x * 64 + wid * 8;
#pragma unroll
    for (int j = 0; j < 8; j += 2) {
        int ra = rbase + j, rb = ra + 1;
        const float* ha = h2 + (size_t)ra * HID;
        const float* hb = h2 + (size_t)rb * HID;
        float acc0[NRES], acc1[NRES];
#pragma unroll
        for (int c = 0; c < NRES; c++) { acc0[c] = 0.f; acc1[c] = 0.f; }
        for (int it = 0; it < 32; it++) {
            int k = it * 32 + lane;
            float va = ha[k];
            float vb = hb[k];
#pragma unroll
            for (int c = 0; c < NRES; c++) {
                float w = w3s[c * HID + k];
                acc0[c] = fmaf(va, w, acc0[c]);
                acc1[c] = fmaf(vb, w, acc1[c]);
            }
        }
#pragma unroll
        for (int c = 0; c < NRES; c++) {
#pragma unroll
            for (int o = 16; o; o >>= 1) {
                acc0[c] += __shfl_xor_sync(0xffffffffu, acc0[c], o);
                acc1[c] += __shfl_xor_sync(0xffffffffu, acc1[c], o);
            }
        }
        if (lane == 0) {
            int best0 = 0, best1 = 0;
            float bv0 = -INFINITY, bv1 = -INFINITY;
            float* l0 = out_logits + (size_t)ra * NRES;
            float* l1 = out_logits + (size_t)rb * NRES;
#pragma unroll
            for (int c = 0; c < NRES; c++) {
                float v0 = acc0[c] + b3[c];
                float v1 = acc1[c] + b3[c];
                l0[c] = v0; l1[c] = v1;
                if (v0 > bv0) { bv0 = v0; best0 = c; }
                if (v1 > bv1) { bv1 = v1; best1 = c; }
            }
            int s0 = fixed_mask[ra] ? seq_t[ra] : best0;
            int s1 = fixed_mask[rb] ? seq_t[rb] : best1;
            seq0i[ra] = s0; seq0i[rb] = s1;
            out_seq0f[ra] = (float)s0; out_seq0f[rb] = (float)s1;
        }
    }
}

// ---------------- geometry: one thread per residue ----------------
__global__ __launch_bounds__(128) void geom_kernel(
    const float* __restrict__ angles,
    const float* __restrict__ rigids,
    const int* __restrict__ residx,
    const float* __restrict__ default_frames,
    const int* __restrict__ group_idx,
    const float* __restrict__ atom14_mask,
    const float* __restrict__ atom37_mask,
    const float* __restrict__ lit_positions,
    const int* __restrict__ seq0i,
    float* __restrict__ out_pred,
    float* __restrict__ out_final,
    float* __restrict__ out_m14,
    float* __restrict__ out_m37)
{
    int r = blockIdx.x * blockDim.x + threadIdx.x;
    if (r >= RTOT) return;

    float q0 = rigids[r * 7 + 0], q1 = rigids[r * 7 + 1];
    float q2 = rigids[r * 7 + 2], q3 = rigids[r * 7 + 3];
    float tb0 = rigids[r * 7 + 4], tb1 = rigids[r * 7 + 5], tb2 = rigids[r * 7 + 6];
    float inv = rsqrtf(q0 * q0 + q1 * q1 + q2 * q2 + q3 * q3 + 1e-8f);
    float w = q0 * inv, x = q1 * inv, y = q2 * inv, z = q3 * inv;
    float rb[9];
    rb[0] = 1.f - 2.f * (y * y + z * z); rb[1] = 2.f * (x * y - w * z); rb[2] = 2.f * (x * z + w * y);
    rb[3] = 2.f * (x * y + w * z); rb[4] = 1.f - 2.f * (x * x + z * z); rb[5] = 2.f * (y * z - w * x);
    rb[6] = 2.f * (x * z - w * y); rb[7] = 2.f * (y * z + w * x); rb[8] = 1.f - 2.f * (x * x + y * y);

    int s = seq0i[r];

    float G[8][12];
    float chain_r[9], chain_t[3];

    for (int g = 0; g < 8; g++) {
        const float* df = default_frames + ((size_t)s * 8 + g) * 16;
        float dr[9], dt[3];
#pragma unroll
        for (int i = 0; i < 3; i++) {
            dr[i * 3 + 0] = df[i * 4 + 0];
            dr[i * 3 + 1] = df[i * 4 + 1];
            dr[i * 3 + 2] = df[i * 4 + 2];
            dt[i] = df[i * 4 + 3];
        }
        float sn, cs;
        if (g == 0) { sn = 0.f; cs = 1.f; }
        else { sn = angles[r * 14 + (g - 1) * 2 + 0]; cs = angles[r * 14 + (g - 1) * 2 + 1]; }

        float fr[9], ft[3];
#pragma unroll
        for (int i = 0; i < 3; i++) {
            fr[i * 3 + 0] = dr[i * 3 + 0];
            fr[i * 3 + 1] = dr[i * 3 + 1] * cs + dr[i * 3 + 2] * sn;
            fr[i * 3 + 2] = -dr[i * 3 + 1] * sn + dr[i * 3 + 2] * cs;
            ft[i] = dt[i];
        }

        float fo[9], to[3];
        if (g <= 4) {
#pragma unroll
            for (int i = 0; i < 9; i++) fo[i] = fr[i];
#pragma unroll
            for (int i = 0; i < 3; i++) to[i] = ft[i];
            if (g == 4) {
#pragma unroll
                for (int i = 0; i < 9; i++) chain_r[i] = fr[i];
#pragma unroll
                for (int i = 0; i < 3; i++) chain_t[i] = ft[i];
            }
        } else {
            float nr[9], nt[3];
#pragma unroll
            for (int i = 0; i < 3; i++) {
#pragma unroll
                for (int j = 0; j < 3; j++) {
                    nr[i * 3 + j] = chain_r[i * 3 + 0] * fr[0 * 3 + j]
                                  + chain_r[i * 3 + 1] * fr[1 * 3 + j]
                                  + chain_r[i * 3 + 2] * fr[2 * 3 + j];
                }
                nt[i] = chain_r[i * 3 + 0] * ft[0] + chain_r[i * 3 + 1] * ft[1]
                      + chain_r[i * 3 + 2] * ft[2] + chain_t[i];
            }
#pragma unroll
            for (int i = 0; i < 9; i++) { chain_r[i] = nr[i]; fo[i] = nr[i]; }
#pragma unroll
            for (int i = 0; i < 3; i++) { chain_t[i] = nt[i]; to[i] = nt[i]; }
        }

#pragma unroll
        for (int i = 0; i < 3; i++) {
#pragma unroll
            for (int j = 0; j < 3; j++) {
                G[g][i * 3 + j] = rb[i * 3 + 0] * fo[0 * 3 + j]
                                + rb[i * 3 + 1] * fo[1 * 3 + j]
                                + rb[i * 3 + 2] * fo[2 * 3 + j];
            }
        }
        G[g][9]  = rb[0] * to[0] + rb[1] * to[1] + rb[2] * to[2] + tb0;
        G[g][10] = rb[3] * to[0] + rb[4] * to[1] + rb[5] * to[2] + tb1;
        G[g][11] = rb[6] * to[0] + rb[7] * to[1] + rb[8] * to[2] + tb2;
    }

    float pv[14][3];
#pragma unroll
    for (int a = 0; a < 14; a++) {
        int gi = group_idx[s * 14 + a];
        const float* Gp = G[gi];
        float lx = lit_positions[((size_t)s * 14 + a) * 3 + 0];
        float ly = lit_positions[((size_t)s * 14 + a) * 3 + 1];
        float lz = lit_positions[((size_t)s * 14 + a) * 3 + 2];
        float m = atom14_mask[s * 14 + a];
        float px = (Gp[0] * lx + Gp[1] * ly + Gp[2] * lz + Gp[9])  * m;
        float py = (Gp[3] * lx + Gp[4] * ly + Gp[5] * lz + Gp[10]) * m;
        float pz = (Gp[6] * lx + Gp[7] * ly + Gp[8] * lz + Gp[11]) * m;
        pv[a][0] = px; pv[a][1] = py; pv[a][2] = pz;
        size_t po = ((size_t)r * 14 + a) * 3;
        out_pred[po + 0] = px; out_pred[po + 1] = py; out_pred[po + 2] = pz;
        out_m14[(size_t)r * 14 + a] = m;
    }

#pragma unroll
    for (int j = 0; j < 37; j++) {
        int a = residx[(size_t)r * 37 + j];
        size_t fo_ = ((size_t)r * 37 + j) * 3;
        out_final[fo_ + 0] = pv[a][0];
        out_final[fo_ + 1] = pv[a][1];
        out_final[fo_ + 2] = pv[a][2];
        out_m37[(size_t)r * 37 + j] = atom37_mask[s * 37 + j];
    }
}

// ---------------- launcher ----------------
extern "C" void kernel_launch(void* const* d_in, const int* in_sizes, int n_in,
                              void* d_out, int out_size)
{
    const float* act        = (const float*)d_in[0];
    const float* angles     = (const float*)d_in[1];
    const float* rigids     = (const float*)d_in[2];
    const int*   fixed_mask = (const int*)d_in[3];
    const int*   seq_t      = (const int*)d_in[4];
    const int*   residx     = (const int*)d_in[5];
    const float* ln_g       = (const float*)d_in[6];
    const float* ln_b       = (const float*)d_in[7];
    const float* w1         = (const float*)d_in[8];
    const float* b1         = (const float*)d_in[9];
    const float* w2         = (const float*)d_in[10];
    const float* b2         = (const float*)d_in[11];
    const float* w3         = (const float*)d_in[12];
    const float* b3         = (const float*)d_in[13];
    const float* dframes    = (const float*)d_in[14];
    const int*   group_idx  = (const int*)d_in[15];
    const float* a14_mask   = (const float*)d_in[16];
    const float* a37_mask   = (const float*)d_in[17];
    const float* lit        = (const float*)d_in[18];

    float* out = (float*)d_out;
    float* out_logits = out + OFF_LOGITS;
    float* out_seq0   = out + OFF_SEQ0;
    float* out_pred   = out + OFF_PRED;
    float* out_final  = out + OFF_FINAL;
    float* out_m14    = out + OFF_M14;
    float* out_m37    = out + OFF_M37;

    float *xnh, *xnl, *h1h, *h1l, *h2, *wt1h, *wt1l, *wt2h, *wt2l;
    int* seq0i;
    cudaGetSymbolAddress((void**)&xnh, g_xn_hi);
    cudaGetSymbolAddress((void**)&xnl, g_xn_lo);
    cudaGetSymbolAddress((void**)&h1h, g_h1_hi);
    cudaGetSymbolAddress((void**)&h1l, g_h1_lo);
    cudaGetSymbolAddress((void**)&h2,  g_h2);
    cudaGetSymbolAddress((void**)&wt1h, g_wt1_hi);
    cudaGetSymbolAddress((void**)&wt1l, g_wt1_lo);
    cudaGetSymbolAddress((void**)&wt2h, g_wt2_hi);
    cudaGetSymbolAddress((void**)&wt2l, g_wt2_lo);
    cudaGetSymbolAddress((void**)&seq0i, g_seq0i);

    const int GEMM_SMEM = 2 * BUFF * 4;   // 147456 B
    cudaFuncSetAttribute(mma_gemm_kernel<CIN, true>,
                         cudaFuncAttributeMaxDynamicSharedMemorySize, GEMM_SMEM);
    cudaFuncSetAttribute(mma_gemm_kernel<HID, false>,
                         cudaFuncAttributeMaxDynamicSharedMemorySize, GEMM_SMEM);
    cudaFuncSetAttribute(head_kernel,
                         cudaFuncAttributeMaxDynamicSharedMemorySize, NRES * HID * 4);

    // 1. LayerNorm with tf32 split output
    ln_kernel<<<RTOT / 8, 256>>>(act, ln_g, ln_b, xnh, xnl);

    // 2. weight prep: coalesced transpose + tf32 split
    {
        dim3 blk(32, 8);
        dim3 g1(HID / 32, CIN / 32);
        tsplit_kernel<<<g1, blk>>>(w1, wt1h, wt1l, CIN, HID);
        dim3 g2(HID / 32, HID / 32);
        tsplit_kernel<<<g2, blk>>>(w2, wt2h, wt2l, HID, HID);
    }

    // 3. GEMM1: relu(xn @ w1 + b1) -> h1 (split)
    {
        dim3 grid(HID / 128, RTOT / 128);
        mma_gemm_kernel<CIN, true><<<grid, 256, GEMM_SMEM>>>(
            xnh, xnl, wt1h, wt1l, b1, h1h, h1l);
    }
    // 4. GEMM2: relu(h1 @ w2 + b2) -> h2
    {
        dim3 grid(HID / 128, RTOT / 128);
        mma_gemm_kernel<HID, false><<<grid, 256, GEMM_SMEM>>>(
            h1h, h1l, wt2h, wt2l, b2, h2, nullptr);
    }
    // 5. logits + argmax + select
    head_kernel<<<RTOT / 64, 256, NRES * HID * 4>>>(h2, w3, b3, fixed_mask, seq_t,
                                                    out_logits, out_seq0, seq0i);
    // 6. geometry
    geom_kernel<<<RTOT / 128, 128>>>(angles, rigids, residx, dframes, group_idx,
                                     a14_mask, a37_mask, lit, seq0i,
                                     out_pred, out_final, out_m14, out_m37);
}

// round 5
// speedup vs baseline: 1.0869x; 1.0089x over previous
#include <cuda_runtime.h>
#include <math.h>
#include <stdint.h>

// ---------------- problem constants ----------------
#define RTOT   32768          // B*N = 32*1024
#define CIN    384
#define HID    1024
#define NRES   20

// output layout (floats)
#define OFF_LOGITS 0
#define OFF_SEQ0   655360
#define OFF_PRED   688128
#define OFF_FINAL  2064384
#define OFF_M14    5701632
#define OFF_M37    6160384

// ---------------- scratch (no cudaMalloc allowed) ----------------
__device__ float g_xn_hi[(size_t)RTOT * CIN];
__device__ float g_xn_lo[(size_t)RTOT * CIN];
__device__ float g_h1_hi[(size_t)RTOT * HID];
__device__ float g_h1_lo[(size_t)RTOT * HID];
__device__ float g_h2[(size_t)RTOT * HID];
__device__ float g_wt1_hi[(size_t)HID * CIN];
__device__ float g_wt1_lo[(size_t)HID * CIN];
__device__ float g_wt2_hi[(size_t)HID * HID];
__device__ float g_wt2_lo[(size_t)HID * HID];
__device__ int   g_seq0i[RTOT];

__device__ __forceinline__ float tf32r(float v) {
    uint32_t u;
    asm("cvt.rna.tf32.f32 %0, %1;" : "=r"(u) : "f"(v));
    return __uint_as_float(u);
}

__device__ __forceinline__ void mma8(float c[4], const uint32_t a[4], const uint32_t b[2]) {
    asm volatile("mma.sync.aligned.m16n8k8.row.col.f32.tf32.tf32.f32 "
        "{%0,%1,%2,%3}, {%4,%5,%6,%7}, {%8,%9}, {%0,%1,%2,%3};"
        : "+f"(c[0]), "+f"(c[1]), "+f"(c[2]), "+f"(c[3])
        : "r"(a[0]), "r"(a[1]), "r"(a[2]), "r"(a[3]), "r"(b[0]), "r"(b[1]));
}

__device__ __forceinline__ void ldsm4(uint32_t r[4], uint32_t addr) {
    asm volatile("ldmatrix.sync.aligned.m8n8.x4.shared.b16 {%0,%1,%2,%3}, [%4];"
        : "=r"(r[0]), "=r"(r[1]), "=r"(r[2]), "=r"(r[3]) : "r"(addr));
}

__device__ __forceinline__ uint32_t smem_u32(const void* p) {
    uint32_t a;
    asm("{ .reg .u64 t; cvta.to.shared.u64 t, %1; cvt.u32.u64 %0, t; }" : "=r"(a) : "l"(p));
    return a;
}

#define CP16(dst, src) \
    asm volatile("cp.async.cg.shared.global [%0], [%1], 16;" :: "r"(dst), "l"(src))
#define CP_COMMIT() asm volatile("cp.async.commit_group;" ::: "memory")
#define CP_WAIT(n)  asm volatile("cp.async.wait_group %0;" :: "n"(n) : "memory")

// ---------------- LayerNorm -> split tf32 hi/lo ----------------
__global__ __launch_bounds__(256) void ln_kernel(
    const float* __restrict__ act,
    const float* __restrict__ gamma,
    const float* __restrict__ beta,
    float* __restrict__ out_hi,
    float* __restrict__ out_lo)
{
    int row  = blockIdx.x * 8 + (threadIdx.x >> 5);
    int lane = threadIdx.x & 31;
    const float* x = act + (size_t)row * CIN;

    float v[12];
    float sum = 0.f;
#pragma unroll
    for (int i = 0; i < 12; i++) { v[i] = x[lane + i * 32]; sum += v[i]; }
#pragma unroll
    for (int o = 16; o; o >>= 1) sum += __shfl_xor_sync(0xffffffffu, sum, o);
    float mu = sum * (1.f / CIN);

    float vs = 0.f;
#pragma unroll
    for (int i = 0; i < 12; i++) { float d = v[i] - mu; vs += d * d; }
#pragma unroll
    for (int o = 16; o; o >>= 1) vs += __shfl_xor_sync(0xffffffffu, vs, o);
    float rstd = rsqrtf(vs * (1.f / CIN) + 1e-5f);

    float* oh = out_hi + (size_t)row * CIN;
    float* ol = out_lo + (size_t)row * CIN;
#pragma unroll
    for (int i = 0; i < 12; i++) {
        int c = lane + i * 32;
        float y = (v[i] - mu) * rstd * gamma[c] + beta[c];
        float hi = tf32r(y);
        oh[c] = hi;
        ol[c] = tf32r(y - hi);
    }
}

// ---------------- coalesced transpose + tf32 split: W[K,N] -> T[N,K] hi/lo ----------------
__global__ __launch_bounds__(256) void tsplit_kernel(
    const float* __restrict__ W, float* __restrict__ Th, float* __restrict__ Tl,
    int Krows, int Ncols)
{
    __shared__ float t[32][33];
    const int tx = threadIdx.x;    // 0..31
    const int ty = threadIdx.y;    // 0..7
    const int n0 = blockIdx.x * 32;
    const int k0 = blockIdx.y * 32;

#pragma unroll
    for (int j = ty; j < 32; j += 8)
        t[j][tx] = W[(size_t)(k0 + j) * Ncols + n0 + tx];
    __syncthreads();

#pragma unroll
    for (int j = ty; j < 32; j += 8) {
        float v = t[tx][j];
        float hi = tf32r(v);
        size_t o = (size_t)(n0 + j) * Krows + k0 + tx;
        Th[o] = hi;
        Tl[o] = tf32r(v - hi);
    }
}

// ---------------- tf32x3 mma.sync GEMM, cp.async double-buffered + ldmatrix ----------------
// C[M,1024] = relu(A[M,K] @ Bt[1024,K]^T + bias)
// block 128x128x32, 8 warps (4M x 2N), warp tile 32x64
#define SROW 36                       // padded smem row stride (floats)
#define ARRB (128 * SROW * 4)         // bytes per array (128 rows)
#define BUFFB (4 * ARRB)              // bytes per stage (Ah, Al, Bh, Bl)

template<int K, bool SPLIT_OUT>
__global__ __launch_bounds__(256, 1) void mma_gemm_kernel(
    const float* __restrict__ Ah, const float* __restrict__ Al,
    const float* __restrict__ Bh, const float* __restrict__ Bl,
    const float* __restrict__ bias,
    float* __restrict__ Ch, float* __restrict__ Cl)
{
    constexpr int KT = K / 32;
    extern __shared__ float smem[];

    const int tid   = threadIdx.x;
    const int wid   = tid >> 5;
    const int lane  = tid & 31;
    const int warpM = wid & 3;
    const int warpN = wid >> 2;
    const int gr    = lane >> 2;
    const int tc    = lane & 3;

    const int m0 = blockIdx.y * 128;
    const int n0 = blockIdx.x * 128;

    // global load mapping: row = tid>>1 (0..127), kq = (tid&1)*16
    const int lrow = tid >> 1;
    const int kq   = (tid & 1) * 16;
    const float* gAh = Ah + (size_t)(m0 + lrow) * K + kq;
    const float* gAl = Al + (size_t)(m0 + lrow) * K + kq;
    const float* gBh = Bh + (size_t)(n0 + lrow) * K + kq;
    const float* gBl = Bl + (size_t)(n0 + lrow) * K + kq;

    const uint32_t sbase = smem_u32(smem);
    const uint32_t trd = (uint32_t)(lrow * SROW + kq) * 4;   // byte offset in an array

    // ldmatrix lane addressing (byte offsets within an array)
    // A x4 tile (ms): rows warpM*32 + ms*16 + (lane&15), col (lane>>4)*4 + ks*8
    const uint32_t aLane = (uint32_t)((warpM * 32 + (lane & 15)) * SROW + (lane >> 4) * 4) * 4;
    // B x4 tile (pair p): rows warpN*64 + p*16 + ((lane>>4)&1)*8 + (lane&7),
    //                     col ((lane>>3)&1)*4 + ks*8
    const uint32_t bLane = (uint32_t)((warpN * 64 + ((lane >> 4) & 1) * 8 + (lane & 7)) * SROW
                                      + ((lane >> 3) & 1) * 4) * 4;

    float acc[2][8][4];
#pragma unroll
    for (int i = 0; i < 2; i++)
#pragma unroll
        for (int j = 0; j < 8; j++)
#pragma unroll
            for (int q = 0; q < 4; q++) acc[i][j][q] = 0.f;

    // issue stage-0 loads
    {
        const uint32_t db = sbase + trd;
#pragma unroll
        for (int i = 0; i < 4; i++) CP16(db + 0 * ARRB + i * 16, gAh + i * 4);
#pragma unroll
        for (int i = 0; i < 4; i++) CP16(db + 1 * ARRB + i * 16, gAl + i * 4);
#pragma unroll
        for (int i = 0; i < 4; i++) CP16(db + 2 * ARRB + i * 16, gBh + i * 4);
#pragma unroll
        for (int i = 0; i < 4; i++) CP16(db + 3 * ARRB + i * 16, gBl + i * 4);
        CP_COMMIT();
    }

    for (int kt = 0; kt < KT; ++kt) {
        const int buf = kt & 1;
        // prefetch next tile into the other stage
        if (kt + 1 < KT) {
            const int kg = (kt + 1) * 32;
            const uint32_t db = sbase + (uint32_t)((kt + 1) & 1) * BUFFB + trd;
#pragma unroll
            for (int i = 0; i < 4; i++) CP16(db + 0 * ARRB + i * 16, gAh + kg + i * 4);
#pragma unroll
            for (int i = 0; i < 4; i++) CP16(db + 1 * ARRB + i * 16, gAl + kg + i * 4);
#pragma unroll
            for (int i = 0; i < 4; i++) CP16(db + 2 * ARRB + i * 16, gBh + kg + i * 4);
#pragma unroll
            for (int i = 0; i < 4; i++) CP16(db + 3 * ARRB + i * 16, gBl + kg + i * 4);
            CP_COMMIT();
            CP_WAIT(1);
        } else {
            CP_WAIT(0);
        }
        __syncthreads();

        const uint32_t stage = sbase + (uint32_t)buf * BUFFB;
        const uint32_t aHi = stage + 0 * ARRB + aLane;
        const uint32_t aLo = stage + 1 * ARRB + aLane;
        const uint32_t bHi = stage + 2 * ARRB + bLane;
        const uint32_t bLo = stage + 3 * ARRB + bLane;

#pragma unroll
        for (int ks = 0; ks < 4; ks++) {
            const uint32_t ko = ks * 32;   // bytes: 8 floats
            uint32_t ah[2][4], al[2][4], bh[4][4], bl[4][4];
#pragma unroll
            for (int ms = 0; ms < 2; ms++) {
                ldsm4(ah[ms], aHi + ms * (16 * SROW * 4) + ko);
                ldsm4(al[ms], aLo + ms * (16 * SROW * 4) + ko);
            }
#pragma unroll
            for (int p = 0; p < 4; p++) {
                ldsm4(bh[p], bHi + p * (16 * SROW * 4) + ko);
                ldsm4(bl[p], bLo + p * (16 * SROW * 4) + ko);
            }
            // pass 1: hi*hi
#pragma unroll
            for (int ms = 0; ms < 2; ms++)
#pragma unroll
                for (int p = 0; p < 4; p++) {
                    mma8(acc[ms][2 * p],     ah[ms], &bh[p][0]);
                    mma8(acc[ms][2 * p + 1], ah[ms], &bh[p][2]);
                }
            // pass 2: hi*lo
#pragma unroll
            for (int ms = 0; ms < 2; ms++)
#pragma unroll
                for (int p = 0; p < 4; p++) {
                    mma8(acc[ms][2 * p],     ah[ms], &bl[p][0]);
                    mma8(acc[ms][2 * p + 1], ah[ms], &bl[p][2]);
                }
            // pass 3: lo*hi
#pragma unroll
            for (int ms = 0; ms < 2; ms++)
#pragma unroll
                for (int p = 0; p < 4; p++) {
                    mma8(acc[ms][2 * p],     al[ms], &bh[p][0]);
                    mma8(acc[ms][2 * p + 1], al[ms], &bh[p][2]);
                }
        }
        __syncthreads();
    }

    // epilogue: bias + relu (+ optional tf32 split), direct stores
    const int mwb = m0 + warpM * 32;
    const int nwb = n0 + warpN * 64;
#pragma unroll
    for (int ms = 0; ms < 2; ms++) {
        int r0 = mwb + ms * 16 + gr;
        int r1 = r0 + 8;
#pragma unroll
        for (int ns = 0; ns < 8; ns++) {
            int c = nwb + ns * 8 + 2 * tc;
            float bz0 = bias[c], bz1 = bias[c + 1];
            float v0 = fmaxf(acc[ms][ns][0] + bz0, 0.f);
            float v1 = fmaxf(acc[ms][ns][1] + bz1, 0.f);
            float v2 = fmaxf(acc[ms][ns][2] + bz0, 0.f);
            float v3 = fmaxf(acc[ms][ns][3] + bz1, 0.f);
            if (SPLIT_OUT) {
                float h0 = tf32r(v0), h1 = tf32r(v1), h2 = tf32r(v2), h3 = tf32r(v3);
                *(float2*)(Ch + (size_t)r0 * HID + c) = make_float2(h0, h1);
                *(float2*)(Ch + (size_t)r1 * HID + c) = make_float2(h2, h3);
                *(float2*)(Cl + (size_t)r0 * HID + c) =
                    make_float2(tf32r(v0 - h0), tf32r(v1 - h1));
                *(float2*)(Cl + (size_t)r1 * HID + c) =
                    make_float2(tf32r(v2 - h2), tf32r(v3 - h3));
            } else {
                *(float2*)(Ch + (size_t)r0 * HID + c) = make_float2(v0, v1);
                *(float2*)(Ch + (size_t)r1 * HID + c) = make_float2(v2, v3);
            }
        }
    }
}

// ---------------- head: logits = h2 @ w3 + b3, argmax, select ----------------
__global__ __launch_bounds__(256) void head_kernel(
    const float* __restrict__ h2,
    const float* __restrict__ w3,
    const float* __restrict__ b3,
    const int* __restrict__ fixed_mask,
    const int* __restrict__ seq_t,
    float* __restrict__ out_logits,
    float* __restrict__ out_seq0f,
    int* __restrict__ seq0i)
{
    extern __shared__ float w3s[];   // [20][1024]
    const int tid = threadIdx.x;
    const int wid = tid >> 5;
    const int lane = tid & 31;

    for (int i = tid; i < NRES * HID; i += 256) {
        int c = i >> 10;
        int k = i & 1023;
        w3s[i] = w3[k * NRES + c];
    }
    __syncthreads();

    const int rbase = blockIdx.x * 64 + wid * 8;
#pragma unroll
    for (int j = 0; j < 8; j += 2) {
        int ra = rbase + j, rb = ra + 1;
        const float* ha = h2 + (size_t)ra * HID;
        const float* hb = h2 + (size_t)rb * HID;
        float acc0[NRES], acc1[NRES];
#pragma unroll
        for (int c = 0; c < NRES; c++) { acc0[c] = 0.f; acc1[c] = 0.f; }
        for (int it = 0; it < 32; it++) {
            int k = it * 32 + lane;
            float va = ha[k];
            float vb = hb[k];
#pragma unroll
            for (int c = 0; c < NRES; c++) {
                float w = w3s[c * HID + k];
                acc0[c] = fmaf(va, w, acc0[c]);
                acc1[c] = fmaf(vb, w, acc1[c]);
            }
        }
#pragma unroll
        for (int c = 0; c < NRES; c++) {
#pragma unroll
            for (int o = 16; o; o >>= 1) {
                acc0[c] += __shfl_xor_sync(0xffffffffu, acc0[c], o);
                acc1[c] += __shfl_xor_sync(0xffffffffu, acc1[c], o);
            }
        }
        if (lane == 0) {
            int best0 = 0, best1 = 0;
            float bv0 = -INFINITY, bv1 = -INFINITY;
            float* l0 = out_logits + (size_t)ra * NRES;
            float* l1 = out_logits + (size_t)rb * NRES;
#pragma unroll
            for (int c = 0; c < NRES; c++) {
                float v0 = acc0[c] + b3[c];
                float v1 = acc1[c] + b3[c];
                l0[c] = v0; l1[c] = v1;
                if (v0 > bv0) { bv0 = v0; best0 = c; }
                if (v1 > bv1) { bv1 = v1; best1 = c; }
            }
            int s0 = fixed_mask[ra] ? seq_t[ra] : best0;
            int s1 = fixed_mask[rb] ? seq_t[rb] : best1;
            seq0i[ra] = s0; seq0i[rb] = s1;
            out_seq0f[ra] = (float)s0; out_seq0f[rb] = (float)s1;
        }
    }
}

// ---------------- geometry: one thread per residue ----------------
__global__ __launch_bounds__(128) void geom_kernel(
    const float* __restrict__ angles,
    const float* __restrict__ rigids,
    const int* __restrict__ residx,
    const float* __restrict__ default_frames,
    const int* __restrict__ group_idx,
    const float* __restrict__ atom14_mask,
    const float* __restrict__ atom37_mask,
    const float* __restrict__ lit_positions,
    const int* __restrict__ seq0i,
    float* __restrict__ out_pred,
    float* __restrict__ out_final,
    float* __restrict__ out_m14,
    float* __restrict__ out_m37)
{
    int r = blockIdx.x * blockDim.x + threadIdx.x;
    if (r >= RTOT) return;

    float q0 = rigids[r * 7 + 0], q1 = rigids[r * 7 + 1];
    float q2 = rigids[r * 7 + 2], q3 = rigids[r * 7 + 3];
    float tb0 = rigids[r * 7 + 4], tb1 = rigids[r * 7 + 5], tb2 = rigids[r * 7 + 6];
    float inv = rsqrtf(q0 * q0 + q1 * q1 + q2 * q2 + q3 * q3 + 1e-8f);
    float w = q0 * inv, x = q1 * inv, y = q2 * inv, z = q3 * inv;
    float rb[9];
    rb[0] = 1.f - 2.f * (y * y + z * z); rb[1] = 2.f * (x * y - w * z); rb[2] = 2.f * (x * z + w * y);
    rb[3] = 2.f * (x * y + w * z); rb[4] = 1.f - 2.f * (x * x + z * z); rb[5] = 2.f * (y * z - w * x);
    rb[6] = 2.f * (x * z - w * y); rb[7] = 2.f * (y * z + w * x); rb[8] = 1.f - 2.f * (x * x + y * y);

    int s = seq0i[r];

    float G[8][12];
    float chain_r[9], chain_t[3];

    for (int g = 0; g < 8; g++) {
        const float* df = default_frames + ((size_t)s * 8 + g) * 16;
        float dr[9], dt[3];
#pragma unroll
        for (int i = 0; i < 3; i++) {
            dr[i * 3 + 0] = df[i * 4 + 0];
            dr[i * 3 + 1] = df[i * 4 + 1];
            dr[i * 3 + 2] = df[i * 4 + 2];
            dt[i] = df[i * 4 + 3];
        }
        float sn, cs;
        if (g == 0) { sn = 0.f; cs = 1.f; }
        else { sn = angles[r * 14 + (g - 1) * 2 + 0]; cs = angles[r * 14 + (g - 1) * 2 + 1]; }

        float fr[9], ft[3];
#pragma unroll
        for (int i = 0; i < 3; i++) {
            fr[i * 3 + 0] = dr[i * 3 + 0];
            fr[i * 3 + 1] = dr[i * 3 + 1] * cs + dr[i * 3 + 2] * sn;
            fr[i * 3 + 2] = -dr[i * 3 + 1] * sn + dr[i * 3 + 2] * cs;
            ft[i] = dt[i];
        }

        float fo[9], to[3];
        if (g <= 4) {
#pragma unroll
            for (int i = 0; i < 9; i++) fo[i] = fr[i];
#pragma unroll
            for (int i = 0; i < 3; i++) to[i] = ft[i];
            if (g == 4) {
#pragma unroll
                for (int i = 0; i < 9; i++) chain_r[i] = fr[i];
#pragma unroll
                for (int i = 0; i < 3; i++) chain_t[i] = ft[i];
            }
        } else {
            float nr[9], nt[3];
#pragma unroll
            for (int i = 0; i < 3; i++) {
#pragma unroll
                for (int j = 0; j < 3; j++) {
                    nr[i * 3 + j] = chain_r[i * 3 + 0] * fr[0 * 3 + j]
                                  + chain_r[i * 3 + 1] * fr[1 * 3 + j]
                                  + chain_r[i * 3 + 2] * fr[2 * 3 + j];
                }
                nt[i] = chain_r[i * 3 + 0] * ft[0] + chain_r[i * 3 + 1] * ft[1]
                      + chain_r[i * 3 + 2] * ft[2] + chain_t[i];
            }
#pragma unroll
            for (int i = 0; i < 9; i++) { chain_r[i] = nr[i]; fo[i] = nr[i]; }
#pragma unroll
            for (int i = 0; i < 3; i++) { chain_t[i] = nt[i]; to[i] = nt[i]; }
        }

#pragma unroll
        for (int i = 0; i < 3; i++) {
#pragma unroll
            for (int j = 0; j < 3; j++) {
                G[g][i * 3 + j] = rb[i * 3 + 0] * fo[0 * 3 + j]
                                + rb[i * 3 + 1] * fo[1 * 3 + j]
                                + rb[i * 3 + 2] * fo[2 * 3 + j];
            }
        }
        G[g][9]  = rb[0] * to[0] + rb[1] * to[1] + rb[2] * to[2] + tb0;
        G[g][10] = rb[3] * to[0] + rb[4] * to[1] + rb[5] * to[2] + tb1;
        G[g][11] = rb[6] * to[0] + rb[7] * to[1] + rb[8] * to[2] + tb2;
    }

    float pv[14][3];
#pragma unroll
    for (int a = 0; a < 14; a++) {
        int gi = group_idx[s * 14 + a];
        const float* Gp = G[gi];
        float lx = lit_positions[((size_t)s * 14 + a) * 3 + 0];
        float ly = lit_positions[((size_t)s * 14 + a) * 3 + 1];
        float lz = lit_positions[((size_t)s * 14 + a) * 3 + 2];
        float m = atom14_mask[s * 14 + a];
        float px = (Gp[0] * lx + Gp[1] * ly + Gp[2] * lz + Gp[9])  * m;
        float py = (Gp[3] * lx + Gp[4] * ly + Gp[5] * lz + Gp[10]) * m;
        float pz = (Gp[6] * lx + Gp[7] * ly + Gp[8] * lz + Gp[11]) * m;
        pv[a][0] = px; pv[a][1] = py; pv[a][2] = pz;
        size_t po = ((size_t)r * 14 + a) * 3;
        out_pred[po + 0] = px; out_pred[po + 1] = py; out_pred[po + 2] = pz;
        out_m14[(size_t)r * 14 + a] = m;
    }

#pragma unroll
    for (int j = 0; j < 37; j++) {
        int a = residx[(size_t)r * 37 + j];
        size_t fo_ = ((size_t)r * 37 + j) * 3;
        out_final[fo_ + 0] = pv[a][0];
        out_final[fo_ + 1] = pv[a][1];
        out_final[fo_ + 2] = pv[a][2];
        out_m37[(size_t)r * 37 + j] = atom37_mask[s * 37 + j];
    }
}

// ---------------- launcher ----------------
extern "C" void kernel_launch(void* const* d_in, const int* in_sizes, int n_in,
                              void* d_out, int out_size)
{
    const float* act        = (const float*)d_in[0];
    const float* angles     = (const float*)d_in[1];
    const float* rigids     = (const float*)d_in[2];
    const int*   fixed_mask = (const int*)d_in[3];
    const int*   seq_t      = (const int*)d_in[4];
    const int*   residx     = (const int*)d_in[5];
    const float* ln_g       = (const float*)d_in[6];
    const float* ln_b       = (const float*)d_in[7];
    const float* w1         = (const float*)d_in[8];
    const float* b1         = (const float*)d_in[9];
    const float* w2         = (const float*)d_in[10];
    const float* b2         = (const float*)d_in[11];
    const float* w3         = (const float*)d_in[12];
    const float* b3         = (const float*)d_in[13];
    const float* dframes    = (const float*)d_in[14];
    const int*   group_idx  = (const int*)d_in[15];
    const float* a14_mask   = (const float*)d_in[16];
    const float* a37_mask   = (const float*)d_in[17];
    const float* lit        = (const float*)d_in[18];

    float* out = (float*)d_out;
    float* out_logits = out + OFF_LOGITS;
    float* out_seq0   = out + OFF_SEQ0;
    float* out_pred   = out + OFF_PRED;
    float* out_final  = out + OFF_FINAL;
    float* out_m14    = out + OFF_M14;
    float* out_m37    = out + OFF_M37;

    float *xnh, *xnl, *h1h, *h1l, *h2, *wt1h, *wt1l, *wt2h, *wt2l;
    int* seq0i;
    cudaGetSymbolAddress((void**)&xnh, g_xn_hi);
    cudaGetSymbolAddress((void**)&xnl, g_xn_lo);
    cudaGetSymbolAddress((void**)&h1h, g_h1_hi);
    cudaGetSymbolAddress((void**)&h1l, g_h1_lo);
    cudaGetSymbolAddress((void**)&h2,  g_h2);
    cudaGetSymbolAddress((void**)&wt1h, g_wt1_hi);
    cudaGetSymbolAddress((void**)&wt1l, g_wt1_lo);
    cudaGetSymbolAddress((void**)&wt2h, g_wt2_hi);
    cudaGetSymbolAddress((void**)&wt2l, g_wt2_lo);
    cudaGetSymbolAddress((void**)&seq0i, g_seq0i);

    const int GEMM_SMEM = 2 * BUFFB;   // 147456 B
    cudaFuncSetAttribute(mma_gemm_kernel<CIN, true>,
                         cudaFuncAttributeMaxDynamicSharedMemorySize, GEMM_SMEM);
    cudaFuncSetAttribute(mma_gemm_kernel<HID, false>,
                         cudaFuncAttributeMaxDynamicSharedMemorySize, GEMM_SMEM);
    cudaFuncSetAttribute(head_kernel,
                         cudaFuncAttributeMaxDynamicSharedMemorySize, NRES * HID * 4);

    // 1. LayerNorm with tf32 split output
    ln_kernel<<<RTOT / 8, 256>>>(act, ln_g, ln_b, xnh, xnl);

    // 2. weight prep: coalesced transpose + tf32 split
    {
        dim3 blk(32, 8);
        dim3 g1(HID / 32, CIN / 32);
        tsplit_kernel<<<g1, blk>>>(w1, wt1h, wt1l, CIN, HID);
        dim3 g2(HID / 32, HID / 32);
        tsplit_kernel<<<g2, blk>>>(w2, wt2h, wt2l, HID, HID);
    }

    // 3. GEMM1: relu(xn @ w1 + b1) -> h1 (split)
    {
        dim3 grid(HID / 128, RTOT / 128);
        mma_gemm_kernel<CIN, true><<<grid, 256, GEMM_SMEM>>>(
            xnh, xnl, wt1h, wt1l, b1, h1h, h1l);
    }
    // 4. GEMM2: relu(h1 @ w2 + b2) -> h2
    {
        dim3 grid(HID / 128, RTOT / 128);
        mma_gemm_kernel<HID, false><<<grid, 256, GEMM_SMEM>>>(
            h1h, h1l, wt2h, wt2l, b2, h2, nullptr);
    }
    // 5. logits + argmax + select
    head_kernel<<<RTOT / 64, 256, NRES * HID * 4>>>(h2, w3, b3, fixed_mask, seq_t,
                                                    out_logits, out_seq0, seq0i);
    // 6. geometry
    geom_kernel<<<RTOT / 128, 128>>>(angles, rigids, residx, dframes, group_idx,
                                     a14_mask, a37_mask, lit, seq0i,
                                     out_pred, out_final, out_m14, out_m37);
}

// round 6
// speedup vs baseline: 1.3237x; 1.2178x over previous
#include <cuda_runtime.h>
#include <math.h>
#include <stdint.h>

// ---------------- problem constants ----------------
#define RTOT   32768          // B*N = 32*1024
#define CIN    384
#define HID    1024
#define NRES   20

// output layout (floats)
#define OFF_LOGITS 0
#define OFF_SEQ0   655360
#define OFF_PRED   688128
#define OFF_FINAL  2064384
#define OFF_M14    5701632
#define OFF_M37    6160384

// ---------------- scratch (no cudaMalloc allowed) ----------------
__device__ float g_xn_hi[(size_t)RTOT * CIN];
__device__ float g_xn_lo[(size_t)RTOT * CIN];
__device__ float g_h1_hi[(size_t)RTOT * HID];
__device__ float g_h1_lo[(size_t)RTOT * HID];
__device__ float g_h2[(size_t)RTOT * HID];
__device__ float g_wt1_hi[(size_t)HID * CIN];
__device__ float g_wt1_lo[(size_t)HID * CIN];
__device__ float g_wt2_hi[(size_t)HID * HID];
__device__ float g_wt2_lo[(size_t)HID * HID];
__device__ int   g_seq0i[RTOT];

__device__ __forceinline__ float tf32r(float v) {
    uint32_t u;
    asm("cvt.rna.tf32.f32 %0, %1;" : "=r"(u) : "f"(v));
    return __uint_as_float(u);
}

__device__ __forceinline__ void mma8(float c[4], const uint32_t a[4], const uint32_t b[2]) {
    asm volatile("mma.sync.aligned.m16n8k8.row.col.f32.tf32.tf32.f32 "
        "{%0,%1,%2,%3}, {%4,%5,%6,%7}, {%8,%9}, {%0,%1,%2,%3};"
        : "+f"(c[0]), "+f"(c[1]), "+f"(c[2]), "+f"(c[3])
        : "r"(a[0]), "r"(a[1]), "r"(a[2]), "r"(a[3]), "r"(b[0]), "r"(b[1]));
}

__device__ __forceinline__ void ldsm4(uint32_t r[4], uint32_t addr) {
    asm volatile("ldmatrix.sync.aligned.m8n8.x4.shared.b16 {%0,%1,%2,%3}, [%4];"
        : "=r"(r[0]), "=r"(r[1]), "=r"(r[2]), "=r"(r[3]) : "r"(addr));
}

__device__ __forceinline__ uint32_t smem_u32(const void* p) {
    uint32_t a;
    asm("{ .reg .u64 t; cvta.to.shared.u64 t, %1; cvt.u32.u64 %0, t; }" : "=r"(a) : "l"(p));
    return a;
}

#define CP16(dst, src) \
    asm volatile("cp.async.cg.shared.global [%0], [%1], 16;" :: "r"(dst), "l"(src))
#define CP_COMMIT() asm volatile("cp.async.commit_group;" ::: "memory")
#define CP_WAIT(n)  asm volatile("cp.async.wait_group %0;" :: "n"(n) : "memory")

// ---------------- LayerNorm -> split tf32 hi/lo ----------------
__global__ __launch_bounds__(256) void ln_kernel(
    const float* __restrict__ act,
    const float* __restrict__ gamma,
    const float* __restrict__ beta,
    float* __restrict__ out_hi,
    float* __restrict__ out_lo)
{
    int row  = blockIdx.x * 8 + (threadIdx.x >> 5);
    int lane = threadIdx.x & 31;
    const float* x = act + (size_t)row * CIN;

    float v[12];
    float sum = 0.f;
#pragma unroll
    for (int i = 0; i < 12; i++) { v[i] = x[lane + i * 32]; sum += v[i]; }
#pragma unroll
    for (int o = 16; o; o >>= 1) sum += __shfl_xor_sync(0xffffffffu, sum, o);
    float mu = sum * (1.f / CIN);

    float vs = 0.f;
#pragma unroll
    for (int i = 0; i < 12; i++) { float d = v[i] - mu; vs += d * d; }
#pragma unroll
    for (int o = 16; o; o >>= 1) vs += __shfl_xor_sync(0xffffffffu, vs, o);
    float rstd = rsqrtf(vs * (1.f / CIN) + 1e-5f);

    float* oh = out_hi + (size_t)row * CIN;
    float* ol = out_lo + (size_t)row * CIN;
#pragma unroll
    for (int i = 0; i < 12; i++) {
        int c = lane + i * 32;
        float y = (v[i] - mu) * rstd * gamma[c] + beta[c];
        float hi = tf32r(y);
        oh[c] = hi;
        ol[c] = tf32r(y - hi);
    }
}

// ---------------- coalesced transpose + tf32 split: W[K,N] -> T[N,K] hi/lo ----------------
__global__ __launch_bounds__(256) void tsplit_kernel(
    const float* __restrict__ W, float* __restrict__ Th, float* __restrict__ Tl,
    int Krows, int Ncols)
{
    __shared__ float t[32][33];
    const int tx = threadIdx.x;    // 0..31
    const int ty = threadIdx.y;    // 0..7
    const int n0 = blockIdx.x * 32;
    const int k0 = blockIdx.y * 32;

#pragma unroll
    for (int j = ty; j < 32; j += 8)
        t[j][tx] = W[(size_t)(k0 + j) * Ncols + n0 + tx];
    __syncthreads();

#pragma unroll
    for (int j = ty; j < 32; j += 8) {
        float v = t[tx][j];
        float hi = tf32r(v);
        size_t o = (size_t)(n0 + j) * Krows + k0 + tx;
        Th[o] = hi;
        Tl[o] = tf32r(v - hi);
    }
}

// ---------------- tf32x3 mma.sync GEMM, cp.async double-buffered + ldmatrix ----------------
// C[M,1024] = relu(A[M,K] @ Bt[1024,K]^T + bias)
// block 128x128x16, 8 warps (4M x 2N), warp tile 32x64, 2 CTAs/SM
#define SROW 20                       // padded smem row stride (floats), k-tile 16
#define ARRB (128 * SROW * 4)         // bytes per array (128 rows) = 10240
#define BUFFB (4 * ARRB)              // bytes per stage (Ah, Al, Bh, Bl) = 40960

template<int K, bool SPLIT_OUT>
__global__ __launch_bounds__(256, 2) void mma_gemm_kernel(
    const float* __restrict__ Ah, const float* __restrict__ Al,
    const float* __restrict__ Bh, const float* __restrict__ Bl,
    const float* __restrict__ bias,
    float* __restrict__ Ch, float* __restrict__ Cl)
{
    constexpr int KT = K / 16;
    extern __shared__ float smem[];

    const int tid   = threadIdx.x;
    const int wid   = tid >> 5;
    const int lane  = tid & 31;
    const int warpM = wid & 3;
    const int warpN = wid >> 2;
    const int gr    = lane >> 2;
    const int tc    = lane & 3;

    const int m0 = blockIdx.y * 128;
    const int n0 = blockIdx.x * 128;

    // global load mapping: row = tid>>1 (0..127), kq = (tid&1)*8
    const int lrow = tid >> 1;
    const int kq   = (tid & 1) * 8;
    const float* gAh = Ah + (size_t)(m0 + lrow) * K + kq;
    const float* gAl = Al + (size_t)(m0 + lrow) * K + kq;
    const float* gBh = Bh + (size_t)(n0 + lrow) * K + kq;
    const float* gBl = Bl + (size_t)(n0 + lrow) * K + kq;

    const uint32_t sbase = smem_u32(smem);
    const uint32_t trd = (uint32_t)(lrow * SROW + kq) * 4;   // byte offset in an array

    // ldmatrix lane addressing (byte offsets within an array)
    const uint32_t aLane = (uint32_t)((warpM * 32 + (lane & 15)) * SROW + (lane >> 4) * 4) * 4;
    const uint32_t bLane = (uint32_t)((warpN * 64 + ((lane >> 4) & 1) * 8 + (lane & 7)) * SROW
                                      + ((lane >> 3) & 1) * 4) * 4;

    float acc[2][8][4];
#pragma unroll
    for (int i = 0; i < 2; i++)
#pragma unroll
        for (int j = 0; j < 8; j++)
#pragma unroll
            for (int q = 0; q < 4; q++) acc[i][j][q] = 0.f;

    // issue stage-0 loads (each thread: 2 CP16 per array)
    {
        const uint32_t db = sbase + trd;
        CP16(db + 0 * ARRB, gAh);
        CP16(db + 0 * ARRB + 16, gAh + 4);
        CP16(db + 1 * ARRB, gAl);
        CP16(db + 1 * ARRB + 16, gAl + 4);
        CP16(db + 2 * ARRB, gBh);
        CP16(db + 2 * ARRB + 16, gBh + 4);
        CP16(db + 3 * ARRB, gBl);
        CP16(db + 3 * ARRB + 16, gBl + 4);
        CP_COMMIT();
    }

    for (int kt = 0; kt < KT; ++kt) {
        const int buf = kt & 1;
        if (kt + 1 < KT) {
            const int kg = (kt + 1) * 16;
            const uint32_t db = sbase + (uint32_t)((kt + 1) & 1) * BUFFB + trd;
            CP16(db + 0 * ARRB, gAh + kg);
            CP16(db + 0 * ARRB + 16, gAh + kg + 4);
            CP16(db + 1 * ARRB, gAl + kg);
            CP16(db + 1 * ARRB + 16, gAl + kg + 4);
            CP16(db + 2 * ARRB, gBh + kg);
            CP16(db + 2 * ARRB + 16, gBh + kg + 4);
            CP16(db + 3 * ARRB, gBl + kg);
            CP16(db + 3 * ARRB + 16, gBl + kg + 4);
            CP_COMMIT();
            CP_WAIT(1);
        } else {
            CP_WAIT(0);
        }
        __syncthreads();

        const uint32_t stage = sbase + (uint32_t)buf * BUFFB;
        const uint32_t aHi = stage + 0 * ARRB + aLane;
        const uint32_t aLo = stage + 1 * ARRB + aLane;
        const uint32_t bHi = stage + 2 * ARRB + bLane;
        const uint32_t bLo = stage + 3 * ARRB + bLane;

#pragma unroll
        for (int ks = 0; ks < 2; ks++) {
            const uint32_t ko = ks * 32;   // 8 floats
            uint32_t ah[2][4], al[2][4], bh[4][4], bl[4][4];
#pragma unroll
            for (int ms = 0; ms < 2; ms++) {
                ldsm4(ah[ms], aHi + ms * (16 * SROW * 4) + ko);
                ldsm4(al[ms], aLo + ms * (16 * SROW * 4) + ko);
            }
#pragma unroll
            for (int p = 0; p < 4; p++) {
                ldsm4(bh[p], bHi + p * (16 * SROW * 4) + ko);
                ldsm4(bl[p], bLo + p * (16 * SROW * 4) + ko);
            }
#pragma unroll
            for (int ms = 0; ms < 2; ms++)
#pragma unroll
                for (int p = 0; p < 4; p++) {
                    mma8(acc[ms][2 * p],     ah[ms], &bh[p][0]);
                    mma8(acc[ms][2 * p + 1], ah[ms], &bh[p][2]);
                }
#pragma unroll
            for (int ms = 0; ms < 2; ms++)
#pragma unroll
                for (int p = 0; p < 4; p++) {
                    mma8(acc[ms][2 * p],     ah[ms], &bl[p][0]);
                    mma8(acc[ms][2 * p + 1], ah[ms], &bl[p][2]);
                }
#pragma unroll
            for (int ms = 0; ms < 2; ms++)
#pragma unroll
                for (int p = 0; p < 4; p++) {
                    mma8(acc[ms][2 * p],     al[ms], &bh[p][0]);
                    mma8(acc[ms][2 * p + 1], al[ms], &bh[p][2]);
                }
        }
        __syncthreads();
    }

    // epilogue: bias + relu (+ optional tf32 split), direct stores
    const int mwb = m0 + warpM * 32;
    const int nwb = n0 + warpN * 64;
#pragma unroll
    for (int ms = 0; ms < 2; ms++) {
        int r0 = mwb + ms * 16 + gr;
        int r1 = r0 + 8;
#pragma unroll
        for (int ns = 0; ns < 8; ns++) {
            int c = nwb + ns * 8 + 2 * tc;
            float bz0 = bias[c], bz1 = bias[c + 1];
            float v0 = fmaxf(acc[ms][ns][0] + bz0, 0.f);
            float v1 = fmaxf(acc[ms][ns][1] + bz1, 0.f);
            float v2 = fmaxf(acc[ms][ns][2] + bz0, 0.f);
            float v3 = fmaxf(acc[ms][ns][3] + bz1, 0.f);
            if (SPLIT_OUT) {
                float h0 = tf32r(v0), h1 = tf32r(v1), h2 = tf32r(v2), h3 = tf32r(v3);
                *(float2*)(Ch + (size_t)r0 * HID + c) = make_float2(h0, h1);
                *(float2*)(Ch + (size_t)r1 * HID + c) = make_float2(h2, h3);
                *(float2*)(Cl + (size_t)r0 * HID + c) =
                    make_float2(tf32r(v0 - h0), tf32r(v1 - h1));
                *(float2*)(Cl + (size_t)r1 * HID + c) =
                    make_float2(tf32r(v2 - h2), tf32r(v3 - h3));
            } else {
                *(float2*)(Ch + (size_t)r0 * HID + c) = make_float2(v0, v1);
                *(float2*)(Ch + (size_t)r1 * HID + c) = make_float2(v2, v3);
            }
        }
    }
}

// ---------------- head: logits = h2 @ w3 + b3, argmax, select ----------------
__global__ __launch_bounds__(256) void head_kernel(
    const float* __restrict__ h2,
    const float* __restrict__ w3,
    const float* __restrict__ b3,
    const int* __restrict__ fixed_mask,
    const int* __restrict__ seq_t,
    float* __restrict__ out_logits,
    float* __restrict__ out_seq0f,
    int* __restrict__ seq0i)
{
    extern __shared__ float w3s[];   // [20][1024]
    const int tid = threadIdx.x;
    const int wid = tid >> 5;
    const int lane = tid & 31;

    for (int i = tid; i < NRES * HID; i += 256) {
        int c = i >> 10;
        int k = i & 1023;
        w3s[i] = w3[k * NRES + c];
    }
    __syncthreads();

    const int rbase = blockIdx.x * 64 + wid * 8;
#pragma unroll
    for (int j = 0; j < 8; j += 2) {
        int ra = rbase + j, rb = ra + 1;
        const float* ha = h2 + (size_t)ra * HID;
        const float* hb = h2 + (size_t)rb * HID;
        float acc0[NRES], acc1[NRES];
#pragma unroll
        for (int c = 0; c < NRES; c++) { acc0[c] = 0.f; acc1[c] = 0.f; }
        for (int it = 0; it < 32; it++) {
            int k = it * 32 + lane;
            float va = ha[k];
            float vb = hb[k];
#pragma unroll
            for (int c = 0; c < NRES; c++) {
                float w = w3s[c * HID + k];
                acc0[c] = fmaf(va, w, acc0[c]);
                acc1[c] = fmaf(vb, w, acc1[c]);
            }
        }
#pragma unroll
        for (int c = 0; c < NRES; c++) {
#pragma unroll
            for (int o = 16; o; o >>= 1) {
                acc0[c] += __shfl_xor_sync(0xffffffffu, acc0[c], o);
                acc1[c] += __shfl_xor_sync(0xffffffffu, acc1[c], o);
            }
        }
        if (lane == 0) {
            int best0 = 0, best1 = 0;
            float bv0 = -INFINITY, bv1 = -INFINITY;
            float* l0 = out_logits + (size_t)ra * NRES;
            float* l1 = out_logits + (size_t)rb * NRES;
#pragma unroll
            for (int c = 0; c < NRES; c++) {
                float v0 = acc0[c] + b3[c];
                float v1 = acc1[c] + b3[c];
                l0[c] = v0; l1[c] = v1;
                if (v0 > bv0) { bv0 = v0; best0 = c; }
                if (v1 > bv1) { bv1 = v1; best1 = c; }
            }
            int s0 = fixed_mask[ra] ? seq_t[ra] : best0;
            int s1 = fixed_mask[rb] ? seq_t[rb] : best1;
            seq0i[ra] = s0; seq0i[rb] = s1;
            out_seq0f[ra] = (float)s0; out_seq0f[rb] = (float)s1;
        }
    }
}

// ---------------- geometry: one thread per residue ----------------
__global__ __launch_bounds__(128) void geom_kernel(
    const float* __restrict__ angles,
    const float* __restrict__ rigids,
    const int* __restrict__ residx,
    const float* __restrict__ default_frames,
    const int* __restrict__ group_idx,
    const float* __restrict__ atom14_mask,
    const float* __restrict__ atom37_mask,
    const float* __restrict__ lit_positions,
    const int* __restrict__ seq0i,
    float* __restrict__ out_pred,
    float* __restrict__ out_final,
    float* __restrict__ out_m14,
    float* __restrict__ out_m37)
{
    int r = blockIdx.x * blockDim.x + threadIdx.x;
    if (r >= RTOT) return;

    float q0 = rigids[r * 7 + 0], q1 = rigids[r * 7 + 1];
    float q2 = rigids[r * 7 + 2], q3 = rigids[r * 7 + 3];
    float tb0 = rigids[r * 7 + 4], tb1 = rigids[r * 7 + 5], tb2 = rigids[r * 7 + 6];
    float inv = rsqrtf(q0 * q0 + q1 * q1 + q2 * q2 + q3 * q3 + 1e-8f);
    float w = q0 * inv, x = q1 * inv, y = q2 * inv, z = q3 * inv;
    float rb[9];
    rb[0] = 1.f - 2.f * (y * y + z * z); rb[1] = 2.f * (x * y - w * z); rb[2] = 2.f * (x * z + w * y);
    rb[3] = 2.f * (x * y + w * z); rb[4] = 1.f - 2.f * (x * x + z * z); rb[5] = 2.f * (y * z - w * x);
    rb[6] = 2.f * (x * z - w * y); rb[7] = 2.f * (y * z + w * x); rb[8] = 1.f - 2.f * (x * x + y * y);

    int s = seq0i[r];

    float G[8][12];
    float chain_r[9], chain_t[3];

    for (int g = 0; g < 8; g++) {
        const float* df = default_frames + ((size_t)s * 8 + g) * 16;
        float dr[9], dt[3];
#pragma unroll
        for (int i = 0; i < 3; i++) {
            dr[i * 3 + 0] = df[i * 4 + 0];
            dr[i * 3 + 1] = df[i * 4 + 1];
            dr[i * 3 + 2] = df[i * 4 + 2];
            dt[i] = df[i * 4 + 3];
        }
        float sn, cs;
        if (g == 0) { sn = 0.f; cs = 1.f; }
        else { sn = angles[r * 14 + (g - 1) * 2 + 0]; cs = angles[r * 14 + (g - 1) * 2 + 1]; }

        float fr[9], ft[3];
#pragma unroll
        for (int i = 0; i < 3; i++) {
            fr[i * 3 + 0] = dr[i * 3 + 0];
            fr[i * 3 + 1] = dr[i * 3 + 1] * cs + dr[i * 3 + 2] * sn;
            fr[i * 3 + 2] = -dr[i * 3 + 1] * sn + dr[i * 3 + 2] * cs;
            ft[i] = dt[i];
        }

        float fo[9], to[3];
        if (g <= 4) {
#pragma unroll
            for (int i = 0; i < 9; i++) fo[i] = fr[i];
#pragma unroll
            for (int i = 0; i < 3; i++) to[i] = ft[i];
            if (g == 4) {
#pragma unroll
                for (int i = 0; i < 9; i++) chain_r[i] = fr[i];
#pragma unroll
                for (int i = 0; i < 3; i++) chain_t[i] = ft[i];
            }
        } else {
            float nr[9], nt[3];
#pragma unroll
            for (int i = 0; i < 3; i++) {
#pragma unroll
                for (int j = 0; j < 3; j++) {
                    nr[i * 3 + j] = chain_r[i * 3 + 0] * fr[0 * 3 + j]
                                  + chain_r[i * 3 + 1] * fr[1 * 3 + j]
                                  + chain_r[i * 3 + 2] * fr[2 * 3 + j];
                }
                nt[i] = chain_r[i * 3 + 0] * ft[0] + chain_r[i * 3 + 1] * ft[1]
                      + chain_r[i * 3 + 2] * ft[2] + chain_t[i];
            }
#pragma unroll
            for (int i = 0; i < 9; i++) { chain_r[i] = nr[i]; fo[i] = nr[i]; }
#pragma unroll
            for (int i = 0; i < 3; i++) { chain_t[i] = nt[i]; to[i] = nt[i]; }
        }

#pragma unroll
        for (int i = 0; i < 3; i++) {
#pragma unroll
            for (int j = 0; j < 3; j++) {
                G[g][i * 3 + j] = rb[i * 3 + 0] * fo[0 * 3 + j]
                                + rb[i * 3 + 1] * fo[1 * 3 + j]
                                + rb[i * 3 + 2] * fo[2 * 3 + j];
            }
        }
        G[g][9]  = rb[0] * to[0] + rb[1] * to[1] + rb[2] * to[2] + tb0;
        G[g][10] = rb[3] * to[0] + rb[4] * to[1] + rb[5] * to[2] + tb1;
        G[g][11] = rb[6] * to[0] + rb[7] * to[1] + rb[8] * to[2] + tb2;
    }

    float pv[14][3];
#pragma unroll
    for (int a = 0; a < 14; a++) {
        int gi = group_idx[s * 14 + a];
        const float* Gp = G[gi];
        float lx = lit_positions[((size_t)s * 14 + a) * 3 + 0];
        float ly = lit_positions[((size_t)s * 14 + a) * 3 + 1];
        float lz = lit_positions[((size_t)s * 14 + a) * 3 + 2];
        float m = atom14_mask[s * 14 + a];
        float px = (Gp[0] * lx + Gp[1] * ly + Gp[2] * lz + Gp[9])  * m;
        float py = (Gp[3] * lx + Gp[4] * ly + Gp[5] * lz + Gp[10]) * m;
        float pz = (Gp[6] * lx + Gp[7] * ly + Gp[8] * lz + Gp[11]) * m;
        pv[a][0] = px; pv[a][1] = py; pv[a][2] = pz;
        size_t po = ((size_t)r * 14 + a) * 3;
        out_pred[po + 0] = px; out_pred[po + 1] = py; out_pred[po + 2] = pz;
        out_m14[(size_t)r * 14 + a] = m;
    }

#pragma unroll
    for (int j = 0; j < 37; j++) {
        int a = residx[(size_t)r * 37 + j];
        size_t fo_ = ((size_t)r * 37 + j) * 3;
        out_final[fo_ + 0] = pv[a][0];
        out_final[fo_ + 1] = pv[a][1];
        out_final[fo_ + 2] = pv[a][2];
        out_m37[(size_t)r * 37 + j] = atom37_mask[s * 37 + j];
    }
}

// ---------------- launcher ----------------
extern "C" void kernel_launch(void* const* d_in, const int* in_sizes, int n_in,
                              void* d_out, int out_size)
{
    const float* act        = (const float*)d_in[0];
    const float* angles     = (const float*)d_in[1];
    const float* rigids     = (const float*)d_in[2];
    const int*   fixed_mask = (const int*)d_in[3];
    const int*   seq_t      = (const int*)d_in[4];
    const int*   residx     = (const int*)d_in[5];
    const float* ln_g       = (const float*)d_in[6];
    const float* ln_b       = (const float*)d_in[7];
    const float* w1         = (const float*)d_in[8];
    const float* b1         = (const float*)d_in[9];
    const float* w2         = (const float*)d_in[10];
    const float* b2         = (const float*)d_in[11];
    const float* w3         = (const float*)d_in[12];
    const float* b3         = (const float*)d_in[13];
    const float* dframes    = (const float*)d_in[14];
    const int*   group_idx  = (const int*)d_in[15];
    const float* a14_mask   = (const float*)d_in[16];
    const float* a37_mask   = (const float*)d_in[17];
    const float* lit        = (const float*)d_in[18];

    float* out = (float*)d_out;
    float* out_logits = out + OFF_LOGITS;
    float* out_seq0   = out + OFF_SEQ0;
    float* out_pred   = out + OFF_PRED;
    float* out_final  = out + OFF_FINAL;
    float* out_m14    = out + OFF_M14;
    float* out_m37    = out + OFF_M37;

    float *xnh, *xnl, *h1h, *h1l, *h2, *wt1h, *wt1l, *wt2h, *wt2l;
    int* seq0i;
    cudaGetSymbolAddress((void**)&xnh, g_xn_hi);
    cudaGetSymbolAddress((void**)&xnl, g_xn_lo);
    cudaGetSymbolAddress((void**)&h1h, g_h1_hi);
    cudaGetSymbolAddress((void**)&h1l, g_h1_lo);
    cudaGetSymbolAddress((void**)&h2,  g_h2);
    cudaGetSymbolAddress((void**)&wt1h, g_wt1_hi);
    cudaGetSymbolAddress((void**)&wt1l, g_wt1_lo);
    cudaGetSymbolAddress((void**)&wt2h, g_wt2_hi);
    cudaGetSymbolAddress((void**)&wt2l, g_wt2_lo);
    cudaGetSymbolAddress((void**)&seq0i, g_seq0i);

    const int GEMM_SMEM = 2 * BUFFB;   // 81920 B -> 2 CTAs/SM
    cudaFuncSetAttribute(mma_gemm_kernel<CIN, true>,
                         cudaFuncAttributeMaxDynamicSharedMemorySize, GEMM_SMEM);
    cudaFuncSetAttribute(mma_gemm_kernel<HID, false>,
                         cudaFuncAttributeMaxDynamicSharedMemorySize, GEMM_SMEM);
    cudaFuncSetAttribute(head_kernel,
                         cudaFuncAttributeMaxDynamicSharedMemorySize, NRES * HID * 4);

    // 1. LayerNorm with tf32 split output
    ln_kernel<<<RTOT / 8, 256>>>(act, ln_g, ln_b, xnh, xnl);

    // 2. weight prep: coalesced transpose + tf32 split
    {
        dim3 blk(32, 8);
        dim3 g1(HID / 32, CIN / 32);
        tsplit_kernel<<<g1, blk>>>(w1, wt1h, wt1l, CIN, HID);
        dim3 g2(HID / 32, HID / 32);
        tsplit_kernel<<<g2, blk>>>(w2, wt2h, wt2l, HID, HID);
    }

    // 3. GEMM1: relu(xn @ w1 + b1) -> h1 (split)
    {
        dim3 grid(HID / 128, RTOT / 128);
        mma_gemm_kernel<CIN, true><<<grid, 256, GEMM_SMEM>>>(
            xnh, xnl, wt1h, wt1l, b1, h1h, h1l);
    }
    // 4. GEMM2: relu(h1 @ w2 + b2) -> h2
    {
        dim3 grid(HID / 128, RTOT / 128);
        mma_gemm_kernel<HID, false><<<grid, 256, GEMM_SMEM>>>(
            h1h, h1l, wt2h, wt2l, b2, h2, nullptr);
    }
    // 5. logits + argmax + select
    head_kernel<<<RTOT / 64, 256, NRES * HID * 4>>>(h2, w3, b3, fixed_mask, seq_t,
                                                    out_logits, out_seq0, seq0i);
    // 6. geometry
    geom_kernel<<<RTOT / 128, 128>>>(angles, rigids, residx, dframes, group_idx,
                                     a14_mask, a37_mask, lit, seq0i,
                                     out_pred, out_final, out_m14, out_m37);
}

// round 7
// speedup vs baseline: 1.4068x; 1.0628x over previous
#include <cuda_runtime.h>
#include <math.h>
#include <stdint.h>

// ---------------- problem constants ----------------
#define RTOT   32768          // B*N = 32*1024
#define CIN    384
#define HID    1024
#define NRES   20

// output layout (floats)
#define OFF_LOGITS 0
#define OFF_SEQ0   655360
#define OFF_PRED   688128
#define OFF_FINAL  2064384
#define OFF_M14    5701632
#define OFF_M37    6160384

// ---------------- scratch (no cudaMalloc allowed) ----------------
__device__ float g_xn_hi[(size_t)RTOT * CIN];
__device__ float g_xn_lo[(size_t)RTOT * CIN];
__device__ float g_h1_hi[(size_t)RTOT * HID];
__device__ float g_h1_lo[(size_t)RTOT * HID];
__device__ float g_h2[(size_t)RTOT * HID];
__device__ float g_wt1_hi[(size_t)HID * CIN];
__device__ float g_wt1_lo[(size_t)HID * CIN];
__device__ float g_wt2_hi[(size_t)HID * HID];
__device__ float g_wt2_lo[(size_t)HID * HID];
__device__ int   g_seq0i[RTOT];

__device__ __forceinline__ float tf32r(float v) {
    uint32_t u;
    asm("cvt.rna.tf32.f32 %0, %1;" : "=r"(u) : "f"(v));
    return __uint_as_float(u);
}

__device__ __forceinline__ void mma8(float c[4], const uint32_t a[4], const uint32_t b[2]) {
    asm volatile("mma.sync.aligned.m16n8k8.row.col.f32.tf32.tf32.f32 "
        "{%0,%1,%2,%3}, {%4,%5,%6,%7}, {%8,%9}, {%0,%1,%2,%3};"
        : "+f"(c[0]), "+f"(c[1]), "+f"(c[2]), "+f"(c[3])
        : "r"(a[0]), "r"(a[1]), "r"(a[2]), "r"(a[3]), "r"(b[0]), "r"(b[1]));
}

__device__ __forceinline__ void ldsm4(uint32_t r[4], uint32_t addr) {
    asm volatile("ldmatrix.sync.aligned.m8n8.x4.shared.b16 {%0,%1,%2,%3}, [%4];"
        : "=r"(r[0]), "=r"(r[1]), "=r"(r[2]), "=r"(r[3]) : "r"(addr));
}

__device__ __forceinline__ uint32_t smem_u32(const void* p) {
    uint32_t a;
    asm("{ .reg .u64 t; cvta.to.shared.u64 t, %1; cvt.u32.u64 %0, t; }" : "=r"(a) : "l"(p));
    return a;
}

#define CP16(dst, src) \
    asm volatile("cp.async.cg.shared.global [%0], [%1], 16;" :: "r"(dst), "l"(src))
#define CP_COMMIT() asm volatile("cp.async.commit_group;" ::: "memory")
#define CP_WAIT(n)  asm volatile("cp.async.wait_group %0;" :: "n"(n) : "memory")

// ---------------- LayerNorm -> split tf32 hi/lo ----------------
__global__ __launch_bounds__(256) void ln_kernel(
    const float* __restrict__ act,
    const float* __restrict__ gamma,
    const float* __restrict__ beta,
    float* __restrict__ out_hi,
    float* __restrict__ out_lo)
{
    int row  = blockIdx.x * 8 + (threadIdx.x >> 5);
    int lane = threadIdx.x & 31;
    const float* x = act + (size_t)row * CIN;

    float v[12];
    float sum = 0.f;
#pragma unroll
    for (int i = 0; i < 12; i++) { v[i] = x[lane + i * 32]; sum += v[i]; }
#pragma unroll
    for (int o = 16; o; o >>= 1) sum += __shfl_xor_sync(0xffffffffu, sum, o);
    float mu = sum * (1.f / CIN);

    float vs = 0.f;
#pragma unroll
    for (int i = 0; i < 12; i++) { float d = v[i] - mu; vs += d * d; }
#pragma unroll
    for (int o = 16; o; o >>= 1) vs += __shfl_xor_sync(0xffffffffu, vs, o);
    float rstd = rsqrtf(vs * (1.f / CIN) + 1e-5f);

    float* oh = out_hi + (size_t)row * CIN;
    float* ol = out_lo + (size_t)row * CIN;
#pragma unroll
    for (int i = 0; i < 12; i++) {
        int c = lane + i * 32;
        float y = (v[i] - mu) * rstd * gamma[c] + beta[c];
        float hi = tf32r(y);
        oh[c] = hi;
        ol[c] = tf32r(y - hi);
    }
}

// ---------------- coalesced transpose + tf32 split: W[K,N] -> T[N,K] hi/lo ----------------
__global__ __launch_bounds__(256) void tsplit_kernel(
    const float* __restrict__ W, float* __restrict__ Th, float* __restrict__ Tl,
    int Krows, int Ncols)
{
    __shared__ float t[32][33];
    const int tx = threadIdx.x;    // 0..31
    const int ty = threadIdx.y;    // 0..7
    const int n0 = blockIdx.x * 32;
    const int k0 = blockIdx.y * 32;

#pragma unroll
    for (int j = ty; j < 32; j += 8)
        t[j][tx] = W[(size_t)(k0 + j) * Ncols + n0 + tx];
    __syncthreads();

#pragma unroll
    for (int j = ty; j < 32; j += 8) {
        float v = t[tx][j];
        float hi = tf32r(v);
        size_t o = (size_t)(n0 + j) * Krows + k0 + tx;
        Th[o] = hi;
        Tl[o] = tf32r(v - hi);
    }
}

// ---------------- tf32x3 mma.sync GEMM: 3-stage cp.async + ldmatrix ----------------
// C[M,1024] = relu(A[M,K] @ Bt[1024,K]^T + bias)
// block tile 128(M) x 256(N) x 16(K), 16 warps (4M x 4N), warp tile 32x64
// 3 smem stages, 1 __syncthreads per k-tile, prefetch distance 2
#define SROW 20                         // padded smem row stride (floats)
#define A_ARRB (128 * SROW * 4)         // 10240 B
#define B_ARRB (256 * SROW * 4)         // 20480 B
#define ST_AH  0
#define ST_AL  (A_ARRB)
#define ST_BH  (2 * A_ARRB)
#define ST_BL  (2 * A_ARRB + B_ARRB)
#define STAGEB (2 * A_ARRB + 2 * B_ARRB)  // 61440 B
#define NSTAGE 3

template<int K, bool SPLIT_OUT>
__global__ __launch_bounds__(512, 1) void mma_gemm_kernel(
    const float* __restrict__ Ah, const float* __restrict__ Al,
    const float* __restrict__ Bh, const float* __restrict__ Bl,
    const float* __restrict__ bias,
    float* __restrict__ Ch, float* __restrict__ Cl)
{
    constexpr int KT = K / 16;
    extern __shared__ float smem[];

    const int tid   = threadIdx.x;
    const int wid   = tid >> 5;
    const int lane  = tid & 31;
    const int warpM = wid & 3;          // 0..3
    const int warpN = wid >> 2;         // 0..3
    const int gr    = lane >> 2;
    const int tc    = lane & 3;

    const int m0 = blockIdx.y * 128;
    const int n0 = blockIdx.x * 256;

    // global load mapping:
    // A: row = tid>>2 (0..127), col = (tid&3)*4  -> 1 CP16 per array
    // B: rows tid>>2 and (tid>>2)+128, col = (tid&3)*4 -> 2 CP16 per array
    const int arow = tid >> 2;
    const int acol = (tid & 3) * 4;
    const float* gAh = Ah + (size_t)(m0 + arow) * K + acol;
    const float* gAl = Al + (size_t)(m0 + arow) * K + acol;
    const float* gBh0 = Bh + (size_t)(n0 + arow) * K + acol;
    const float* gBl0 = Bl + (size_t)(n0 + arow) * K + acol;
    const float* gBh1 = Bh + (size_t)(n0 + arow + 128) * K + acol;
    const float* gBl1 = Bl + (size_t)(n0 + arow + 128) * K + acol;

    const uint32_t sbase = smem_u32(smem);
    const uint32_t aoff  = (uint32_t)(arow * SROW + acol) * 4;          // A arrays
    const uint32_t boff0 = (uint32_t)(arow * SROW + acol) * 4;          // B rows 0..127
    const uint32_t boff1 = (uint32_t)((arow + 128) * SROW + acol) * 4;  // B rows 128..255

    // ldmatrix lane addressing (byte offsets within an array)
    const uint32_t aLane = (uint32_t)((warpM * 32 + (lane & 15)) * SROW + (lane >> 4) * 4) * 4;
    const uint32_t bLane = (uint32_t)((warpN * 64 + ((lane >> 4) & 1) * 8 + (lane & 7)) * SROW
                                      + ((lane >> 3) & 1) * 4) * 4;

    float acc[2][8][4];
#pragma unroll
    for (int i = 0; i < 2; i++)
#pragma unroll
        for (int j = 0; j < 8; j++)
#pragma unroll
            for (int q = 0; q < 4; q++) acc[i][j][q] = 0.f;

    // prefetch helper (kt -> stage s)
#define PREFETCH(kt_, s_) do { \
        const int _kg = (kt_) * 16; \
        const uint32_t _db = sbase + (uint32_t)(s_) * STAGEB; \
        CP16(_db + ST_AH + aoff,  gAh  + _kg); \
        CP16(_db + ST_AL + aoff,  gAl  + _kg); \
        CP16(_db + ST_BH + boff0, gBh0 + _kg); \
        CP16(_db + ST_BH + boff1, gBh1 + _kg); \
        CP16(_db + ST_BL + boff0, gBl0 + _kg); \
        CP16(_db + ST_BL + boff1, gBl1 + _kg); \
        CP_COMMIT(); \
    } while (0)

    PREFETCH(0, 0);
    PREFETCH(1, 1);

    int s_cur = 0;        // stage of kt
    int s_nxt2 = 2;       // stage of kt+2
    for (int kt = 0; kt < KT; ++kt) {
        CP_WAIT(1);            // group kt complete (kt+1 may be in flight)
        __syncthreads();       // all threads' stage-kt data visible; all past kt-1 MMAs
        if (kt + 2 < KT) {
            PREFETCH(kt + 2, s_nxt2);   // overwrites stage read at kt-1 — safe after sync
        }

        const uint32_t stage = sbase + (uint32_t)s_cur * STAGEB;
        const uint32_t aHi = stage + ST_AH + aLane;
        const uint32_t aLo = stage + ST_AL + aLane;
        const uint32_t bHi = stage + ST_BH + bLane;
        const uint32_t bLo = stage + ST_BL + bLane;

#pragma unroll
        for (int ks = 0; ks < 2; ks++) {
            const uint32_t ko = ks * 32;   // 8 floats
            uint32_t ah[2][4], al[2][4], bh[4][4], bl[4][4];
#pragma unroll
            for (int ms = 0; ms < 2; ms++) {
                ldsm4(ah[ms], aHi + ms * (16 * SROW * 4) + ko);
                ldsm4(al[ms], aLo + ms * (16 * SROW * 4) + ko);
            }
#pragma unroll
            for (int p = 0; p < 4; p++) {
                ldsm4(bh[p], bHi + p * (16 * SROW * 4) + ko);
                ldsm4(bl[p], bLo + p * (16 * SROW * 4) + ko);
            }
#pragma unroll
            for (int ms = 0; ms < 2; ms++)
#pragma unroll
                for (int p = 0; p < 4; p++) {
                    mma8(acc[ms][2 * p],     ah[ms], &bh[p][0]);
                    mma8(acc[ms][2 * p + 1], ah[ms], &bh[p][2]);
                }
#pragma unroll
            for (int ms = 0; ms < 2; ms++)
#pragma unroll
                for (int p = 0; p < 4; p++) {
                    mma8(acc[ms][2 * p],     ah[ms], &bl[p][0]);
                    mma8(acc[ms][2 * p + 1], ah[ms], &bl[p][2]);
                }
#pragma unroll
            for (int ms = 0; ms < 2; ms++)
#pragma unroll
                for (int p = 0; p < 4; p++) {
                    mma8(acc[ms][2 * p],     al[ms], &bh[p][0]);
                    mma8(acc[ms][2 * p + 1], al[ms], &bh[p][2]);
                }
        }
        // advance cyclic stage counters
        s_cur = (s_cur == 2) ? 0 : s_cur + 1;
        s_nxt2 = (s_nxt2 == 2) ? 0 : s_nxt2 + 1;
    }
#undef PREFETCH

    // epilogue: bias + relu (+ optional tf32 split), direct stores
    const int mwb = m0 + warpM * 32;
    const int nwb = n0 + warpN * 64;
#pragma unroll
    for (int ms = 0; ms < 2; ms++) {
        int r0 = mwb + ms * 16 + gr;
        int r1 = r0 + 8;
#pragma unroll
        for (int ns = 0; ns < 8; ns++) {
            int c = nwb + ns * 8 + 2 * tc;
            float bz0 = bias[c], bz1 = bias[c + 1];
            float v0 = fmaxf(acc[ms][ns][0] + bz0, 0.f);
            float v1 = fmaxf(acc[ms][ns][1] + bz1, 0.f);
            float v2 = fmaxf(acc[ms][ns][2] + bz0, 0.f);
            float v3 = fmaxf(acc[ms][ns][3] + bz1, 0.f);
            if (SPLIT_OUT) {
                float h0 = tf32r(v0), h1 = tf32r(v1), h2 = tf32r(v2), h3 = tf32r(v3);
                *(float2*)(Ch + (size_t)r0 * HID + c) = make_float2(h0, h1);
                *(float2*)(Ch + (size_t)r1 * HID + c) = make_float2(h2, h3);
                *(float2*)(Cl + (size_t)r0 * HID + c) =
                    make_float2(tf32r(v0 - h0), tf32r(v1 - h1));
                *(float2*)(Cl + (size_t)r1 * HID + c) =
                    make_float2(tf32r(v2 - h2), tf32r(v3 - h3));
            } else {
                *(float2*)(Ch + (size_t)r0 * HID + c) = make_float2(v0, v1);
                *(float2*)(Ch + (size_t)r1 * HID + c) = make_float2(v2, v3);
            }
        }
    }
}

// ---------------- head: logits = h2 @ w3 + b3, argmax, select ----------------
__global__ __launch_bounds__(256) void head_kernel(
    const float* __restrict__ h2,
    const float* __restrict__ w3,
    const float* __restrict__ b3,
    const int* __restrict__ fixed_mask,
    const int* __restrict__ seq_t,
    float* __restrict__ out_logits,
    float* __restrict__ out_seq0f,
    int* __restrict__ seq0i)
{
    extern __shared__ float w3s[];   // [20][1024]
    const int tid = threadIdx.x;
    const int wid = tid >> 5;
    const int lane = tid & 31;

    for (int i = tid; i < NRES * HID; i += 256) {
        int c = i >> 10;
        int k = i & 1023;
        w3s[i] = w3[k * NRES + c];
    }
    __syncthreads();

    const int rbase = blockIdx.x * 64 + wid * 8;
#pragma unroll
    for (int j = 0; j < 8; j += 2) {
        int ra = rbase + j, rb = ra + 1;
        const float* ha = h2 + (size_t)ra * HID;
        const float* hb = h2 + (size_t)rb * HID;
        float acc0[NRES], acc1[NRES];
#pragma unroll
        for (int c = 0; c < NRES; c++) { acc0[c] = 0.f; acc1[c] = 0.f; }
        for (int it = 0; it < 32; it++) {
            int k = it * 32 + lane;
            float va = ha[k];
            float vb = hb[k];
#pragma unroll
            for (int c = 0; c < NRES; c++) {
                float w = w3s[c * HID + k];
                acc0[c] = fmaf(va, w, acc0[c]);
                acc1[c] = fmaf(vb, w, acc1[c]);
            }
        }
#pragma unroll
        for (int c = 0; c < NRES; c++) {
#pragma unroll
            for (int o = 16; o; o >>= 1) {
                acc0[c] += __shfl_xor_sync(0xffffffffu, acc0[c], o);
                acc1[c] += __shfl_xor_sync(0xffffffffu, acc1[c], o);
            }
        }
        if (lane == 0) {
            int best0 = 0, best1 = 0;
            float bv0 = -INFINITY, bv1 = -INFINITY;
            float* l0 = out_logits + (size_t)ra * NRES;
            float* l1 = out_logits + (size_t)rb * NRES;
#pragma unroll
            for (int c = 0; c < NRES; c++) {
                float v0 = acc0[c] + b3[c];
                float v1 = acc1[c] + b3[c];
                l0[c] = v0; l1[c] = v1;
                if (v0 > bv0) { bv0 = v0; best0 = c; }
                if (v1 > bv1) { bv1 = v1; best1 = c; }
            }
            int s0 = fixed_mask[ra] ? seq_t[ra] : best0;
            int s1 = fixed_mask[rb] ? seq_t[rb] : best1;
            seq0i[ra] = s0; seq0i[rb] = s1;
            out_seq0f[ra] = (float)s0; out_seq0f[rb] = (float)s1;
        }
    }
}

// ---------------- geometry: one thread per residue ----------------
__global__ __launch_bounds__(128) void geom_kernel(
    const float* __restrict__ angles,
    const float* __restrict__ rigids,
    const int* __restrict__ residx,
    const float* __restrict__ default_frames,
    const int* __restrict__ group_idx,
    const float* __restrict__ atom14_mask,
    const float* __restrict__ atom37_mask,
    const float* __restrict__ lit_positions,
    const int* __restrict__ seq0i,
    float* __restrict__ out_pred,
    float* __restrict__ out_final,
    float* __restrict__ out_m14,
    float* __restrict__ out_m37)
{
    int r = blockIdx.x * blockDim.x + threadIdx.x;
    if (r >= RTOT) return;

    float q0 = rigids[r * 7 + 0], q1 = rigids[r * 7 + 1];
    float q2 = rigids[r * 7 + 2], q3 = rigids[r * 7 + 3];
    float tb0 = rigids[r * 7 + 4], tb1 = rigids[r * 7 + 5], tb2 = rigids[r * 7 + 6];
    float inv = rsqrtf(q0 * q0 + q1 * q1 + q2 * q2 + q3 * q3 + 1e-8f);
    float w = q0 * inv, x = q1 * inv, y = q2 * inv, z = q3 * inv;
    float rb[9];
    rb[0] = 1.f - 2.f * (y * y + z * z); rb[1] = 2.f * (x * y - w * z); rb[2] = 2.f * (x * z + w * y);
    rb[3] = 2.f * (x * y + w * z); rb[4] = 1.f - 2.f * (x * x + z * z); rb[5] = 2.f * (y * z - w * x);
    rb[6] = 2.f * (x * z - w * y); rb[7] = 2.f * (y * z + w * x); rb[8] = 1.f - 2.f * (x * x + y * y);

    int s = seq0i[r];

    float G[8][12];
    float chain_r[9], chain_t[3];

    for (int g = 0; g < 8; g++) {
        const float* df = default_frames + ((size_t)s * 8 + g) * 16;
        float dr[9], dt[3];
#pragma unroll
        for (int i = 0; i < 3; i++) {
            dr[i * 3 + 0] = df[i * 4 + 0];
            dr[i * 3 + 1] = df[i * 4 + 1];
            dr[i * 3 + 2] = df[i * 4 + 2];
            dt[i] = df[i * 4 + 3];
        }
        float sn, cs;
        if (g == 0) { sn = 0.f; cs = 1.f; }
        else { sn = angles[r * 14 + (g - 1) * 2 + 0]; cs = angles[r * 14 + (g - 1) * 2 + 1]; }

        float fr[9], ft[3];
#pragma unroll
        for (int i = 0; i < 3; i++) {
            fr[i * 3 + 0] = dr[i * 3 + 0];
            fr[i * 3 + 1] = dr[i * 3 + 1] * cs + dr[i * 3 + 2] * sn;
            fr[i * 3 + 2] = -dr[i * 3 + 1] * sn + dr[i * 3 + 2] * cs;
            ft[i] = dt[i];
        }

        float fo[9], to[3];
        if (g <= 4) {
#pragma unroll
            for (int i = 0; i < 9; i++) fo[i] = fr[i];
#pragma unroll
            for (int i = 0; i < 3; i++) to[i] = ft[i];
            if (g == 4) {
#pragma unroll
                for (int i = 0; i < 9; i++) chain_r[i] = fr[i];
#pragma unroll
                for (int i = 0; i < 3; i++) chain_t[i] = ft[i];
            }
        } else {
            float nr[9], nt[3];
#pragma unroll
            for (int i = 0; i < 3; i++) {
#pragma unroll
                for (int j = 0; j < 3; j++) {
                    nr[i * 3 + j] = chain_r[i * 3 + 0] * fr[0 * 3 + j]
                                  + chain_r[i * 3 + 1] * fr[1 * 3 + j]
                                  + chain_r[i * 3 + 2] * fr[2 * 3 + j];
                }
                nt[i] = chain_r[i * 3 + 0] * ft[0] + chain_r[i * 3 + 1] * ft[1]
                      + chain_r[i * 3 + 2] * ft[2] + chain_t[i];
            }
#pragma unroll
            for (int i = 0; i < 9; i++) { chain_r[i] = nr[i]; fo[i] = nr[i]; }
#pragma unroll
            for (int i = 0; i < 3; i++) { chain_t[i] = nt[i]; to[i] = nt[i]; }
        }

#pragma unroll
        for (int i = 0; i < 3; i++) {
#pragma unroll
            for (int j = 0; j < 3; j++) {
                G[g][i * 3 + j] = rb[i * 3 + 0] * fo[0 * 3 + j]
                                + rb[i * 3 + 1] * fo[1 * 3 + j]
                                + rb[i * 3 + 2] * fo[2 * 3 + j];
            }
        }
        G[g][9]  = rb[0] * to[0] + rb[1] * to[1] + rb[2] * to[2] + tb0;
        G[g][10] = rb[3] * to[0] + rb[4] * to[1] + rb[5] * to[2] + tb1;
        G[g][11] = rb[6] * to[0] + rb[7] * to[1] + rb[8] * to[2] + tb2;
    }

    float pv[14][3];
#pragma unroll
    for (int a = 0; a < 14; a++) {
        int gi = group_idx[s * 14 + a];
        const float* Gp = G[gi];
        float lx = lit_positions[((size_t)s * 14 + a) * 3 + 0];
        float ly = lit_positions[((size_t)s * 14 + a) * 3 + 1];
        float lz = lit_positions[((size_t)s * 14 + a) * 3 + 2];
        float m = atom14_mask[s * 14 + a];
        float px = (Gp[0] * lx + Gp[1] * ly + Gp[2] * lz + Gp[9])  * m;
        float py = (Gp[3] * lx + Gp[4] * ly + Gp[5] * lz + Gp[10]) * m;
        float pz = (Gp[6] * lx + Gp[7] * ly + Gp[8] * lz + Gp[11]) * m;
        pv[a][0] = px; pv[a][1] = py; pv[a][2] = pz;
        size_t po = ((size_t)r * 14 + a) * 3;
        out_pred[po + 0] = px; out_pred[po + 1] = py; out_pred[po + 2] = pz;
        out_m14[(size_t)r * 14 + a] = m;
    }

#pragma unroll
    for (int j = 0; j < 37; j++) {
        int a = residx[(size_t)r * 37 + j];
        size_t fo_ = ((size_t)r * 37 + j) * 3;
        out_final[fo_ + 0] = pv[a][0];
        out_final[fo_ + 1] = pv[a][1];
        out_final[fo_ + 2] = pv[a][2];
        out_m37[(size_t)r * 37 + j] = atom37_mask[s * 37 + j];
    }
}

// ---------------- launcher ----------------
extern "C" void kernel_launch(void* const* d_in, const int* in_sizes, int n_in,
                              void* d_out, int out_size)
{
    const float* act        = (const float*)d_in[0];
    const float* angles     = (const float*)d_in[1];
    const float* rigids     = (const float*)d_in[2];
    const int*   fixed_mask = (const int*)d_in[3];
    const int*   seq_t      = (const int*)d_in[4];
    const int*   residx     = (const int*)d_in[5];
    const float* ln_g       = (const float*)d_in[6];
    const float* ln_b       = (const float*)d_in[7];
    const float* w1         = (const float*)d_in[8];
    const float* b1         = (const float*)d_in[9];
    const float* w2         = (const float*)d_in[10];
    const float* b2         = (const float*)d_in[11];
    const float* w3         = (const float*)d_in[12];
    const float* b3         = (const float*)d_in[13];
    const float* dframes    = (const float*)d_in[14];
    const int*   group_idx  = (const int*)d_in[15];
    const float* a14_mask   = (const float*)d_in[16];
    const float* a37_mask   = (const float*)d_in[17];
    const float* lit        = (const float*)d_in[18];

    float* out = (float*)d_out;
    float* out_logits = out + OFF_LOGITS;
    float* out_seq0   = out + OFF_SEQ0;
    float* out_pred   = out + OFF_PRED;
    float* out_final  = out + OFF_FINAL;
    float* out_m14    = out + OFF_M14;
    float* out_m37    = out + OFF_M37;

    float *xnh, *xnl, *h1h, *h1l, *h2, *wt1h, *wt1l, *wt2h, *wt2l;
    int* seq0i;
    cudaGetSymbolAddress((void**)&xnh, g_xn_hi);
    cudaGetSymbolAddress((void**)&xnl, g_xn_lo);
    cudaGetSymbolAddress((void**)&h1h, g_h1_hi);
    cudaGetSymbolAddress((void**)&h1l, g_h1_lo);
    cudaGetSymbolAddress((void**)&h2,  g_h2);
    cudaGetSymbolAddress((void**)&wt1h, g_wt1_hi);
    cudaGetSymbolAddress((void**)&wt1l, g_wt1_lo);
    cudaGetSymbolAddress((void**)&wt2h, g_wt2_hi);
    cudaGetSymbolAddress((void**)&wt2l, g_wt2_lo);
    cudaGetSymbolAddress((void**)&seq0i, g_seq0i);

    const int GEMM_SMEM = NSTAGE * STAGEB;   // 184320 B -> 1 CTA, 16 warps/SM
    cudaFuncSetAttribute(mma_gemm_kernel<CIN, true>,
                         cudaFuncAttributeMaxDynamicSharedMemorySize, GEMM_SMEM);
    cudaFuncSetAttribute(mma_gemm_kernel<HID, false>,
                         cudaFuncAttributeMaxDynamicSharedMemorySize, GEMM_SMEM);
    cudaFuncSetAttribute(head_kernel,
                         cudaFuncAttributeMaxDynamicSharedMemorySize, NRES * HID * 4);

    // 1. LayerNorm with tf32 split output
    ln_kernel<<<RTOT / 8, 256>>>(act, ln_g, ln_b, xnh, xnl);

    // 2. weight prep: coalesced transpose + tf32 split
    {
        dim3 blk(32, 8);
        dim3 g1(HID / 32, CIN / 32);
        tsplit_kernel<<<g1, blk>>>(w1, wt1h, wt1l, CIN, HID);
        dim3 g2(HID / 32, HID / 32);
        tsplit_kernel<<<g2, blk>>>(w2, wt2h, wt2l, HID, HID);
    }

    // 3. GEMM1: relu(xn @ w1 + b1) -> h1 (split)
    {
        dim3 grid(HID / 256, RTOT / 128);
        mma_gemm_kernel<CIN, true><<<grid, 512, GEMM_SMEM>>>(
            xnh, xnl, wt1h, wt1l, b1, h1h, h1l);
    }
    // 4. GEMM2: relu(h1 @ w2 + b2) -> h2
    {
        dim3 grid(HID / 256, RTOT / 128);
        mma_gemm_kernel<HID, false><<<grid, 512, GEMM_SMEM>>>(
            h1h, h1l, wt2h, wt2l, b2, h2, nullptr);
    }
    // 5. logits + argmax + select
    head_kernel<<<RTOT / 64, 256, NRES * HID * 4>>>(h2, w3, b3, fixed_mask, seq_t,
                                                    out_logits, out_seq0, seq0i);
    // 6. geometry
    geom_kernel<<<RTOT / 128, 128>>>(angles, rigids, residx, dframes, group_idx,
                                     a14_mask, a37_mask, lit, seq0i,
                                     out_pred, out_final, out_m14, out_m37);
}

// round 8
// speedup vs baseline: 1.4227x; 1.0113x over previous
#include <cuda_runtime.h>
#include <math.h>
#include <stdint.h>

// ---------------- problem constants ----------------
#define RTOT   32768          // B*N = 32*1024
#define CIN    384
#define HID    1024
#define NRES   20

// output layout (floats)
#define OFF_LOGITS 0
#define OFF_SEQ0   655360
#define OFF_PRED   688128
#define OFF_FINAL  2064384
#define OFF_M14    5701632
#define OFF_M37    6160384

// ---------------- scratch (no cudaMalloc allowed) ----------------
__device__ float g_xn_hi[(size_t)RTOT * CIN];
__device__ float g_xn_lo[(size_t)RTOT * CIN];
__device__ float g_h1_hi[(size_t)RTOT * HID];
__device__ float g_h1_lo[(size_t)RTOT * HID];
__device__ float g_h2[(size_t)RTOT * HID];
__device__ float g_wt1_hi[(size_t)HID * CIN];
__device__ float g_wt1_lo[(size_t)HID * CIN];
__device__ float g_wt2_hi[(size_t)HID * HID];
__device__ float g_wt2_lo[(size_t)HID * HID];
__device__ int   g_seq0i[RTOT];

__device__ __forceinline__ float tf32r(float v) {
    uint32_t u;
    asm("cvt.rna.tf32.f32 %0, %1;" : "=r"(u) : "f"(v));
    return __uint_as_float(u);
}

__device__ __forceinline__ void mma8(float c[4], const uint32_t a[4], const uint32_t b[2]) {
    asm volatile("mma.sync.aligned.m16n8k8.row.col.f32.tf32.tf32.f32 "
        "{%0,%1,%2,%3}, {%4,%5,%6,%7}, {%8,%9}, {%0,%1,%2,%3};"
        : "+f"(c[0]), "+f"(c[1]), "+f"(c[2]), "+f"(c[3])
        : "r"(a[0]), "r"(a[1]), "r"(a[2]), "r"(a[3]), "r"(b[0]), "r"(b[1]));
}

__device__ __forceinline__ void ldsm4(uint32_t r[4], uint32_t addr) {
    asm volatile("ldmatrix.sync.aligned.m8n8.x4.shared.b16 {%0,%1,%2,%3}, [%4];"
        : "=r"(r[0]), "=r"(r[1]), "=r"(r[2]), "=r"(r[3]) : "r"(addr));
}

__device__ __forceinline__ uint32_t smem_u32(const void* p) {
    uint32_t a;
    asm("{ .reg .u64 t; cvta.to.shared.u64 t, %1; cvt.u32.u64 %0, t; }" : "=r"(a) : "l"(p));
    return a;
}

#define CP16(dst, src) \
    asm volatile("cp.async.cg.shared.global [%0], [%1], 16;" :: "r"(dst), "l"(src))
#define CP_COMMIT() asm volatile("cp.async.commit_group;" ::: "memory")
#define CP_WAIT(n)  asm volatile("cp.async.wait_group %0;" :: "n"(n) : "memory")

// ---------------- LayerNorm -> split tf32 hi/lo ----------------
__global__ __launch_bounds__(256) void ln_kernel(
    const float* __restrict__ act,
    const float* __restrict__ gamma,
    const float* __restrict__ beta,
    float* __restrict__ out_hi,
    float* __restrict__ out_lo)
{
    int row  = blockIdx.x * 8 + (threadIdx.x >> 5);
    int lane = threadIdx.x & 31;
    const float* x = act + (size_t)row * CIN;

    float v[12];
    float sum = 0.f;
#pragma unroll
    for (int i = 0; i < 12; i++) { v[i] = x[lane + i * 32]; sum += v[i]; }
#pragma unroll
    for (int o = 16; o; o >>= 1) sum += __shfl_xor_sync(0xffffffffu, sum, o);
    float mu = sum * (1.f / CIN);

    float vs = 0.f;
#pragma unroll
    for (int i = 0; i < 12; i++) { float d = v[i] - mu; vs += d * d; }
#pragma unroll
    for (int o = 16; o; o >>= 1) vs += __shfl_xor_sync(0xffffffffu, vs, o);
    float rstd = rsqrtf(vs * (1.f / CIN) + 1e-5f);

    float* oh = out_hi + (size_t)row * CIN;
    float* ol = out_lo + (size_t)row * CIN;
#pragma unroll
    for (int i = 0; i < 12; i++) {
        int c = lane + i * 32;
        float y = (v[i] - mu) * rstd * gamma[c] + beta[c];
        float hi = tf32r(y);
        oh[c] = hi;
        ol[c] = tf32r(y - hi);
    }
}

// ---------------- coalesced transpose + tf32 split: W[K,N] -> T[N,K] hi/lo ----------------
__global__ __launch_bounds__(256) void tsplit_kernel(
    const float* __restrict__ W, float* __restrict__ Th, float* __restrict__ Tl,
    int Krows, int Ncols)
{
    __shared__ float t[32][33];
    const int tx = threadIdx.x;    // 0..31
    const int ty = threadIdx.y;    // 0..7
    const int n0 = blockIdx.x * 32;
    const int k0 = blockIdx.y * 32;

#pragma unroll
    for (int j = ty; j < 32; j += 8)
        t[j][tx] = W[(size_t)(k0 + j) * Ncols + n0 + tx];
    __syncthreads();

#pragma unroll
    for (int j = ty; j < 32; j += 8) {
        float v = t[tx][j];
        float hi = tf32r(v);
        size_t o = (size_t)(n0 + j) * Krows + k0 + tx;
        Th[o] = hi;
        Tl[o] = tf32r(v - hi);
    }
}

// ---------------- tf32x3 mma.sync GEMM: 4-stage cp.async + ldmatrix ----------------
// C[M,1024] = relu(A[M,K] @ Bt[1024,K]^T + bias)
// block tile 128(M) x 256(N) x 16(K), 16 warps (4M x 4N), warp tile 32x64
// hi/lo interleaved per row: [hi 64B | lo 64B], stride 144B
// 4 smem stages, 1 __syncthreads per k-tile, prefetch distance 3
#define SROWI 36                        // interleaved row stride (floats) = 144B
#define A_ARRB (128 * SROWI * 4)        // 18432 B
#define B_ARRB (256 * SROWI * 4)        // 36864 B
#define ST_A   0
#define ST_B   A_ARRB
#define STAGEB (A_ARRB + B_ARRB)        // 55296 B
#define NSTAGE 4
#define LO_OFF 64                       // byte offset of lo half within a row

template<int K, bool SPLIT_OUT>
__global__ __launch_bounds__(512, 1) void mma_gemm_kernel(
    const float* __restrict__ Ah, const float* __restrict__ Al,
    const float* __restrict__ Bh, const float* __restrict__ Bl,
    const float* __restrict__ bias,
    float* __restrict__ Ch, float* __restrict__ Cl)
{
    constexpr int KT = K / 16;
    extern __shared__ float smem[];

    const int tid   = threadIdx.x;
    const int wid   = tid >> 5;
    const int lane  = tid & 31;
    const int warpM = wid & 3;          // 0..3
    const int warpN = wid >> 2;         // 0..3
    const int gr    = lane >> 2;
    const int tc    = lane & 3;

    const int m0 = blockIdx.y * 128;
    const int n0 = blockIdx.x * 256;

    // global load mapping: row = tid>>2, chunk = (tid&3)*4 floats
    const int arow  = tid >> 2;          // 0..127
    const int achk  = (tid & 3) * 4;     // 0,4,8,12
    const float* gAh  = Ah + (size_t)(m0 + arow) * K + achk;
    const float* gAl  = Al + (size_t)(m0 + arow) * K + achk;
    const float* gBh0 = Bh + (size_t)(n0 + arow) * K + achk;
    const float* gBl0 = Bl + (size_t)(n0 + arow) * K + achk;
    const float* gBh1 = Bh + (size_t)(n0 + arow + 128) * K + achk;
    const float* gBl1 = Bl + (size_t)(n0 + arow + 128) * K + achk;

    const uint32_t sbase = smem_u32(smem);
    const uint32_t aoff  = (uint32_t)(arow * SROWI + achk) * 4;            // A row, hi
    const uint32_t boff0 = (uint32_t)(arow * SROWI + achk) * 4;            // B rows 0..127
    const uint32_t boff1 = (uint32_t)((arow + 128) * SROWI + achk) * 4;    // B rows 128..255

    // ldmatrix lane addressing (byte offsets, hi half; lo = +LO_OFF)
    const uint32_t aLane = (uint32_t)((warpM * 32 + (lane & 15)) * SROWI + (lane >> 4) * 4) * 4;
    const uint32_t bLane = (uint32_t)((warpN * 64 + ((lane >> 4) & 1) * 8 + (lane & 7)) * SROWI
                                      + ((lane >> 3) & 1) * 4) * 4;

    float acc[2][8][4];
#pragma unroll
    for (int i = 0; i < 2; i++)
#pragma unroll
        for (int j = 0; j < 8; j++)
#pragma unroll
            for (int q = 0; q < 4; q++) acc[i][j][q] = 0.f;

#define PREFETCH(kt_, s_) do { \
        const int _kg = (kt_) * 16; \
        const uint32_t _db = sbase + (uint32_t)(s_) * STAGEB; \
        CP16(_db + ST_A + aoff,           gAh  + _kg); \
        CP16(_db + ST_A + aoff + LO_OFF,  gAl  + _kg); \
        CP16(_db + ST_B + boff0,          gBh0 + _kg); \
        CP16(_db + ST_B + boff0 + LO_OFF, gBl0 + _kg); \
        CP16(_db + ST_B + boff1,          gBh1 + _kg); \
        CP16(_db + ST_B + boff1 + LO_OFF, gBl1 + _kg); \
        CP_COMMIT(); \
    } while (0)

    PREFETCH(0, 0);
    PREFETCH(1, 1);
    PREFETCH(2, 2);

    for (int kt = 0; kt < KT; ++kt) {
        if (kt < KT - 2)      { CP_WAIT(2); }
        else if (kt == KT - 2){ CP_WAIT(1); }
        else                  { CP_WAIT(0); }
        __syncthreads();
        if (kt + 3 < KT) {
            PREFETCH(kt + 3, (kt + 3) & 3);
        }

        const uint32_t stage = sbase + (uint32_t)(kt & 3) * STAGEB;
        const uint32_t aHi = stage + ST_A + aLane;
        const uint32_t bHi = stage + ST_B + bLane;

#pragma unroll
        for (int ks = 0; ks < 2; ks++) {
            const uint32_t ko = ks * 32;   // 8 floats
            uint32_t ah[2][4], al[2][4], bh[4][4], bl[4][4];
#pragma unroll
            for (int ms = 0; ms < 2; ms++) {
                ldsm4(ah[ms], aHi + ms * (16 * SROWI * 4) + ko);
                ldsm4(al[ms], aHi + ms * (16 * SROWI * 4) + ko + LO_OFF);
            }
#pragma unroll
            for (int p = 0; p < 4; p++) {
                ldsm4(bh[p], bHi + p * (16 * SROWI * 4) + ko);
                ldsm4(bl[p], bHi + p * (16 * SROWI * 4) + ko + LO_OFF);
            }
#pragma unroll
            for (int ms = 0; ms < 2; ms++)
#pragma unroll
                for (int p = 0; p < 4; p++) {
                    mma8(acc[ms][2 * p],     ah[ms], &bh[p][0]);
                    mma8(acc[ms][2 * p + 1], ah[ms], &bh[p][2]);
                }
#pragma unroll
            for (int ms = 0; ms < 2; ms++)
#pragma unroll
                for (int p = 0; p < 4; p++) {
                    mma8(acc[ms][2 * p],     ah[ms], &bl[p][0]);
                    mma8(acc[ms][2 * p + 1], ah[ms], &bl[p][2]);
                }
#pragma unroll
            for (int ms = 0; ms < 2; ms++)
#pragma unroll
                for (int p = 0; p < 4; p++) {
                    mma8(acc[ms][2 * p],     al[ms], &bh[p][0]);
                    mma8(acc[ms][2 * p + 1], al[ms], &bh[p][2]);
                }
        }
    }
#undef PREFETCH

    // epilogue: bias + relu (+ optional tf32 split), direct stores
    const int mwb = m0 + warpM * 32;
    const int nwb = n0 + warpN * 64;
#pragma unroll
    for (int ms = 0; ms < 2; ms++) {
        int r0 = mwb + ms * 16 + gr;
        int r1 = r0 + 8;
#pragma unroll
        for (int ns = 0; ns < 8; ns++) {
            int c = nwb + ns * 8 + 2 * tc;
            float bz0 = bias[c], bz1 = bias[c + 1];
            float v0 = fmaxf(acc[ms][ns][0] + bz0, 0.f);
            float v1 = fmaxf(acc[ms][ns][1] + bz1, 0.f);
            float v2 = fmaxf(acc[ms][ns][2] + bz0, 0.f);
            float v3 = fmaxf(acc[ms][ns][3] + bz1, 0.f);
            if (SPLIT_OUT) {
                float h0 = tf32r(v0), h1 = tf32r(v1), h2 = tf32r(v2), h3 = tf32r(v3);
                *(float2*)(Ch + (size_t)r0 * HID + c) = make_float2(h0, h1);
                *(float2*)(Ch + (size_t)r1 * HID + c) = make_float2(h2, h3);
                *(float2*)(Cl + (size_t)r0 * HID + c) =
                    make_float2(tf32r(v0 - h0), tf32r(v1 - h1));
                *(float2*)(Cl + (size_t)r1 * HID + c) =
                    make_float2(tf32r(v2 - h2), tf32r(v3 - h3));
            } else {
                *(float2*)(Ch + (size_t)r0 * HID + c) = make_float2(v0, v1);
                *(float2*)(Ch + (size_t)r1 * HID + c) = make_float2(v2, v3);
            }
        }
    }
}

// ---------------- head: logits = h2 @ w3 + b3, argmax, select ----------------
__global__ __launch_bounds__(256) void head_kernel(
    const float* __restrict__ h2,
    const float* __restrict__ w3,
    const float* __restrict__ b3,
    const int* __restrict__ fixed_mask,
    const int* __restrict__ seq_t,
    float* __restrict__ out_logits,
    float* __restrict__ out_seq0f,
    int* __restrict__ seq0i)
{
    extern __shared__ float w3s[];   // [20][1024]
    const int tid = threadIdx.x;
    const int wid = tid >> 5;
    const int lane = tid & 31;

    for (int i = tid; i < NRES * HID; i += 256) {
        int c = i >> 10;
        int k = i & 1023;
        w3s[i] = w3[k * NRES + c];
    }
    __syncthreads();

    const int rbase = blockIdx.x * 64 + wid * 8;
#pragma unroll
    for (int j = 0; j < 8; j += 2) {
        int ra = rbase + j, rb = ra + 1;
        const float* ha = h2 + (size_t)ra * HID;
        const float* hb = h2 + (size_t)rb * HID;
        float acc0[NRES], acc1[NRES];
#pragma unroll
        for (int c = 0; c < NRES; c++) { acc0[c] = 0.f; acc1[c] = 0.f; }
        for (int it = 0; it < 32; it++) {
            int k = it * 32 + lane;
            float va = ha[k];
            float vb = hb[k];
#pragma unroll
            for (int c = 0; c < NRES; c++) {
                float w = w3s[c * HID + k];
                acc0[c] = fmaf(va, w, acc0[c]);
                acc1[c] = fmaf(vb, w, acc1[c]);
            }
        }
#pragma unroll
        for (int c = 0; c < NRES; c++) {
#pragma unroll
            for (int o = 16; o; o >>= 1) {
                acc0[c] += __shfl_xor_sync(0xffffffffu, acc0[c], o);
                acc1[c] += __shfl_xor_sync(0xffffffffu, acc1[c], o);
            }
        }
        if (lane == 0) {
            int best0 = 0, best1 = 0;
            float bv0 = -INFINITY, bv1 = -INFINITY;
            float* l0 = out_logits + (size_t)ra * NRES;
            float* l1 = out_logits + (size_t)rb * NRES;
#pragma unroll
            for (int c = 0; c < NRES; c++) {
                float v0 = acc0[c] + b3[c];
                float v1 = acc1[c] + b3[c];
                l0[c] = v0; l1[c] = v1;
                if (v0 > bv0) { bv0 = v0; best0 = c; }
                if (v1 > bv1) { bv1 = v1; best1 = c; }
            }
            int s0 = fixed_mask[ra] ? seq_t[ra] : best0;
            int s1 = fixed_mask[rb] ? seq_t[rb] : best1;
            seq0i[ra] = s0; seq0i[rb] = s1;
            out_seq0f[ra] = (float)s0; out_seq0f[rb] = (float)s1;
        }
    }
}

// ---------------- geometry: one thread per residue ----------------
__global__ __launch_bounds__(128) void geom_kernel(
    const float* __restrict__ angles,
    const float* __restrict__ rigids,
    const int* __restrict__ residx,
    const float* __restrict__ default_frames,
    const int* __restrict__ group_idx,
    const float* __restrict__ atom14_mask,
    const float* __restrict__ atom37_mask,
    const float* __restrict__ lit_positions,
    const int* __restrict__ seq0i,
    float* __restrict__ out_pred,
    float* __restrict__ out_final,
    float* __restrict__ out_m14,
    float* __restrict__ out_m37)
{
    int r = blockIdx.x * blockDim.x + threadIdx.x;
    if (r >= RTOT) return;

    float q0 = rigids[r * 7 + 0], q1 = rigids[r * 7 + 1];
    float q2 = rigids[r * 7 + 2], q3 = rigids[r * 7 + 3];
    float tb0 = rigids[r * 7 + 4], tb1 = rigids[r * 7 + 5], tb2 = rigids[r * 7 + 6];
    float inv = rsqrtf(q0 * q0 + q1 * q1 + q2 * q2 + q3 * q3 + 1e-8f);
    float w = q0 * inv, x = q1 * inv, y = q2 * inv, z = q3 * inv;
    float rb[9];
    rb[0] = 1.f - 2.f * (y * y + z * z); rb[1] = 2.f * (x * y - w * z); rb[2] = 2.f * (x * z + w * y);
    rb[3] = 2.f * (x * y + w * z); rb[4] = 1.f - 2.f * (x * x + z * z); rb[5] = 2.f * (y * z - w * x);
    rb[6] = 2.f * (x * z - w * y); rb[7] = 2.f * (y * z + w * x); rb[8] = 1.f - 2.f * (x * x + y * y);

    int s = seq0i[r];

    float G[8][12];
    float chain_r[9], chain_t[3];

    for (int g = 0; g < 8; g++) {
        const float* df = default_frames + ((size_t)s * 8 + g) * 16;
        float dr[9], dt[3];
#pragma unroll
        for (int i = 0; i < 3; i++) {
            dr[i * 3 + 0] = df[i * 4 + 0];
            dr[i * 3 + 1] = df[i * 4 + 1];
            dr[i * 3 + 2] = df[i * 4 + 2];
            dt[i] = df[i * 4 + 3];
        }
        float sn, cs;
        if (g == 0) { sn = 0.f; cs = 1.f; }
        else { sn = angles[r * 14 + (g - 1) * 2 + 0]; cs = angles[r * 14 + (g - 1) * 2 + 1]; }

        float fr[9], ft[3];
#pragma unroll
        for (int i = 0; i < 3; i++) {
            fr[i * 3 + 0] = dr[i * 3 + 0];
            fr[i * 3 + 1] = dr[i * 3 + 1] * cs + dr[i * 3 + 2] * sn;
            fr[i * 3 + 2] = -dr[i * 3 + 1] * sn + dr[i * 3 + 2] * cs;
            ft[i] = dt[i];
        }

        float fo[9], to[3];
        if (g <= 4) {
#pragma unroll
            for (int i = 0; i < 9; i++) fo[i] = fr[i];
#pragma unroll
            for (int i = 0; i < 3; i++) to[i] = ft[i];
            if (g == 4) {
#pragma unroll
                for (int i = 0; i < 9; i++) chain_r[i] = fr[i];
#pragma unroll
                for (int i = 0; i < 3; i++) chain_t[i] = ft[i];
            }
        } else {
            float nr[9], nt[3];
#pragma unroll
            for (int i = 0; i < 3; i++) {
#pragma unroll
                for (int j = 0; j < 3; j++) {
                    nr[i * 3 + j] = chain_r[i * 3 + 0] * fr[0 * 3 + j]
                                  + chain_r[i * 3 + 1] * fr[1 * 3 + j]
                                  + chain_r[i * 3 + 2] * fr[2 * 3 + j];
                }
                nt[i] = chain_r[i * 3 + 0] * ft[0] + chain_r[i * 3 + 1] * ft[1]
                      + chain_r[i * 3 + 2] * ft[2] + chain_t[i];
            }
#pragma unroll
            for (int i = 0; i < 9; i++) { chain_r[i] = nr[i]; fo[i] = nr[i]; }
#pragma unroll
            for (int i = 0; i < 3; i++) { chain_t[i] = nt[i]; to[i] = nt[i]; }
        }

#pragma unroll
        for (int i = 0; i < 3; i++) {
#pragma unroll
            for (int j = 0; j < 3; j++) {
                G[g][i * 3 + j] = rb[i * 3 + 0] * fo[0 * 3 + j]
                                + rb[i * 3 + 1] * fo[1 * 3 + j]
                                + rb[i * 3 + 2] * fo[2 * 3 + j];
            }
        }
        G[g][9]  = rb[0] * to[0] + rb[1] * to[1] + rb[2] * to[2] + tb0;
        G[g][10] = rb[3] * to[0] + rb[4] * to[1] + rb[5] * to[2] + tb1;
        G[g][11] = rb[6] * to[0] + rb[7] * to[1] + rb[8] * to[2] + tb2;
    }

    float pv[14][3];
#pragma unroll
    for (int a = 0; a < 14; a++) {
        int gi = group_idx[s * 14 + a];
        const float* Gp = G[gi];
        float lx = lit_positions[((size_t)s * 14 + a) * 3 + 0];
        float ly = lit_positions[((size_t)s * 14 + a) * 3 + 1];
        float lz = lit_positions[((size_t)s * 14 + a) * 3 + 2];
        float m = atom14_mask[s * 14 + a];
        float px = (Gp[0] * lx + Gp[1] * ly + Gp[2] * lz + Gp[9])  * m;
        float py = (Gp[3] * lx + Gp[4] * ly + Gp[5] * lz + Gp[10]) * m;
        float pz = (Gp[6] * lx + Gp[7] * ly + Gp[8] * lz + Gp[11]) * m;
        pv[a][0] = px; pv[a][1] = py; pv[a][2] = pz;
        size_t po = ((size_t)r * 14 + a) * 3;
        out_pred[po + 0] = px; out_pred[po + 1] = py; out_pred[po + 2] = pz;
        out_m14[(size_t)r * 14 + a] = m;
    }

#pragma unroll
    for (int j = 0; j < 37; j++) {
        int a = residx[(size_t)r * 37 + j];
        size_t fo_ = ((size_t)r * 37 + j) * 3;
        out_final[fo_ + 0] = pv[a][0];
        out_final[fo_ + 1] = pv[a][1];
        out_final[fo_ + 2] = pv[a][2];
        out_m37[(size_t)r * 37 + j] = atom37_mask[s * 37 + j];
    }
}

// ---------------- launcher ----------------
extern "C" void kernel_launch(void* const* d_in, const int* in_sizes, int n_in,
                              void* d_out, int out_size)
{
    const float* act        = (const float*)d_in[0];
    const float* angles     = (const float*)d_in[1];
    const float* rigids     = (const float*)d_in[2];
    const int*   fixed_mask = (const int*)d_in[3];
    const int*   seq_t      = (const int*)d_in[4];
    const int*   residx     = (const int*)d_in[5];
    const float* ln_g       = (const float*)d_in[6];
    const float* ln_b       = (const float*)d_in[7];
    const float* w1         = (const float*)d_in[8];
    const float* b1         = (const float*)d_in[9];
    const float* w2         = (const float*)d_in[10];
    const float* b2         = (const float*)d_in[11];
    const float* w3         = (const float*)d_in[12];
    const float* b3         = (const float*)d_in[13];
    const float* dframes    = (const float*)d_in[14];
    const int*   group_idx  = (const int*)d_in[15];
    const float* a14_mask   = (const float*)d_in[16];
    const float* a37_mask   = (const float*)d_in[17];
    const float* lit        = (const float*)d_in[18];

    float* out = (float*)d_out;
    float* out_logits = out + OFF_LOGITS;
    float* out_seq0   = out + OFF_SEQ0;
    float* out_pred   = out + OFF_PRED;
    float* out_final  = out + OFF_FINAL;
    float* out_m14    = out + OFF_M14;
    float* out_m37    = out + OFF_M37;

    float *xnh, *xnl, *h1h, *h1l, *h2, *wt1h, *wt1l, *wt2h, *wt2l;
    int* seq0i;
    cudaGetSymbolAddress((void**)&xnh, g_xn_hi);
    cudaGetSymbolAddress((void**)&xnl, g_xn_lo);
    cudaGetSymbolAddress((void**)&h1h, g_h1_hi);
    cudaGetSymbolAddress((void**)&h1l, g_h1_lo);
    cudaGetSymbolAddress((void**)&h2,  g_h2);
    cudaGetSymbolAddress((void**)&wt1h, g_wt1_hi);
    cudaGetSymbolAddress((void**)&wt1l, g_wt1_lo);
    cudaGetSymbolAddress((void**)&wt2h, g_wt2_hi);
    cudaGetSymbolAddress((void**)&wt2l, g_wt2_lo);
    cudaGetSymbolAddress((void**)&seq0i, g_seq0i);

    const int GEMM_SMEM = NSTAGE * STAGEB;   // 221184 B -> 1 CTA, 16 warps/SM
    cudaFuncSetAttribute(mma_gemm_kernel<CIN, true>,
                         cudaFuncAttributeMaxDynamicSharedMemorySize, GEMM_SMEM);
    cudaFuncSetAttribute(mma_gemm_kernel<HID, false>,
                         cudaFuncAttributeMaxDynamicSharedMemorySize, GEMM_SMEM);
    cudaFuncSetAttribute(head_kernel,
                         cudaFuncAttributeMaxDynamicSharedMemorySize, NRES * HID * 4);

    // 1. LayerNorm with tf32 split output
    ln_kernel<<<RTOT / 8, 256>>>(act, ln_g, ln_b, xnh, xnl);

    // 2. weight prep: coalesced transpose + tf32 split
    {
        dim3 blk(32, 8);
        dim3 g1(HID / 32, CIN / 32);
        tsplit_kernel<<<g1, blk>>>(w1, wt1h, wt1l, CIN, HID);
        dim3 g2(HID / 32, HID / 32);
        tsplit_kernel<<<g2, blk>>>(w2, wt2h, wt2l, HID, HID);
    }

    // 3. GEMM1: relu(xn @ w1 + b1) -> h1 (split)
    {
        dim3 grid(HID / 256, RTOT / 128);
        mma_gemm_kernel<CIN, true><<<grid, 512, GEMM_SMEM>>>(
            xnh, xnl, wt1h, wt1l, b1, h1h, h1l);
    }
    // 4. GEMM2: relu(h1 @ w2 + b2) -> h2
    {
        dim3 grid(HID / 256, RTOT / 128);
        mma_gemm_kernel<HID, false><<<grid, 512, GEMM_SMEM>>>(
            h1h, h1l, wt2h, wt2l, b2, h2, nullptr);
    }
    // 5. logits + argmax + select
    head_kernel<<<RTOT / 64, 256, NRES * HID * 4>>>(h2, w3, b3, fixed_mask, seq_t,
                                                    out_logits, out_seq0, seq0i);
    // 6. geometry
    geom_kernel<<<RTOT / 128, 128>>>(angles, rigids, residx, dframes, group_idx,
                                     a14_mask, a37_mask, lit, seq0i,
                                     out_pred, out_final, out_m14, out_m37);
}

// round 9
// speedup vs baseline: 2.0950x; 1.4725x over previous
#include <cuda_runtime.h>
#include <cuda_fp16.h>
#include <math.h>
#include <stdint.h>

// ---------------- problem constants ----------------
#define RTOT   32768          // B*N = 32*1024
#define CIN    384
#define HID    1024
#define NRES   20

// output layout (floats)
#define OFF_LOGITS 0
#define OFF_SEQ0   655360
#define OFF_PRED   688128
#define OFF_FINAL  2064384
#define OFF_M14    5701632
#define OFF_M37    6160384

// ---------------- scratch (no cudaMalloc allowed) ----------------
__device__ __align__(256) __half g_xn_hi[(size_t)RTOT * CIN];
__device__ __align__(256) __half g_xn_lo[(size_t)RTOT * CIN];
__device__ __align__(256) __half g_h1_hi[(size_t)RTOT * HID];
__device__ __align__(256) __half g_h1_lo[(size_t)RTOT * HID];
__device__ __align__(256) float  g_h2[(size_t)RTOT * HID];
__device__ __align__(256) __half g_wt1_hi[(size_t)HID * CIN];
__device__ __align__(256) __half g_wt1_lo[(size_t)HID * CIN];
__device__ __align__(256) __half g_wt2_hi[(size_t)HID * HID];
__device__ __align__(256) __half g_wt2_lo[(size_t)HID * HID];
__device__ int g_seq0i[RTOT];

__device__ __forceinline__ void mma16(float c[4], const uint32_t a[4], const uint32_t b[2]) {
    asm volatile("mma.sync.aligned.m16n8k16.row.col.f32.f16.f16.f32 "
        "{%0,%1,%2,%3}, {%4,%5,%6,%7}, {%8,%9}, {%0,%1,%2,%3};"
        : "+f"(c[0]), "+f"(c[1]), "+f"(c[2]), "+f"(c[3])
        : "r"(a[0]), "r"(a[1]), "r"(a[2]), "r"(a[3]), "r"(b[0]), "r"(b[1]));
}

__device__ __forceinline__ void ldsm4(uint32_t r[4], uint32_t addr) {
    asm volatile("ldmatrix.sync.aligned.m8n8.x4.shared.b16 {%0,%1,%2,%3}, [%4];"
        : "=r"(r[0]), "=r"(r[1]), "=r"(r[2]), "=r"(r[3]) : "r"(addr));
}

__device__ __forceinline__ uint32_t smem_u32(const void* p) {
    uint32_t a;
    asm("{ .reg .u64 t; cvta.to.shared.u64 t, %1; cvt.u32.u64 %0, t; }" : "=r"(a) : "l"(p));
    return a;
}

#define CP16(dst, src) \
    asm volatile("cp.async.cg.shared.global [%0], [%1], 16;" :: "r"(dst), "l"(src))
#define CP_COMMIT() asm volatile("cp.async.commit_group;" ::: "memory")
#define CP_WAIT(n)  asm volatile("cp.async.wait_group %0;" :: "n"(n) : "memory")

// ---------------- LayerNorm -> split fp16 hi/lo ----------------
__global__ __launch_bounds__(256) void ln_kernel(
    const float* __restrict__ act,
    const float* __restrict__ gamma,
    const float* __restrict__ beta,
    __half* __restrict__ out_hi,
    __half* __restrict__ out_lo)
{
    int row  = blockIdx.x * 8 + (threadIdx.x >> 5);
    int lane = threadIdx.x & 31;
    const float* x = act + (size_t)row * CIN;

    float v[12];
    float sum = 0.f;
#pragma unroll
    for (int i = 0; i < 12; i++) { v[i] = x[lane + i * 32]; sum += v[i]; }
#pragma unroll
    for (int o = 16; o; o >>= 1) sum += __shfl_xor_sync(0xffffffffu, sum, o);
    float mu = sum * (1.f / CIN);

    float vs = 0.f;
#pragma unroll
    for (int i = 0; i < 12; i++) { float d = v[i] - mu; vs += d * d; }
#pragma unroll
    for (int o = 16; o; o >>= 1) vs += __shfl_xor_sync(0xffffffffu, vs, o);
    float rstd = rsqrtf(vs * (1.f / CIN) + 1e-5f);

    __half* oh = out_hi + (size_t)row * CIN;
    __half* ol = out_lo + (size_t)row * CIN;
#pragma unroll
    for (int i = 0; i < 12; i++) {
        int c = lane + i * 32;
        float y = (v[i] - mu) * rstd * gamma[c] + beta[c];
        __half hi = __float2half_rn(y);
        oh[c] = hi;
        ol[c] = __float2half_rn(y - __half2float(hi));
    }
}

// ---------------- coalesced transpose + fp16 split: W[K,N] -> T[N,K] hi/lo ----------------
__global__ __launch_bounds__(256) void tsplit_kernel(
    const float* __restrict__ W, __half* __restrict__ Th, __half* __restrict__ Tl,
    int Krows, int Ncols)
{
    __shared__ float t[32][33];
    const int tx = threadIdx.x;    // 0..31
    const int ty = threadIdx.y;    // 0..7
    const int n0 = blockIdx.x * 32;
    const int k0 = blockIdx.y * 32;

#pragma unroll
    for (int j = ty; j < 32; j += 8)
        t[j][tx] = W[(size_t)(k0 + j) * Ncols + n0 + tx];
    __syncthreads();

#pragma unroll
    for (int j = ty; j < 32; j += 8) {
        float v = t[tx][j];
        __half hi = __float2half_rn(v);
        size_t o = (size_t)(n0 + j) * Krows + k0 + tx;
        Th[o] = hi;
        Tl[o] = __float2half_rn(v - __half2float(hi));
    }
}

// ---------------- fp16x3 mma.sync m16n8k16 GEMM: 4-stage cp.async + ldmatrix ----------------
// C[M,1024] = relu(A[M,K] @ Bt[1024,K]^T + bias)
// block tile 128(M) x 256(N) x 16(K), 16 warps (4M x 4N), warp tile 32x64
// smem row: [hi 16 halves (32B) | lo 16 halves (32B)] stride 80B
#define SRB    80                       // bytes per smem row
#define A_ARRB (128 * SRB)              // 10240 B
#define B_ARRB (256 * SRB)              // 20480 B
#define ST_A   0
#define ST_B   A_ARRB
#define STAGEB (A_ARRB + B_ARRB)        // 30720 B
#define NSTAGE 4
#define LO_OFF 32                       // byte offset of lo half within a row

template<int K, bool SPLIT_OUT>
__global__ __launch_bounds__(512, 1) void mma_gemm_kernel(
    const __half* __restrict__ Ah, const __half* __restrict__ Al,
    const __half* __restrict__ Bh, const __half* __restrict__ Bl,
    const float* __restrict__ bias,
    float* __restrict__ Cf,
    __half* __restrict__ Ch16, __half* __restrict__ Cl16)
{
    constexpr int KT = K / 16;
    extern __shared__ char smem[];

    const int tid   = threadIdx.x;
    const int wid   = tid >> 5;
    const int lane  = tid & 31;
    const int warpM = wid & 3;          // 0..3
    const int warpN = wid >> 2;         // 0..3
    const int gr    = lane >> 2;
    const int tc    = lane & 3;

    const int m0 = blockIdx.y * 128;
    const int n0 = blockIdx.x * 256;

    // global load mapping: row = tid>>2, part = tid&3
    // part 0: hi k0-7, part 1: hi k8-15, part 2: lo k0-7, part 3: lo k8-15
    const int row  = tid >> 2;
    const int part = tid & 3;
    const int koffA = (part & 1) * 8;    // halves
    const __half* gA  = ((part < 2) ? Ah : Al) + (size_t)(m0 + row) * K + koffA;
    const __half* gB0 = ((part < 2) ? Bh : Bl) + (size_t)(n0 + row) * K + koffA;
    const __half* gB1 = ((part < 2) ? Bh : Bl) + (size_t)(n0 + row + 128) * K + koffA;

    const uint32_t sbase = smem_u32(smem);
    const uint32_t dpart = (uint32_t)((part >> 1) * 32 + (part & 1) * 16);
    const uint32_t dstA  = (uint32_t)(row * SRB) + dpart;
    const uint32_t dstB0 = (uint32_t)(row * SRB) + dpart;
    const uint32_t dstB1 = (uint32_t)((row + 128) * SRB) + dpart;

    // ldmatrix lane addressing (byte offsets within arrays, hi half; lo = +LO_OFF)
    // A (16x16): lanes0-15 rows 0-15 (k0-7), lanes16-31 rows 0-15 (k8-15)
    const uint32_t aLane = (uint32_t)((warpM * 32 + (lane & 15)) * SRB + (lane >> 4) * 16);
    // B ([n8 x k16] x2): lanes0-7 n0-7 k0-7, 8-15 n0-7 k8-15, 16-23 n8-15 k0-7, 24-31 n8-15 k8-15
    const uint32_t bLane = (uint32_t)((warpN * 64 + (lane & 7) + ((lane >> 4) & 1) * 8) * SRB
                                      + ((lane >> 3) & 1) * 16);

    float acc[2][8][4];
#pragma unroll
    for (int i = 0; i < 2; i++)
#pragma unroll
        for (int j = 0; j < 8; j++)
#pragma unroll
            for (int q = 0; q < 4; q++) acc[i][j][q] = 0.f;

#define PREFETCH(kt_, s_) do { \
        const int _kg = (kt_) * 16; \
        const uint32_t _db = sbase + (uint32_t)(s_) * STAGEB; \
        CP16(_db + ST_A + dstA,  gA  + _kg); \
        CP16(_db + ST_B + dstB0, gB0 + _kg); \
        CP16(_db + ST_B + dstB1, gB1 + _kg); \
        CP_COMMIT(); \
    } while (0)

    PREFETCH(0, 0);
    PREFETCH(1, 1);
    PREFETCH(2, 2);

    for (int kt = 0; kt < KT; ++kt) {
        if (kt < KT - 2)       { CP_WAIT(2); }
        else if (kt == KT - 2) { CP_WAIT(1); }
        else                   { CP_WAIT(0); }
        __syncthreads();
        if (kt + 3 < KT) {
            PREFETCH(kt + 3, (kt + 3) & 3);
        }

        const uint32_t stage = sbase + (uint32_t)(kt & 3) * STAGEB;
        const uint32_t aHi = stage + ST_A + aLane;
        const uint32_t bHi = stage + ST_B + bLane;

        uint32_t ah[2][4], al[2][4], bh[4][4], bl[4][4];
#pragma unroll
        for (int ms = 0; ms < 2; ms++) {
            ldsm4(ah[ms], aHi + ms * (16 * SRB));
            ldsm4(al[ms], aHi + ms * (16 * SRB) + LO_OFF);
        }
#pragma unroll
        for (int p = 0; p < 4; p++) {
            ldsm4(bh[p], bHi + p * (16 * SRB));
            ldsm4(bl[p], bHi + p * (16 * SRB) + LO_OFF);
        }
        // pass 1: hi*hi
#pragma unroll
        for (int ms = 0; ms < 2; ms++)
#pragma unroll
            for (int p = 0; p < 4; p++) {
                mma16(acc[ms][2 * p],     ah[ms], &bh[p][0]);
                mma16(acc[ms][2 * p + 1], ah[ms], &bh[p][2]);
            }
        // pass 2: hi*lo
#pragma unroll
        for (int ms = 0; ms < 2; ms++)
#pragma unroll
            for (int p = 0; p < 4; p++) {
                mma16(acc[ms][2 * p],     ah[ms], &bl[p][0]);
                mma16(acc[ms][2 * p + 1], ah[ms], &bl[p][2]);
            }
        // pass 3: lo*hi
#pragma unroll
        for (int ms = 0; ms < 2; ms++)
#pragma unroll
            for (int p = 0; p < 4; p++) {
                mma16(acc[ms][2 * p],     al[ms], &bh[p][0]);
                mma16(acc[ms][2 * p + 1], al[ms], &bh[p][2]);
            }
    }
#undef PREFETCH

    // epilogue: bias + relu; fp32 out or fp16 hi/lo split out
    const int mwb = m0 + warpM * 32;
    const int nwb = n0 + warpN * 64;
#pragma unroll
    for (int ms = 0; ms < 2; ms++) {
        int r0 = mwb + ms * 16 + gr;
        int r1 = r0 + 8;
#pragma unroll
        for (int ns = 0; ns < 8; ns++) {
            int c = nwb + ns * 8 + 2 * tc;
            float bz0 = bias[c], bz1 = bias[c + 1];
            float v0 = fmaxf(acc[ms][ns][0] + bz0, 0.f);
            float v1 = fmaxf(acc[ms][ns][1] + bz1, 0.f);
            float v2 = fmaxf(acc[ms][ns][2] + bz0, 0.f);
            float v3 = fmaxf(acc[ms][ns][3] + bz1, 0.f);
            if (SPLIT_OUT) {
                __half h0 = __float2half_rn(v0), h1 = __float2half_rn(v1);
                __half h2 = __float2half_rn(v2), h3 = __float2half_rn(v3);
                __half l0 = __float2half_rn(v0 - __half2float(h0));
                __half l1 = __float2half_rn(v1 - __half2float(h1));
                __half l2 = __float2half_rn(v2 - __half2float(h2));
                __half l3 = __float2half_rn(v3 - __half2float(h3));
                *(__half2*)(Ch16 + (size_t)r0 * HID + c) = __halves2half2(h0, h1);
                *(__half2*)(Ch16 + (size_t)r1 * HID + c) = __halves2half2(h2, h3);
                *(__half2*)(Cl16 + (size_t)r0 * HID + c) = __halves2half2(l0, l1);
                *(__half2*)(Cl16 + (size_t)r1 * HID + c) = __halves2half2(l2, l3);
            } else {
                *(float2*)(Cf + (size_t)r0 * HID + c) = make_float2(v0, v1);
                *(float2*)(Cf + (size_t)r1 * HID + c) = make_float2(v2, v3);
            }
        }
    }
}

// ---------------- head: logits = h2 @ w3 + b3, argmax, select ----------------
__global__ __launch_bounds__(256) void head_kernel(
    const float* __restrict__ h2,
    const float* __restrict__ w3,
    const float* __restrict__ b3,
    const int* __restrict__ fixed_mask,
    const int* __restrict__ seq_t,
    float* __restrict__ out_logits,
    float* __restrict__ out_seq0f,
    int* __restrict__ seq0i)
{
    extern __shared__ float w3s[];   // [20][1024]
    const int tid = threadIdx.x;
    const int wid = tid >> 5;
    const int lane = tid & 31;

    for (int i = tid; i < NRES * HID; i += 256) {
        int c = i >> 10;
        int k = i & 1023;
        w3s[i] = w3[k * NRES + c];
    }
    __syncthreads();

    const int rbase = blockIdx.x * 64 + wid * 8;
#pragma unroll
    for (int j = 0; j < 8; j += 2) {
        int ra = rbase + j, rb = ra + 1;
        const float* ha = h2 + (size_t)ra * HID;
        const float* hb = h2 + (size_t)rb * HID;
        float acc0[NRES], acc1[NRES];
#pragma unroll
        for (int c = 0; c < NRES; c++) { acc0[c] = 0.f; acc1[c] = 0.f; }
        for (int it = 0; it < 32; it++) {
            int k = it * 32 + lane;
            float va = ha[k];
            float vb = hb[k];
#pragma unroll
            for (int c = 0; c < NRES; c++) {
                float w = w3s[c * HID + k];
                acc0[c] = fmaf(va, w, acc0[c]);
                acc1[c] = fmaf(vb, w, acc1[c]);
            }
        }
#pragma unroll
        for (int c = 0; c < NRES; c++) {
#pragma unroll
            for (int o = 16; o; o >>= 1) {
                acc0[c] += __shfl_xor_sync(0xffffffffu, acc0[c], o);
                acc1[c] += __shfl_xor_sync(0xffffffffu, acc1[c], o);
            }
        }
        if (lane == 0) {
            int best0 = 0, best1 = 0;
            float bv0 = -INFINITY, bv1 = -INFINITY;
            float* l0 = out_logits + (size_t)ra * NRES;
            float* l1 = out_logits + (size_t)rb * NRES;
#pragma unroll
            for (int c = 0; c < NRES; c++) {
                float v0 = acc0[c] + b3[c];
                float v1 = acc1[c] + b3[c];
                l0[c] = v0; l1[c] = v1;
                if (v0 > bv0) { bv0 = v0; best0 = c; }
                if (v1 > bv1) { bv1 = v1; best1 = c; }
            }
            int s0 = fixed_mask[ra] ? seq_t[ra] : best0;
            int s1 = fixed_mask[rb] ? seq_t[rb] : best1;
            seq0i[ra] = s0; seq0i[rb] = s1;
            out_seq0f[ra] = (float)s0; out_seq0f[rb] = (float)s1;
        }
    }
}

// ---------------- geometry: one thread per residue ----------------
__global__ __launch_bounds__(128) void geom_kernel(
    const float* __restrict__ angles,
    const float* __restrict__ rigids,
    const int* __restrict__ residx,
    const float* __restrict__ default_frames,
    const int* __restrict__ group_idx,
    const float* __restrict__ atom14_mask,
    const float* __restrict__ atom37_mask,
    const float* __restrict__ lit_positions,
    const int* __restrict__ seq0i,
    float* __restrict__ out_pred,
    float* __restrict__ out_final,
    float* __restrict__ out_m14,
    float* __restrict__ out_m37)
{
    int r = blockIdx.x * blockDim.x + threadIdx.x;
    if (r >= RTOT) return;

    float q0 = rigids[r * 7 + 0], q1 = rigids[r * 7 + 1];
    float q2 = rigids[r * 7 + 2], q3 = rigids[r * 7 + 3];
    float tb0 = rigids[r * 7 + 4], tb1 = rigids[r * 7 + 5], tb2 = rigids[r * 7 + 6];
    float inv = rsqrtf(q0 * q0 + q1 * q1 + q2 * q2 + q3 * q3 + 1e-8f);
    float w = q0 * inv, x = q1 * inv, y = q2 * inv, z = q3 * inv;
    float rb[9];
    rb[0] = 1.f - 2.f * (y * y + z * z); rb[1] = 2.f * (x * y - w * z); rb[2] = 2.f * (x * z + w * y);
    rb[3] = 2.f * (x * y + w * z); rb[4] = 1.f - 2.f * (x * x + z * z); rb[5] = 2.f * (y * z - w * x);
    rb[6] = 2.f * (x * z - w * y); rb[7] = 2.f * (y * z + w * x); rb[8] = 1.f - 2.f * (x * x + y * y);

    int s = seq0i[r];

    float G[8][12];
    float chain_r[9], chain_t[3];

    for (int g = 0; g < 8; g++) {
        const float* df = default_frames + ((size_t)s * 8 + g) * 16;
        float dr[9], dt[3];
#pragma unroll
        for (int i = 0; i < 3; i++) {
            dr[i * 3 + 0] = df[i * 4 + 0];
            dr[i * 3 + 1] = df[i * 4 + 1];
            dr[i * 3 + 2] = df[i * 4 + 2];
            dt[i] = df[i * 4 + 3];
        }
        float sn, cs;
        if (g == 0) { sn = 0.f; cs = 1.f; }
        else { sn = angles[r * 14 + (g - 1) * 2 + 0]; cs = angles[r * 14 + (g - 1) * 2 + 1]; }

        float fr[9], ft[3];
#pragma unroll
        for (int i = 0; i < 3; i++) {
            fr[i * 3 + 0] = dr[i * 3 + 0];
            fr[i * 3 + 1] = dr[i * 3 + 1] * cs + dr[i * 3 + 2] * sn;
            fr[i * 3 + 2] = -dr[i * 3 + 1] * sn + dr[i * 3 + 2] * cs;
            ft[i] = dt[i];
        }

        float fo[9], to[3];
        if (g <= 4) {
#pragma unroll
            for (int i = 0; i < 9; i++) fo[i] = fr[i];
#pragma unroll
            for (int i = 0; i < 3; i++) to[i] = ft[i];
            if (g == 4) {
#pragma unroll
                for (int i = 0; i < 9; i++) chain_r[i] = fr[i];
#pragma unroll
                for (int i = 0; i < 3; i++) chain_t[i] = ft[i];
            }
        } else {
            float nr[9], nt[3];
#pragma unroll
            for (int i = 0; i < 3; i++) {
#pragma unroll
                for (int j = 0; j < 3; j++) {
                    nr[i * 3 + j] = chain_r[i * 3 + 0] * fr[0 * 3 + j]
                                  + chain_r[i * 3 + 1] * fr[1 * 3 + j]
                                  + chain_r[i * 3 + 2] * fr[2 * 3 + j];
                }
                nt[i] = chain_r[i * 3 + 0] * ft[0] + chain_r[i * 3 + 1] * ft[1]
                      + chain_r[i * 3 + 2] * ft[2] + chain_t[i];
            }
#pragma unroll
            for (int i = 0; i < 9; i++) { chain_r[i] = nr[i]; fo[i] = nr[i]; }
#pragma unroll
            for (int i = 0; i < 3; i++) { chain_t[i] = nt[i]; to[i] = nt[i]; }
        }

#pragma unroll
        for (int i = 0; i < 3; i++) {
#pragma unroll
            for (int j = 0; j < 3; j++) {
                G[g][i * 3 + j] = rb[i * 3 + 0] * fo[0 * 3 + j]
                                + rb[i * 3 + 1] * fo[1 * 3 + j]
                                + rb[i * 3 + 2] * fo[2 * 3 + j];
            }
        }
        G[g][9]  = rb[0] * to[0] + rb[1] * to[1] + rb[2] * to[2] + tb0;
        G[g][10] = rb[3] * to[0] + rb[4] * to[1] + rb[5] * to[2] + tb1;
        G[g][11] = rb[6] * to[0] + rb[7] * to[1] + rb[8] * to[2] + tb2;
    }

    float pv[14][3];
#pragma unroll
    for (int a = 0; a < 14; a++) {
        int gi = group_idx[s * 14 + a];
        const float* Gp = G[gi];
        float lx = lit_positions[((size_t)s * 14 + a) * 3 + 0];
        float ly = lit_positions[((size_t)s * 14 + a) * 3 + 1];
        float lz = lit_positions[((size_t)s * 14 + a) * 3 + 2];
        float m = atom14_mask[s * 14 + a];
        float px = (Gp[0] * lx + Gp[1] * ly + Gp[2] * lz + Gp[9])  * m;
        float py = (Gp[3] * lx + Gp[4] * ly + Gp[5] * lz + Gp[10]) * m;
        float pz = (Gp[6] * lx + Gp[7] * ly + Gp[8] * lz + Gp[11]) * m;
        pv[a][0] = px; pv[a][1] = py; pv[a][2] = pz;
        size_t po = ((size_t)r * 14 + a) * 3;
        out_pred[po + 0] = px; out_pred[po + 1] = py; out_pred[po + 2] = pz;
        out_m14[(size_t)r * 14 + a] = m;
    }

#pragma unroll
    for (int j = 0; j < 37; j++) {
        int a = residx[(size_t)r * 37 + j];
        size_t fo_ = ((size_t)r * 37 + j) * 3;
        out_final[fo_ + 0] = pv[a][0];
        out_final[fo_ + 1] = pv[a][1];
        out_final[fo_ + 2] = pv[a][2];
        out_m37[(size_t)r * 37 + j] = atom37_mask[s * 37 + j];
    }
}

// ---------------- launcher ----------------
extern "C" void kernel_launch(void* const* d_in, const int* in_sizes, int n_in,
                              void* d_out, int out_size)
{
    const float* act        = (const float*)d_in[0];
    const float* angles     = (const float*)d_in[1];
    const float* rigids     = (const float*)d_in[2];
    const int*   fixed_mask = (const int*)d_in[3];
    const int*   seq_t      = (const int*)d_in[4];
    const int*   residx     = (const int*)d_in[5];
    const float* ln_g       = (const float*)d_in[6];
    const float* ln_b       = (const float*)d_in[7];
    const float* w1         = (const float*)d_in[8];
    const float* b1         = (const float*)d_in[9];
    const float* w2         = (const float*)d_in[10];
    const float* b2         = (const float*)d_in[11];
    const float* w3         = (const float*)d_in[12];
    const float* b3         = (const float*)d_in[13];
    const float* dframes    = (const float*)d_in[14];
    const int*   group_idx  = (const int*)d_in[15];
    const float* a14_mask   = (const float*)d_in[16];
    const float* a37_mask   = (const float*)d_in[17];
    const float* lit        = (const float*)d_in[18];

    float* out = (float*)d_out;
    float* out_logits = out + OFF_LOGITS;
    float* out_seq0   = out + OFF_SEQ0;
    float* out_pred   = out + OFF_PRED;
    float* out_final  = out + OFF_FINAL;
    float* out_m14    = out + OFF_M14;
    float* out_m37    = out + OFF_M37;

    __half *xnh, *xnl, *h1h, *h1l, *wt1h, *wt1l, *wt2h, *wt2l;
    float *h2;
    int* seq0i;
    cudaGetSymbolAddress((void**)&xnh, g_xn_hi);
    cudaGetSymbolAddress((void**)&xnl, g_xn_lo);
    cudaGetSymbolAddress((void**)&h1h, g_h1_hi);
    cudaGetSymbolAddress((void**)&h1l, g_h1_lo);
    cudaGetSymbolAddress((void**)&h2,  g_h2);
    cudaGetSymbolAddress((void**)&wt1h, g_wt1_hi);
    cudaGetSymbolAddress((void**)&wt1l, g_wt1_lo);
    cudaGetSymbolAddress((void**)&wt2h, g_wt2_hi);
    cudaGetSymbolAddress((void**)&wt2l, g_wt2_lo);
    cudaGetSymbolAddress((void**)&seq0i, g_seq0i);

    const int GEMM_SMEM = NSTAGE * STAGEB;   // 122880 B -> 1 CTA, 16 warps/SM
    cudaFuncSetAttribute(mma_gemm_kernel<CIN, true>,
                         cudaFuncAttributeMaxDynamicSharedMemorySize, GEMM_SMEM);
    cudaFuncSetAttribute(mma_gemm_kernel<HID, false>,
                         cudaFuncAttributeMaxDynamicSharedMemorySize, GEMM_SMEM);
    cudaFuncSetAttribute(head_kernel,
                         cudaFuncAttributeMaxDynamicSharedMemorySize, NRES * HID * 4);

    // 1. LayerNorm with fp16 split output
    ln_kernel<<<RTOT / 8, 256>>>(act, ln_g, ln_b, xnh, xnl);

    // 2. weight prep: coalesced transpose + fp16 split
    {
        dim3 blk(32, 8);
        dim3 g1(HID / 32, CIN / 32);
        tsplit_kernel<<<g1, blk>>>(w1, wt1h, wt1l, CIN, HID);
        dim3 g2(HID / 32, HID / 32);
        tsplit_kernel<<<g2, blk>>>(w2, wt2h, wt2l, HID, HID);
    }

    // 3. GEMM1: relu(xn @ w1 + b1) -> h1 (fp16 split)
    {
        dim3 grid(HID / 256, RTOT / 128);
        mma_gemm_kernel<CIN, true><<<grid, 512, GEMM_SMEM>>>(
            xnh, xnl, wt1h, wt1l, b1, nullptr, h1h, h1l);
    }
    // 4. GEMM2: relu(h1 @ w2 + b2) -> h2 (fp32)
    {
        dim3 grid(HID / 256, RTOT / 128);
        mma_gemm_kernel<HID, false><<<grid, 512, GEMM_SMEM>>>(
            h1h, h1l, wt2h, wt2l, b2, h2, nullptr, nullptr);
    }
    // 5. logits + argmax + select
    head_kernel<<<RTOT / 64, 256, NRES * HID * 4>>>(h2, w3, b3, fixed_mask, seq_t,
                                                    out_logits, out_seq0, seq0i);
    // 6. geometry
    geom_kernel<<<RTOT / 128, 128>>>(angles, rigids, residx, dframes, group_idx,
                                     a14_mask, a37_mask, lit, seq0i,
                                     out_pred, out_final, out_m14, out_m37);
}

// round 10
// speedup vs baseline: 2.1385x; 1.0208x over previous
#include <cuda_runtime.h>
#include <cuda_fp16.h>
#include <math.h>
#include <stdint.h>

// ---------------- problem constants ----------------
#define RTOT   32768          // B*N = 32*1024
#define CIN    384
#define HID    1024
#define NRES   20

// output layout (floats)
#define OFF_LOGITS 0
#define OFF_SEQ0   655360
#define OFF_PRED   688128
#define OFF_FINAL  2064384
#define OFF_M14    5701632
#define OFF_M37    6160384

// ---------------- scratch (no cudaMalloc allowed) ----------------
__device__ __align__(256) __half g_xn_hi[(size_t)RTOT * CIN];
__device__ __align__(256) __half g_xn_lo[(size_t)RTOT * CIN];
__device__ __align__(256) __half g_h1_hi[(size_t)RTOT * HID];
__device__ __align__(256) __half g_h1_lo[(size_t)RTOT * HID];
__device__ __align__(256) float  g_h2[(size_t)RTOT * HID];
__device__ __align__(256) __half g_wt1_hi[(size_t)HID * CIN];
__device__ __align__(256) __half g_wt1_lo[(size_t)HID * CIN];
__device__ __align__(256) __half g_wt2_hi[(size_t)HID * HID];
__device__ __align__(256) __half g_wt2_lo[(size_t)HID * HID];
__device__ int g_seq0i[RTOT];

__device__ __forceinline__ void mma16(float c[4], const uint32_t a[4], const uint32_t b[2]) {
    asm volatile("mma.sync.aligned.m16n8k16.row.col.f32.f16.f16.f32 "
        "{%0,%1,%2,%3}, {%4,%5,%6,%7}, {%8,%9}, {%0,%1,%2,%3};"
        : "+f"(c[0]), "+f"(c[1]), "+f"(c[2]), "+f"(c[3])
        : "r"(a[0]), "r"(a[1]), "r"(a[2]), "r"(a[3]), "r"(b[0]), "r"(b[1]));
}

__device__ __forceinline__ void ldsm4(uint32_t r[4], uint32_t addr) {
    asm volatile("ldmatrix.sync.aligned.m8n8.x4.shared.b16 {%0,%1,%2,%3}, [%4];"
        : "=r"(r[0]), "=r"(r[1]), "=r"(r[2]), "=r"(r[3]) : "r"(addr));
}

__device__ __forceinline__ uint32_t smem_u32(const void* p) {
    uint32_t a;
    asm("{ .reg .u64 t; cvta.to.shared.u64 t, %1; cvt.u32.u64 %0, t; }" : "=r"(a) : "l"(p));
    return a;
}

#define CP16(dst, src) \
    asm volatile("cp.async.cg.shared.global [%0], [%1], 16;" :: "r"(dst), "l"(src))
#define CP_COMMIT() asm volatile("cp.async.commit_group;" ::: "memory")
#define CP_WAIT(n)  asm volatile("cp.async.wait_group %0;" :: "n"(n) : "memory")

// ---------------- LayerNorm -> split fp16 hi/lo ----------------
__global__ __launch_bounds__(256) void ln_kernel(
    const float* __restrict__ act,
    const float* __restrict__ gamma,
    const float* __restrict__ beta,
    __half* __restrict__ out_hi,
    __half* __restrict__ out_lo)
{
    int row  = blockIdx.x * 8 + (threadIdx.x >> 5);
    int lane = threadIdx.x & 31;
    const float* x = act + (size_t)row * CIN;

    float v[12];
    float sum = 0.f;
#pragma unroll
    for (int i = 0; i < 12; i++) { v[i] = x[lane + i * 32]; sum += v[i]; }
#pragma unroll
    for (int o = 16; o; o >>= 1) sum += __shfl_xor_sync(0xffffffffu, sum, o);
    float mu = sum * (1.f / CIN);

    float vs = 0.f;
#pragma unroll
    for (int i = 0; i < 12; i++) { float d = v[i] - mu; vs += d * d; }
#pragma unroll
    for (int o = 16; o; o >>= 1) vs += __shfl_xor_sync(0xffffffffu, vs, o);
    float rstd = rsqrtf(vs * (1.f / CIN) + 1e-5f);

    __half* oh = out_hi + (size_t)row * CIN;
    __half* ol = out_lo + (size_t)row * CIN;
#pragma unroll
    for (int i = 0; i < 12; i++) {
        int c = lane + i * 32;
        float y = (v[i] - mu) * rstd * gamma[c] + beta[c];
        __half hi = __float2half_rn(y);
        oh[c] = hi;
        ol[c] = __float2half_rn(y - __half2float(hi));
    }
}

// ---------------- coalesced transpose + fp16 split: W[K,N] -> T[N,K] hi/lo ----------------
__global__ __launch_bounds__(256) void tsplit_kernel(
    const float* __restrict__ W, __half* __restrict__ Th, __half* __restrict__ Tl,
    int Krows, int Ncols)
{
    __shared__ float t[32][33];
    const int tx = threadIdx.x;    // 0..31
    const int ty = threadIdx.y;    // 0..7
    const int n0 = blockIdx.x * 32;
    const int k0 = blockIdx.y * 32;

#pragma unroll
    for (int j = ty; j < 32; j += 8)
        t[j][tx] = W[(size_t)(k0 + j) * Ncols + n0 + tx];
    __syncthreads();

#pragma unroll
    for (int j = ty; j < 32; j += 8) {
        float v = t[tx][j];
        __half hi = __float2half_rn(v);
        size_t o = (size_t)(n0 + j) * Krows + k0 + tx;
        Th[o] = hi;
        Tl[o] = __float2half_rn(v - __half2float(hi));
    }
}

// ---------------- fp16x3 mma.sync m16n8k16 GEMM: 3-stage cp.async, k-tile 32 ----------------
// C[M,1024] = relu(A[M,K] @ Bt[1024,K]^T + bias)
// block tile 128(M) x 256(N) x 32(K), 16 warps (4M x 4N), warp tile 32x64
// smem row (176B stride, 128B used):
//   [hi k0-7 |hi k8-15 |lo k0-7 |lo k8-15 |hi k16-23|hi k24-31|lo k16-23|lo k24-31]
//    +0       +16       +32      +48       +64       +80       +96       +112
// stride 176B = 11 x 16B -> 8-row ldmatrix phases {0,3,6,1,4,7,2,5}: conflict-free
#define SRB    176                      // bytes per smem row
#define A_ARRB (128 * SRB)              // 22528 B
#define B_ARRB (256 * SRB)              // 45056 B
#define ST_A   0
#define ST_B   A_ARRB
#define STAGEB (A_ARRB + B_ARRB)        // 67584 B
#define NSTAGE 3
#define LO_OFF 32                       // byte offset of lo half within a k16 slab

template<int K, bool SPLIT_OUT>
__global__ __launch_bounds__(512, 1) void mma_gemm_kernel(
    const __half* __restrict__ Ah, const __half* __restrict__ Al,
    const __half* __restrict__ Bh, const __half* __restrict__ Bl,
    const float* __restrict__ bias,
    float* __restrict__ Cf,
    __half* __restrict__ Ch16, __half* __restrict__ Cl16)
{
    constexpr int KT = K / 32;
    extern __shared__ char smem[];

    const int tid   = threadIdx.x;
    const int wid   = tid >> 5;
    const int lane  = tid & 31;
    const int warpM = wid & 3;          // 0..3
    const int warpN = wid >> 2;         // 0..3
    const int gr    = lane >> 2;
    const int tc    = lane & 3;

    const int m0 = blockIdx.y * 128;
    const int n0 = blockIdx.x * 256;

    // global load mapping: row = tid>>2, sub-part = tid&3
    //   hl  = hi/lo array select, seg = k sub-8 within a k16 slab
    // each thread covers both k16 slabs (j=0 at +0, j=1 at +64 / gsrc +16)
    const int row = tid >> 2;
    const int p0  = tid & 3;
    const int hl  = (p0 >> 1) & 1;
    const int seg = p0 & 1;
    const __half* gA  = (hl ? Al : Ah) + (size_t)(m0 + row) * K + seg * 8;
    const __half* gB0 = (hl ? Bl : Bh) + (size_t)(n0 + row) * K + seg * 8;
    const __half* gB1 = (hl ? Bl : Bh) + (size_t)(n0 + row + 128) * K + seg * 8;

    const uint32_t sbase = smem_u32(smem);
    const uint32_t dpart = (uint32_t)(hl * 32 + seg * 16);
    const uint32_t dstA  = (uint32_t)(row * SRB) + dpart;
    const uint32_t dstB0 = (uint32_t)(row * SRB) + dpart;
    const uint32_t dstB1 = (uint32_t)((row + 128) * SRB) + dpart;

    // ldmatrix lane addressing (byte offsets, hi of slab 0; slab j = +j*64, lo = +LO_OFF)
    const uint32_t aLane = (uint32_t)((warpM * 32 + (lane & 15)) * SRB + (lane >> 4) * 16);
    const uint32_t bLane = (uint32_t)((warpN * 64 + (lane & 7) + ((lane >> 4) & 1) * 8) * SRB
                                      + ((lane >> 3) & 1) * 16);

    float acc[2][8][4];
#pragma unroll
    for (int i = 0; i < 2; i++)
#pragma unroll
        for (int j = 0; j < 8; j++)
#pragma unroll
            for (int q = 0; q < 4; q++) acc[i][j][q] = 0.f;

#define PREFETCH(kt_, s_) do { \
        const int _kg = (kt_) * 32; \
        const uint32_t _db = sbase + (uint32_t)(s_) * STAGEB; \
        CP16(_db + ST_A + dstA,       gA  + _kg); \
        CP16(_db + ST_A + dstA + 64,  gA  + _kg + 16); \
        CP16(_db + ST_B + dstB0,      gB0 + _kg); \
        CP16(_db + ST_B + dstB0 + 64, gB0 + _kg + 16); \
        CP16(_db + ST_B + dstB1,      gB1 + _kg); \
        CP16(_db + ST_B + dstB1 + 64, gB1 + _kg + 16); \
        CP_COMMIT(); \
    } while (0)

    PREFETCH(0, 0);
    PREFETCH(1, 1);

    int s_cur = 0;    // stage of kt
    int s_pf  = 2;    // stage of kt+2
    for (int kt = 0; kt < KT; ++kt) {
        if (kt < KT - 1) { CP_WAIT(1); }
        else             { CP_WAIT(0); }
        __syncthreads();
        if (kt + 2 < KT) {
            PREFETCH(kt + 2, s_pf);
        }

        const uint32_t stage = sbase + (uint32_t)s_cur * STAGEB;

#pragma unroll
        for (int j = 0; j < 2; j++) {
            const uint32_t aHi = stage + ST_A + aLane + j * 64;
            const uint32_t bHi = stage + ST_B + bLane + j * 64;

            uint32_t ah[2][4], al[2][4], bh[4][4], bl[4][4];
#pragma unroll
            for (int ms = 0; ms < 2; ms++) {
                ldsm4(ah[ms], aHi + ms * (16 * SRB));
                ldsm4(al[ms], aHi + ms * (16 * SRB) + LO_OFF);
            }
#pragma unroll
            for (int p = 0; p < 4; p++) {
                ldsm4(bh[p], bHi + p * (16 * SRB));
                ldsm4(bl[p], bHi + p * (16 * SRB) + LO_OFF);
            }
            // pass 1: hi*hi
#pragma unroll
            for (int ms = 0; ms < 2; ms++)
#pragma unroll
                for (int p = 0; p < 4; p++) {
                    mma16(acc[ms][2 * p],     ah[ms], &bh[p][0]);
                    mma16(acc[ms][2 * p + 1], ah[ms], &bh[p][2]);
                }
            // pass 2: hi*lo
#pragma unroll
            for (int ms = 0; ms < 2; ms++)
#pragma unroll
                for (int p = 0; p < 4; p++) {
                    mma16(acc[ms][2 * p],     ah[ms], &bl[p][0]);
                    mma16(acc[ms][2 * p + 1], ah[ms], &bl[p][2]);
                }
            // pass 3: lo*hi
#pragma unroll
            for (int ms = 0; ms < 2; ms++)
#pragma unroll
                for (int p = 0; p < 4; p++) {
                    mma16(acc[ms][2 * p],     al[ms], &bh[p][0]);
                    mma16(acc[ms][2 * p + 1], al[ms], &bh[p][2]);
                }
        }
        s_cur = (s_cur == 2) ? 0 : s_cur + 1;
        s_pf  = (s_pf == 2) ? 0 : s_pf + 1;
    }
#undef PREFETCH

    // epilogue: bias + relu; fp32 out or fp16 hi/lo split out
    const int mwb = m0 + warpM * 32;
    const int nwb = n0 + warpN * 64;
#pragma unroll
    for (int ms = 0; ms < 2; ms++) {
        int r0 = mwb + ms * 16 + gr;
        int r1 = r0 + 8;
#pragma unroll
        for (int ns = 0; ns < 8; ns++) {
            int c = nwb + ns * 8 + 2 * tc;
            float bz0 = bias[c], bz1 = bias[c + 1];
            float v0 = fmaxf(acc[ms][ns][0] + bz0, 0.f);
            float v1 = fmaxf(acc[ms][ns][1] + bz1, 0.f);
            float v2 = fmaxf(acc[ms][ns][2] + bz0, 0.f);
            float v3 = fmaxf(acc[ms][ns][3] + bz1, 0.f);
            if (SPLIT_OUT) {
                __half h0 = __float2half_rn(v0), h1 = __float2half_rn(v1);
                __half h2 = __float2half_rn(v2), h3 = __float2half_rn(v3);
                __half l0 = __float2half_rn(v0 - __half2float(h0));
                __half l1 = __float2half_rn(v1 - __half2float(h1));
                __half l2 = __float2half_rn(v2 - __half2float(h2));
                __half l3 = __float2half_rn(v3 - __half2float(h3));
                *(__half2*)(Ch16 + (size_t)r0 * HID + c) = __halves2half2(h0, h1);
                *(__half2*)(Ch16 + (size_t)r1 * HID + c) = __halves2half2(h2, h3);
                *(__half2*)(Cl16 + (size_t)r0 * HID + c) = __halves2half2(l0, l1);
                *(__half2*)(Cl16 + (size_t)r1 * HID + c) = __halves2half2(l2, l3);
            } else {
                *(float2*)(Cf + (size_t)r0 * HID + c) = make_float2(v0, v1);
                *(float2*)(Cf + (size_t)r1 * HID + c) = make_float2(v2, v3);
            }
        }
    }
}

// ---------------- head: logits = h2 @ w3 + b3, argmax, select ----------------
__global__ __launch_bounds__(256) void head_kernel(
    const float* __restrict__ h2,
    const float* __restrict__ w3,
    const float* __restrict__ b3,
    const int* __restrict__ fixed_mask,
    const int* __restrict__ seq_t,
    float* __restrict__ out_logits,
    float* __restrict__ out_seq0f,
    int* __restrict__ seq0i)
{
    extern __shared__ float w3s[];   // [20][1024]
    const int tid = threadIdx.x;
    const int wid = tid >> 5;
    const int lane = tid & 31;

    for (int i = tid; i < NRES * HID; i += 256) {
        int c = i >> 10;
        int k = i & 1023;
        w3s[i] = w3[k * NRES + c];
    }
    __syncthreads();

    const int rbase = blockIdx.x * 64 + wid * 8;
#pragma unroll
    for (int j = 0; j < 8; j += 2) {
        int ra = rbase + j, rb = ra + 1;
        const float* ha = h2 + (size_t)ra * HID;
        const float* hb = h2 + (size_t)rb * HID;
        float acc0[NRES], acc1[NRES];
#pragma unroll
        for (int c = 0; c < NRES; c++) { acc0[c] = 0.f; acc1[c] = 0.f; }
        for (int it = 0; it < 32; it++) {
            int k = it * 32 + lane;
            float va = ha[k];
            float vb = hb[k];
#pragma unroll
            for (int c = 0; c < NRES; c++) {
                float w = w3s[c * HID + k];
                acc0[c] = fmaf(va, w, acc0[c]);
                acc1[c] = fmaf(vb, w, acc1[c]);
            }
        }
#pragma unroll
        for (int c = 0; c < NRES; c++) {
#pragma unroll
            for (int o = 16; o; o >>= 1) {
                acc0[c] += __shfl_xor_sync(0xffffffffu, acc0[c], o);
                acc1[c] += __shfl_xor_sync(0xffffffffu, acc1[c], o);
            }
        }
        if (lane == 0) {
            int best0 = 0, best1 = 0;
            float bv0 = -INFINITY, bv1 = -INFINITY;
            float* l0 = out_logits + (size_t)ra * NRES;
            float* l1 = out_logits + (size_t)rb * NRES;
#pragma unroll
            for (int c = 0; c < NRES; c++) {
                float v0 = acc0[c] + b3[c];
                float v1 = acc1[c] + b3[c];
                l0[c] = v0; l1[c] = v1;
                if (v0 > bv0) { bv0 = v0; best0 = c; }
                if (v1 > bv1) { bv1 = v1; best1 = c; }
            }
            int s0 = fixed_mask[ra] ? seq_t[ra] : best0;
            int s1 = fixed_mask[rb] ? seq_t[rb] : best1;
            seq0i[ra] = s0; seq0i[rb] = s1;
            out_seq0f[ra] = (float)s0; out_seq0f[rb] = (float)s1;
        }
    }
}

// ---------------- geometry: one thread per residue ----------------
__global__ __launch_bounds__(128) void geom_kernel(
    const float* __restrict__ angles,
    const float* __restrict__ rigids,
    const int* __restrict__ residx,
    const float* __restrict__ default_frames,
    const int* __restrict__ group_idx,
    const float* __restrict__ atom14_mask,
    const float* __restrict__ atom37_mask,
    const float* __restrict__ lit_positions,
    const int* __restrict__ seq0i,
    float* __restrict__ out_pred,
    float* __restrict__ out_final,
    float* __restrict__ out_m14,
    float* __restrict__ out_m37)
{
    int r = blockIdx.x * blockDim.x + threadIdx.x;
    if (r >= RTOT) return;

    float q0 = rigids[r * 7 + 0], q1 = rigids[r * 7 + 1];
    float q2 = rigids[r * 7 + 2], q3 = rigids[r * 7 + 3];
    float tb0 = rigids[r * 7 + 4], tb1 = rigids[r * 7 + 5], tb2 = rigids[r * 7 + 6];
    float inv = rsqrtf(q0 * q0 + q1 * q1 + q2 * q2 + q3 * q3 + 1e-8f);
    float w = q0 * inv, x = q1 * inv, y = q2 * inv, z = q3 * inv;
    float rb[9];
    rb[0] = 1.f - 2.f * (y * y + z * z); rb[1] = 2.f * (x * y - w * z); rb[2] = 2.f * (x * z + w * y);
    rb[3] = 2.f * (x * y + w * z); rb[4] = 1.f - 2.f * (x * x + z * z); rb[5] = 2.f * (y * z - w * x);
    rb[6] = 2.f * (x * z - w * y); rb[7] = 2.f * (y * z + w * x); rb[8] = 1.f - 2.f * (x * x + y * y);

    int s = seq0i[r];

    float G[8][12];
    float chain_r[9], chain_t[3];

    for (int g = 0; g < 8; g++) {
        const float* df = default_frames + ((size_t)s * 8 + g) * 16;
        float dr[9], dt[3];
#pragma unroll
        for (int i = 0; i < 3; i++) {
            dr[i * 3 + 0] = df[i * 4 + 0];
            dr[i * 3 + 1] = df[i * 4 + 1];
            dr[i * 3 + 2] = df[i * 4 + 2];
            dt[i] = df[i * 4 + 3];
        }
        float sn, cs;
        if (g == 0) { sn = 0.f; cs = 1.f; }
        else { sn = angles[r * 14 + (g - 1) * 2 + 0]; cs = angles[r * 14 + (g - 1) * 2 + 1]; }

        float fr[9], ft[3];
#pragma unroll
        for (int i = 0; i < 3; i++) {
            fr[i * 3 + 0] = dr[i * 3 + 0];
            fr[i * 3 + 1] = dr[i * 3 + 1] * cs + dr[i * 3 + 2] * sn;
            fr[i * 3 + 2] = -dr[i * 3 + 1] * sn + dr[i * 3 + 2] * cs;
            ft[i] = dt[i];
        }

        float fo[9], to[3];
        if (g <= 4) {
#pragma unroll
            for (int i = 0; i < 9; i++) fo[i] = fr[i];
#pragma unroll
            for (int i = 0; i < 3; i++) to[i] = ft[i];
            if (g == 4) {
#pragma unroll
                for (int i = 0; i < 9; i++) chain_r[i] = fr[i];
#pragma unroll
                for (int i = 0; i < 3; i++) chain_t[i] = ft[i];
            }
        } else {
            float nr[9], nt[3];
#pragma unroll
            for (int i = 0; i < 3; i++) {
#pragma unroll
                for (int j = 0; j < 3; j++) {
                    nr[i * 3 + j] = chain_r[i * 3 + 0] * fr[0 * 3 + j]
                                  + chain_r[i * 3 + 1] * fr[1 * 3 + j]
                                  + chain_r[i * 3 + 2] * fr[2 * 3 + j];
                }
                nt[i] = chain_r[i * 3 + 0] * ft[0] + chain_r[i * 3 + 1] * ft[1]
                      + chain_r[i * 3 + 2] * ft[2] + chain_t[i];
            }
#pragma unroll
            for (int i = 0; i < 9; i++) { chain_r[i] = nr[i]; fo[i] = nr[i]; }
#pragma unroll
            for (int i = 0; i < 3; i++) { chain_t[i] = nt[i]; to[i] = nt[i]; }
        }

#pragma unroll
        for (int i = 0; i < 3; i++) {
#pragma unroll
            for (int j = 0; j < 3; j++) {
                G[g][i * 3 + j] = rb[i * 3 + 0] * fo[0 * 3 + j]
                                + rb[i * 3 + 1] * fo[1 * 3 + j]
                                + rb[i * 3 + 2] * fo[2 * 3 + j];
            }
        }
        G[g][9]  = rb[0] * to[0] + rb[1] * to[1] + rb[2] * to[2] + tb0;
        G[g][10] = rb[3] * to[0] + rb[4] * to[1] + rb[5] * to[2] + tb1;
        G[g][11] = rb[6] * to[0] + rb[7] * to[1] + rb[8] * to[2] + tb2;
    }

    float pv[14][3];
#pragma unroll
    for (int a = 0; a < 14; a++) {
        int gi = group_idx[s * 14 + a];
        const float* Gp = G[gi];
        float lx = lit_positions[((size_t)s * 14 + a) * 3 + 0];
        float ly = lit_positions[((size_t)s * 14 + a) * 3 + 1];
        float lz = lit_positions[((size_t)s * 14 + a) * 3 + 2];
        float m = atom14_mask[s * 14 + a];
        float px = (Gp[0] * lx + Gp[1] * ly + Gp[2] * lz + Gp[9])  * m;
        float py = (Gp[3] * lx + Gp[4] * ly + Gp[5] * lz + Gp[10]) * m;
        float pz = (Gp[6] * lx + Gp[7] * ly + Gp[8] * lz + Gp[11]) * m;
        pv[a][0] = px; pv[a][1] = py; pv[a][2] = pz;
        size_t po = ((size_t)r * 14 + a) * 3;
        out_pred[po + 0] = px; out_pred[po + 1] = py; out_pred[po + 2] = pz;
        out_m14[(size_t)r * 14 + a] = m;
    }

#pragma unroll
    for (int j = 0; j < 37; j++) {
        int a = residx[(size_t)r * 37 + j];
        size_t fo_ = ((size_t)r * 37 + j) * 3;
        out_final[fo_ + 0] = pv[a][0];
        out_final[fo_ + 1] = pv[a][1];
        out_final[fo_ + 2] = pv[a][2];
        out_m37[(size_t)r * 37 + j] = atom37_mask[s * 37 + j];
    }
}

// ---------------- launcher ----------------
extern "C" void kernel_launch(void* const* d_in, const int* in_sizes, int n_in,
                              void* d_out, int out_size)
{
    const float* act        = (const float*)d_in[0];
    const float* angles     = (const float*)d_in[1];
    const float* rigids     = (const float*)d_in[2];
    const int*   fixed_mask = (const int*)d_in[3];
    const int*   seq_t      = (const int*)d_in[4];
    const int*   residx     = (const int*)d_in[5];
    const float* ln_g       = (const float*)d_in[6];
    const float* ln_b       = (const float*)d_in[7];
    const float* w1         = (const float*)d_in[8];
    const float* b1         = (const float*)d_in[9];
    const float* w2         = (const float*)d_in[10];
    const float* b2         = (const float*)d_in[11];
    const float* w3         = (const float*)d_in[12];
    const float* b3         = (const float*)d_in[13];
    const float* dframes    = (const float*)d_in[14];
    const int*   group_idx  = (const int*)d_in[15];
    const float* a14_mask   = (const float*)d_in[16];
    const float* a37_mask   = (const float*)d_in[17];
    const float* lit        = (const float*)d_in[18];

    float* out = (float*)d_out;
    float* out_logits = out + OFF_LOGITS;
    float* out_seq0   = out + OFF_SEQ0;
    float* out_pred   = out + OFF_PRED;
    float* out_final  = out + OFF_FINAL;
    float* out_m14    = out + OFF_M14;
    float* out_m37    = out + OFF_M37;

    __half *xnh, *xnl, *h1h, *h1l, *wt1h, *wt1l, *wt2h, *wt2l;
    float *h2;
    int* seq0i;
    cudaGetSymbolAddress((void**)&xnh, g_xn_hi);
    cudaGetSymbolAddress((void**)&xnl, g_xn_lo);
    cudaGetSymbolAddress((void**)&h1h, g_h1_hi);
    cudaGetSymbolAddress((void**)&h1l, g_h1_lo);
    cudaGetSymbolAddress((void**)&h2,  g_h2);
    cudaGetSymbolAddress((void**)&wt1h, g_wt1_hi);
    cudaGetSymbolAddress((void**)&wt1l, g_wt1_lo);
    cudaGetSymbolAddress((void**)&wt2h, g_wt2_hi);
    cudaGetSymbolAddress((void**)&wt2l, g_wt2_lo);
    cudaGetSymbolAddress((void**)&seq0i, g_seq0i);

    const int GEMM_SMEM = NSTAGE * STAGEB;   // 202752 B -> 1 CTA, 16 warps/SM
    cudaFuncSetAttribute(mma_gemm_kernel<CIN, true>,
                         cudaFuncAttributeMaxDynamicSharedMemorySize, GEMM_SMEM);
    cudaFuncSetAttribute(mma_gemm_kernel<HID, false>,
                         cudaFuncAttributeMaxDynamicSharedMemorySize, GEMM_SMEM);
    cudaFuncSetAttribute(head_kernel,
                         cudaFuncAttributeMaxDynamicSharedMemorySize, NRES * HID * 4);

    // 1. LayerNorm with fp16 split output
    ln_kernel<<<RTOT / 8, 256>>>(act, ln_g, ln_b, xnh, xnl);

    // 2. weight prep: coalesced transpose + fp16 split
    {
        dim3 blk(32, 8);
        dim3 g1(HID / 32, CIN / 32);
        tsplit_kernel<<<g1, blk>>>(w1, wt1h, wt1l, CIN, HID);
        dim3 g2(HID / 32, HID / 32);
        tsplit_kernel<<<g2, blk>>>(w2, wt2h, wt2l, HID, HID);
    }

    // 3. GEMM1: relu(xn @ w1 + b1) -> h1 (fp16 split)
    {
        dim3 grid(HID / 256, RTOT / 128);
        mma_gemm_kernel<CIN, true><<<grid, 512, GEMM_SMEM>>>(
            xnh, xnl, wt1h, wt1l, b1, nullptr, h1h, h1l);
    }
    // 4. GEMM2: relu(h1 @ w2 + b2) -> h2 (fp32)
    {
        dim3 grid(HID / 256, RTOT / 128);
        mma_gemm_kernel<HID, false><<<grid, 512, GEMM_SMEM>>>(
            h1h, h1l, wt2h, wt2l, b2, h2, nullptr, nullptr);
    }
    // 5. logits + argmax + select
    head_kernel<<<RTOT / 64, 256, NRES * HID * 4>>>(h2, w3, b3, fixed_mask, seq_t,
                                                    out_logits, out_seq0, seq0i);
    // 6. geometry
    geom_kernel<<<RTOT / 128, 128>>>(angles, rigids, residx, dframes, group_idx,
                                     a14_mask, a37_mask, lit, seq0i,
                                     out_pred, out_final, out_m14, out_m37);
}